// round 6
// baseline (speedup 1.0000x reference)
#include <cuda_runtime.h>
#include <cuda_fp16.h>
#include <math.h>
#include <stdint.h>

// ---------------- problem constants ----------------
#define NL     6
#define DMODEL 1024
#define DFF    4096
#define VOC    32000
#define NH     16
#define HDIM   64
#define BATCH  2
#define TSEQ   1024
#define MTOK   (BATCH*TSEQ)   // 2048

// ---------------- scratch (static device globals; no allocation) ----------------
__device__ float g_x[MTOK * DMODEL];

__device__ __align__(16) half g_h [MTOK * DMODEL];
__device__ __align__(16) half g_qkvh[(size_t)MTOK * 3 * DMODEL], g_qkvl[(size_t)MTOK * 3 * DMODEL];
__device__ __align__(16) half g_o [MTOK * DMODEL];
__device__ __align__(16) half g_f [(size_t)MTOK * DFF];

__device__ __align__(16) half g_wqh[(size_t)NL*3*DMODEL*DMODEL], g_wql[(size_t)NL*3*DMODEL*DMODEL];
__device__ __align__(16) half g_woh[(size_t)NL*DMODEL*DMODEL],   g_wol[(size_t)NL*DMODEL*DMODEL];
__device__ __align__(16) half g_w1h[(size_t)NL*DFF*DMODEL],      g_w1l[(size_t)NL*DFF*DMODEL];
__device__ __align__(16) half g_w2h[(size_t)NL*DMODEL*DFF],      g_w2l[(size_t)NL*DMODEL*DFF];
__device__ __align__(16) half g_eh [(size_t)VOC*DMODEL];

// ---------------- helpers ----------------
__device__ __forceinline__ void f2hilo(float x, half& h, half& l) {
    h = __float2half(x);
    l = __float2half(x - __half2float(h));
}
__device__ __forceinline__ uint32_t packh(half a, half b) {
    __half2 t; t.x = a; t.y = b;
    return *(uint32_t*)&t;
}

__device__ __forceinline__ void cp_async16(uint32_t s, const void* g) {
    asm volatile("cp.async.cg.shared.global [%0], [%1], 16;\n" :: "r"(s), "l"(g));
}
__device__ __forceinline__ void cp_commit() { asm volatile("cp.async.commit_group;\n"); }
template<int N> __device__ __forceinline__ void cp_wait() {
    asm volatile("cp.async.wait_group %0;\n" :: "n"(N));
}

__device__ __forceinline__ void ldsm4(uint32_t* r, uint32_t addr) {
    asm volatile("ldmatrix.sync.aligned.m8n8.x4.shared.b16 {%0,%1,%2,%3}, [%4];\n"
        : "=r"(r[0]), "=r"(r[1]), "=r"(r[2]), "=r"(r[3]) : "r"(addr));
}
__device__ __forceinline__ void ldsm4t(uint32_t* r, uint32_t addr) {
    asm volatile("ldmatrix.sync.aligned.m8n8.x4.trans.shared.b16 {%0,%1,%2,%3}, [%4];\n"
        : "=r"(r[0]), "=r"(r[1]), "=r"(r[2]), "=r"(r[3]) : "r"(addr));
}

__device__ __forceinline__ void mma16816(float* c, const uint32_t* a, uint32_t b0, uint32_t b1) {
    asm volatile(
        "mma.sync.aligned.m16n8k16.row.col.f32.f16.f16.f32 "
        "{%0,%1,%2,%3}, {%4,%5,%6,%7}, {%8,%9}, {%0,%1,%2,%3};\n"
        : "+f"(c[0]), "+f"(c[1]), "+f"(c[2]), "+f"(c[3])
        : "r"(a[0]), "r"(a[1]), "r"(a[2]), "r"(a[3]), "r"(b0), "r"(b1));
}

// ---------------- fp32 -> (hi,lo) fp16 conversion ----------------
__global__ __launch_bounds__(256) void cvt_hilo(const float* __restrict__ x,
                                                half* __restrict__ h, half* __restrict__ l,
                                                int n)
{
    int i = (blockIdx.x * 256 + threadIdx.x) * 4;
    if (i >= n) return;
    float4 v = *(const float4*)(x + i);
    half h0, h1, h2, h3, l0, l1, l2, l3;
    f2hilo(v.x, h0, l0); f2hilo(v.y, h1, l1);
    f2hilo(v.z, h2, l2); f2hilo(v.w, h3, l3);
    *(uint32_t*)(h + i)     = packh(h0, h1);
    *(uint32_t*)(h + i + 2) = packh(h2, h3);
    *(uint32_t*)(l + i)     = packh(l0, l1);
    *(uint32_t*)(l + i + 2) = packh(l2, l3);
}

// fp32 -> single fp16
__global__ __launch_bounds__(256) void cvt_h(const float* __restrict__ x,
                                             half* __restrict__ h, int n)
{
    int i = (blockIdx.x * 256 + threadIdx.x) * 4;
    if (i >= n) return;
    float4 v = *(const float4*)(x + i);
    *(uint32_t*)(h + i)     = packh(__float2half(v.x), __float2half(v.y));
    *(uint32_t*)(h + i + 2) = packh(__float2half(v.z), __float2half(v.w));
}

// ---------------- fp16 GEMM (mma.sync), templated tile + terms ----------------
// C[M,N] = A[M,K] * (Bh[+Bl])[N,K]^T
// 128 x BN block, BK=32, 256 threads (8 warps, 2x4), warp tile 64 x BN/4.
#define EPI_STORE 0
#define EPI_ADD   1
#define EPI_GELU  2
#define EPI_HILO  3

template<int BN, int TERMS, int EPI>
__global__ __launch_bounds__(256) void gemm_f16(
    const half* __restrict__ A,
    const half* __restrict__ Bh, const half* __restrict__ Bl,
    float* __restrict__ C, half* __restrict__ Ch, half* __restrict__ Cl,
    int M, int N, int K)
{
    constexpr int P       = BN / 64;          // 16-row B groups per warp region
    constexpr int NT      = BN / 32;          // n-tiles per warp
    constexpr uint32_t BBYTES = (uint32_t)BN * 64;
    constexpr uint32_t STAGE  = 8192 + (uint32_t)TERMS * BBYTES;

    extern __shared__ uint8_t smem[];
    const uint32_t smem_u32 = (uint32_t)__cvta_generic_to_shared(smem);

    const int tid  = threadIdx.x;
    const int lane = tid & 31;
    const int wid  = tid >> 5;
    const int wm   = wid & 1;
    const int wn   = wid >> 1;
    const int bm   = blockIdx.y * 128;
    const int bn   = blockIdx.x * BN;

    const half* Ab  = A  + (size_t)bm * K;
    const half* Bhb = Bh + (size_t)bn * K;
    const half* Blb = (TERMS == 2) ? (Bl + (size_t)bn * K) : nullptr;

    float acc[4][NT][4];
#pragma unroll
    for (int a = 0; a < 4; a++)
#pragma unroll
        for (int b = 0; b < NT; b++)
#pragma unroll
            for (int c = 0; c < 4; c++) acc[a][b][c] = 0.f;

    const int ntiles = K >> 5;

    auto load_stage = [&](int st, int k0) {
        uint32_t base = smem_u32 + (uint32_t)st * STAGE;
#pragma unroll
        for (int i = 0; i < 2; i++) {                   // A: 512 chunks
            int idx = tid * 2 + i;
            int r = idx >> 2, c = idx & 3;
            size_t go = (size_t)r * K + k0 + c * 8;
            uint32_t so = base + r * 64 + (((uint32_t)(c ^ (r & 3))) << 4);
            cp_async16(so, Ab + go);
        }
#pragma unroll
        for (int i = 0; i < BN/64; i++) {               // B: BN*4 chunks per tensor
            int idx = tid * (BN/64) + i;
            int r = idx >> 2, c = idx & 3;
            size_t go = (size_t)r * K + k0 + c * 8;
            uint32_t so = base + 8192 + r * 64 + (((uint32_t)(c ^ (r & 3))) << 4);
            cp_async16(so, Bhb + go);
            if (TERMS == 2) cp_async16(so + BBYTES, Blb + go);
        }
    };

    load_stage(0, 0);
    cp_commit();

    for (int t = 0; t < ntiles; t++) {
        if (t + 1 < ntiles) {
            load_stage((t + 1) & 1, (t + 1) << 5);
            cp_commit();
            cp_wait<1>();
        } else {
            cp_wait<0>();
        }
        __syncthreads();

        const uint32_t bA  = smem_u32 + (uint32_t)(t & 1) * STAGE;
        const uint32_t bBh = bA + 8192;

#pragma unroll
        for (int s = 0; s < 2; s++) {
            uint32_t af[4][4];
#pragma unroll
            for (int mt = 0; mt < 4; mt++) {
                int row = wm * 64 + mt * 16 + (lane & 15);
                int ch  = 2 * s + (lane >> 4);
                uint32_t off = row * 64 + (((uint32_t)(ch ^ (row & 3))) << 4);
                ldsm4(af[mt], bA + off);
            }
#pragma unroll
            for (int p = 0; p < P; p++) {
                int row = wn * (BN/4) + p * 16 + (lane & 15);
                int ch  = 2 * s + (lane >> 4);
                uint32_t off = row * 64 + (((uint32_t)(ch ^ (row & 3))) << 4);
                uint32_t bh4[4];
                ldsm4(bh4, bBh + off);
#pragma unroll
                for (int mt = 0; mt < 4; mt++)
#pragma unroll
                    for (int q = 0; q < 2; q++)
                        mma16816(acc[mt][p*2+q], af[mt], bh4[q], bh4[q+2]);
                if (TERMS == 2) {
                    uint32_t bl4[4];
                    ldsm4(bl4, bBh + BBYTES + off);
#pragma unroll
                    for (int mt = 0; mt < 4; mt++)
#pragma unroll
                        for (int q = 0; q < 2; q++)
                            mma16816(acc[mt][p*2+q], af[mt], bl4[q], bl4[q+2]);
                }
            }
        }
        __syncthreads();
    }

    // --- epilogue ---
#pragma unroll
    for (int mt = 0; mt < 4; mt++) {
#pragma unroll
        for (int nt = 0; nt < NT; nt++) {
            int row = bm + wm * 64 + mt * 16 + (lane >> 2);
            int col = bn + wn * (BN/4) + nt * 8 + (lane & 3) * 2;
            size_t i0 = (size_t)row * N + col;
            size_t i1 = i0 + (size_t)8 * N;
            float* c = acc[mt][nt];
            if (EPI == EPI_STORE) {
                *(float2*)(C + i0) = make_float2(c[0], c[1]);
                *(float2*)(C + i1) = make_float2(c[2], c[3]);
            } else if (EPI == EPI_ADD) {
                C[i0]   += c[0]; C[i0+1] += c[1];
                C[i1]   += c[2]; C[i1+1] += c[3];
            } else if (EPI == EPI_GELU) {
#pragma unroll
                for (int e = 0; e < 4; e += 2) {
                    size_t ii = (e == 0) ? i0 : i1;
                    float v0 = c[e], v1 = c[e+1];
                    float q0 = 0.5f * v0 * (1.f + erff(v0 * 0.70710678118654752f));
                    float q1 = 0.5f * v1 * (1.f + erff(v1 * 0.70710678118654752f));
                    *(uint32_t*)(Ch + ii) = packh(__float2half(q0), __float2half(q1));
                }
            } else {  // EPI_HILO
#pragma unroll
                for (int e = 0; e < 4; e += 2) {
                    size_t ii = (e == 0) ? i0 : i1;
                    half h0, l0, h1, l1;
                    f2hilo(c[e], h0, l0); f2hilo(c[e+1], h1, l1);
                    *(uint32_t*)(Ch + ii) = packh(h0, h1);
                    *(uint32_t*)(Cl + ii) = packh(l0, l1);
                }
            }
        }
    }
}

// ---------------- flash attention (split-fp16 mma.sync) ----------------
__global__ __launch_bounds__(256) void flash_kernel(
    const half* __restrict__ qkvh, const half* __restrict__ qkvl,
    half* __restrict__ o)
{
    extern __shared__ uint8_t fsm[];
    const uint32_t sb  = (uint32_t)__cvta_generic_to_shared(fsm);
    const uint32_t sQh = sb, sQl = sb + 16384;
    const uint32_t sKV = sb + 32768;

    const int tid = threadIdx.x, lane = tid & 31, w = tid >> 5;
    const int qi = (int)gridDim.x - 1 - (int)blockIdx.x;
    const int bh = blockIdx.y;
    const int b = bh >> 4, h = bh & 15;
    const int qbase = qi * 128;
    const int nkb = (qbase + 128) >> 6;

    const size_t tb = (size_t)b * TSEQ;
    const half* Qh_ = qkvh + tb * 3 * DMODEL + h * HDIM;
    const half* Ql_ = qkvl + tb * 3 * DMODEL + h * HDIM;
    const half* Kh_ = Qh_ + DMODEL;
    const half* Kl_ = Ql_ + DMODEL;
    const half* Vh_ = Qh_ + 2 * DMODEL;
    const half* Vl_ = Ql_ + 2 * DMODEL;

    auto load_kv = [&](int buf, int kb) {
        uint32_t base = sKV + (uint32_t)buf * 32768;
#pragma unroll
        for (int i = 0; i < 2; i++) {
            int idx = tid * 2 + i;
            int r = idx >> 3, c = idx & 7;
            size_t go = (size_t)(kb * 64 + r) * 3 * DMODEL + c * 8;
            uint32_t so = r * 128 + (((uint32_t)(c ^ (r & 7))) << 4);
            cp_async16(base + so,         Kh_ + go);
            cp_async16(base + 8192 + so,  Kl_ + go);
            cp_async16(base + 16384 + so, Vh_ + go);
            cp_async16(base + 24576 + so, Vl_ + go);
        }
    };

#pragma unroll
    for (int i = 0; i < 4; i++) {
        int idx = tid * 4 + i;
        int r = idx >> 3, c = idx & 7;
        size_t go = (size_t)(qbase + r) * 3 * DMODEL + c * 8;
        uint32_t so = r * 128 + (((uint32_t)(c ^ (r & 7))) << 4);
        cp_async16(sQh + so, Qh_ + go);
        cp_async16(sQl + so, Ql_ + go);
    }
    load_kv(0, 0);
    cp_commit();
    if (nkb > 1) { load_kv(1, 1); cp_commit(); cp_wait<1>(); }
    else cp_wait<0>();
    __syncthreads();

    uint32_t qfh[4][4], qfl[4][4];
#pragma unroll
    for (int s = 0; s < 4; s++) {
        int r = 16 * w + (lane & 15);
        int c = 2 * s + (lane >> 4);
        uint32_t so = r * 128 + (((uint32_t)(c ^ (r & 7))) << 4);
        ldsm4(qfh[s], sQh + so);
        ldsm4(qfl[s], sQl + so);
    }

    float oacc[8][4];
#pragma unroll
    for (int j = 0; j < 8; j++)
#pragma unroll
        for (int c = 0; c < 4; c++) oacc[j][c] = 0.f;
    float mrow0 = -1e30f, mrow1 = -1e30f, lrow0 = 0.f, lrow1 = 0.f;
    const int r0 = qbase + 16 * w + (lane >> 2);

    for (int kb = 0; kb < nkb; kb++) {
        if (kb * 64 <= qbase + 16 * w + 15) {
            uint32_t base = sKV + (uint32_t)(kb & 1) * 32768;
            float sacc[8][4];
#pragma unroll
            for (int j = 0; j < 8; j++)
#pragma unroll
                for (int c = 0; c < 4; c++) sacc[j][c] = 0.f;

#pragma unroll
            for (int p = 0; p < 4; p++) {
                int rr = 16 * p + (lane & 15);
#pragma unroll
                for (int s = 0; s < 4; s++) {
                    int cc = 2 * s + (lane >> 4);
                    uint32_t so = rr * 128 + (((uint32_t)(cc ^ (rr & 7))) << 4);
                    uint32_t kh4[4], kl4[4];
                    ldsm4(kh4, base + so);
                    ldsm4(kl4, base + 8192 + so);
                    mma16816(sacc[2*p],   qfh[s], kh4[0], kh4[2]);
                    mma16816(sacc[2*p+1], qfh[s], kh4[1], kh4[3]);
                    mma16816(sacc[2*p],   qfh[s], kl4[0], kl4[2]);
                    mma16816(sacc[2*p+1], qfh[s], kl4[1], kl4[3]);
                    mma16816(sacc[2*p],   qfl[s], kh4[0], kh4[2]);
                    mma16816(sacc[2*p+1], qfl[s], kh4[1], kh4[3]);
                }
            }
            int cbase = kb * 64 + 2 * (lane & 3);
#pragma unroll
            for (int j = 0; j < 8; j++) {
                int c0 = cbase + 8 * j;
                sacc[j][0] = (c0     <= r0    ) ? sacc[j][0] * 0.125f : -1e30f;
                sacc[j][1] = (c0 + 1 <= r0    ) ? sacc[j][1] * 0.125f : -1e30f;
                sacc[j][2] = (c0     <= r0 + 8) ? sacc[j][2] * 0.125f : -1e30f;
                sacc[j][3] = (c0 + 1 <= r0 + 8) ? sacc[j][3] * 0.125f : -1e30f;
            }
            float mx0 = -1e30f, mx1 = -1e30f;
#pragma unroll
            for (int j = 0; j < 8; j++) {
                mx0 = fmaxf(mx0, fmaxf(sacc[j][0], sacc[j][1]));
                mx1 = fmaxf(mx1, fmaxf(sacc[j][2], sacc[j][3]));
            }
            mx0 = fmaxf(mx0, __shfl_xor_sync(0xffffffffu, mx0, 1));
            mx0 = fmaxf(mx0, __shfl_xor_sync(0xffffffffu, mx0, 2));
            mx1 = fmaxf(mx1, __shfl_xor_sync(0xffffffffu, mx1, 1));
            mx1 = fmaxf(mx1, __shfl_xor_sync(0xffffffffu, mx1, 2));
            float mn0 = fmaxf(mrow0, mx0), mn1 = fmaxf(mrow1, mx1);
            float al0 = __expf(mrow0 - mn0), al1 = __expf(mrow1 - mn1);
            mrow0 = mn0; mrow1 = mn1;

            uint32_t ph[8][2], pl[8][2];
            float ls0 = 0.f, ls1 = 0.f;
#pragma unroll
            for (int j = 0; j < 8; j++) {
                float p0 = __expf(sacc[j][0] - mn0);
                float p1 = __expf(sacc[j][1] - mn0);
                float p2 = __expf(sacc[j][2] - mn1);
                float p3 = __expf(sacc[j][3] - mn1);
                ls0 += p0 + p1; ls1 += p2 + p3;
                half h0, l0, h1, l1, h2, l2, h3, l3;
                f2hilo(p0, h0, l0); f2hilo(p1, h1, l1);
                f2hilo(p2, h2, l2); f2hilo(p3, h3, l3);
                ph[j][0] = packh(h0, h1); pl[j][0] = packh(l0, l1);
                ph[j][1] = packh(h2, h3); pl[j][1] = packh(l2, l3);
            }
            ls0 += __shfl_xor_sync(0xffffffffu, ls0, 1);
            ls0 += __shfl_xor_sync(0xffffffffu, ls0, 2);
            ls1 += __shfl_xor_sync(0xffffffffu, ls1, 1);
            ls1 += __shfl_xor_sync(0xffffffffu, ls1, 2);
            lrow0 = lrow0 * al0 + ls0;
            lrow1 = lrow1 * al1 + ls1;
#pragma unroll
            for (int j = 0; j < 8; j++) {
                oacc[j][0] *= al0; oacc[j][1] *= al0;
                oacc[j][2] *= al1; oacc[j][3] *= al1;
            }
#pragma unroll
            for (int pv = 0; pv < 4; pv++) {
#pragma unroll
                for (int s = 0; s < 4; s++) {
                    int tok = 16 * s + ((lane >> 3) & 1) * 8 + (lane & 7);
                    int dc  = 16 * pv + (lane >> 4) * 8;
                    uint32_t so = tok * 128 + ((((uint32_t)(dc >> 3)) ^ (uint32_t)(tok & 7)) << 4);
                    uint32_t v4h[4], v4l[4];
                    ldsm4t(v4h, base + 16384 + so);
                    ldsm4t(v4l, base + 24576 + so);
                    uint32_t pah[4] = {ph[2*s][0], ph[2*s][1], ph[2*s+1][0], ph[2*s+1][1]};
                    uint32_t pal[4] = {pl[2*s][0], pl[2*s][1], pl[2*s+1][0], pl[2*s+1][1]};
                    mma16816(oacc[2*pv],   pah, v4h[0], v4h[1]);
                    mma16816(oacc[2*pv+1], pah, v4h[2], v4h[3]);
                    mma16816(oacc[2*pv],   pah, v4l[0], v4l[1]);
                    mma16816(oacc[2*pv+1], pah, v4l[2], v4l[3]);
                    mma16816(oacc[2*pv],   pal, v4h[0], v4h[1]);
                    mma16816(oacc[2*pv+1], pal, v4h[2], v4h[3]);
                }
            }
        }
        __syncthreads();
        if (kb + 1 < nkb) {
            if (kb + 2 < nkb) { load_kv(kb & 1, kb + 2); cp_commit(); cp_wait<1>(); }
            else cp_wait<0>();
            __syncthreads();
        }
    }

    float rl0 = 1.f / lrow0, rl1 = 1.f / lrow1;
    size_t ob0 = (tb + r0) * (size_t)DMODEL + h * HDIM + 2 * (lane & 3);
    size_t ob1 = ob0 + 8 * (size_t)DMODEL;
#pragma unroll
    for (int j = 0; j < 8; j++) {
        *(uint32_t*)(o + ob0 + 8 * j) =
            packh(__float2half(oacc[j][0] * rl0), __float2half(oacc[j][1] * rl0));
        *(uint32_t*)(o + ob1 + 8 * j) =
            packh(__float2half(oacc[j][2] * rl1), __float2half(oacc[j][3] * rl1));
    }
}

// ---------------- embedding ----------------
__global__ void embed_kernel(const int* __restrict__ idx,
                             const float* __restrict__ tok,
                             const float* __restrict__ pos,
                             float* __restrict__ x)
{
    int t = blockIdx.x;
    int token = idx[t];
    const float* tr = tok + (size_t)token * DMODEL;
    const float* pr = pos + (size_t)(t & (TSEQ - 1)) * DMODEL;
    float* xr = x + (size_t)t * DMODEL;
    for (int d = threadIdx.x; d < DMODEL; d += blockDim.x)
        xr[d] = tr[d] + pr[d];
}

// ---------------- layernorm: warp per row, 8 rows/CTA ----------------
__global__ __launch_bounds__(256) void layernorm_kernel(
    const float* __restrict__ x, half* __restrict__ y,
    const float* __restrict__ w, const float* __restrict__ bvec)
{
    int lane = threadIdx.x & 31, wid = threadIdx.x >> 5;
    int row = blockIdx.x * 8 + wid;
    const float4* px = (const float4*)(x + (size_t)row * DMODEL);

    float4 v[8];
    float s = 0.f, ss = 0.f;
#pragma unroll
    for (int c = 0; c < 8; c++) {
        v[c] = px[lane + c * 32];
        s  += v[c].x + v[c].y + v[c].z + v[c].w;
        ss += v[c].x*v[c].x + v[c].y*v[c].y + v[c].z*v[c].z + v[c].w*v[c].w;
    }
#pragma unroll
    for (int o = 16; o; o >>= 1) {
        s  += __shfl_xor_sync(0xffffffffu, s,  o);
        ss += __shfl_xor_sync(0xffffffffu, ss, o);
    }
    float mean = s * (1.f / DMODEL);
    float var  = ss * (1.f / DMODEL) - mean * mean;
    float inv  = rsqrtf(var + 1e-5f);

    half* py = y + (size_t)row * DMODEL;
#pragma unroll
    for (int c = 0; c < 8; c++) {
        int j = (lane + c * 32) * 4;
        float4 wv = *(const float4*)(w + j);
        float4 bv = *(const float4*)(bvec + j);
        float y0 = (v[c].x - mean) * inv * wv.x + bv.x;
        float y1 = (v[c].y - mean) * inv * wv.y + bv.y;
        float y2 = (v[c].z - mean) * inv * wv.z + bv.z;
        float y3 = (v[c].w - mean) * inv * wv.w + bv.w;
        uint2 pk;
        pk.x = packh(__float2half(y0), __float2half(y1));
        pk.y = packh(__float2half(y2), __float2half(y3));
        *(uint2*)(py + j) = pk;
    }
}

// ---------------- launch ----------------
extern "C" void kernel_launch(void* const* d_in, const int* in_sizes, int n_in,
                              void* d_out, int out_size)
{
    (void)in_sizes; (void)n_in; (void)out_size;
    const int*   idx     = (const int*)  d_in[0];
    const float* tok_emb = (const float*)d_in[1];
    const float* pos_emb = (const float*)d_in[2];
    const float* ln1_w   = (const float*)d_in[3];
    const float* ln1_b   = (const float*)d_in[4];
    const float* qkv_w   = (const float*)d_in[5];
    const float* out_w   = (const float*)d_in[6];
    const float* ln2_w   = (const float*)d_in[7];
    const float* ln2_b   = (const float*)d_in[8];
    const float* ffn1_w  = (const float*)d_in[9];
    const float* ffn2_w  = (const float*)d_in[10];
    const float* lnf_w   = (const float*)d_in[11];
    const float* lnf_b   = (const float*)d_in[12];
    float* out = (float*)d_out;

    float *x;
    half *h, *qvh, *qvl, *o, *f;
    half *wqh, *wql, *woh, *wol, *w1h, *w1l, *w2h, *w2l, *eh;
    cudaGetSymbolAddress((void**)&x,    g_x);
    cudaGetSymbolAddress((void**)&h,    g_h);
    cudaGetSymbolAddress((void**)&qvh,  g_qkvh); cudaGetSymbolAddress((void**)&qvl, g_qkvl);
    cudaGetSymbolAddress((void**)&o,    g_o);
    cudaGetSymbolAddress((void**)&f,    g_f);
    cudaGetSymbolAddress((void**)&wqh,  g_wqh);  cudaGetSymbolAddress((void**)&wql, g_wql);
    cudaGetSymbolAddress((void**)&woh,  g_woh);  cudaGetSymbolAddress((void**)&wol, g_wol);
    cudaGetSymbolAddress((void**)&w1h,  g_w1h);  cudaGetSymbolAddress((void**)&w1l, g_w1l);
    cudaGetSymbolAddress((void**)&w2h,  g_w2h);  cudaGetSymbolAddress((void**)&w2l, g_w2l);
    cudaGetSymbolAddress((void**)&eh,   g_eh);

    // smem sizes: BN=128,T=2: 48KB; BN=256,T=2: 80KB; BN=256,T=1: 48KB
    cudaFuncSetAttribute(gemm_f16<256,2,EPI_HILO>,  cudaFuncAttributeMaxDynamicSharedMemorySize, 81920);
    cudaFuncSetAttribute(gemm_f16<256,2,EPI_GELU>,  cudaFuncAttributeMaxDynamicSharedMemorySize, 81920);
    cudaFuncSetAttribute(gemm_f16<128,2,EPI_ADD>,   cudaFuncAttributeMaxDynamicSharedMemorySize, 49152);
    cudaFuncSetAttribute(gemm_f16<256,1,EPI_STORE>, cudaFuncAttributeMaxDynamicSharedMemorySize, 49152);
    cudaFuncSetAttribute(flash_kernel,              cudaFuncAttributeMaxDynamicSharedMemorySize, 98304);

    // weight conversions
    {
        int n;
        n = NL*3*DMODEL*DMODEL; cvt_hilo<<<n/1024, 256>>>(qkv_w,  wqh, wql, n);
        n = NL*DMODEL*DMODEL;   cvt_hilo<<<n/1024, 256>>>(out_w,  woh, wol, n);
        n = NL*DFF*DMODEL;      cvt_hilo<<<n/1024, 256>>>(ffn1_w, w1h, w1l, n);
        n = NL*DMODEL*DFF;      cvt_hilo<<<n/1024, 256>>>(ffn2_w, w2h, w2l, n);
        n = VOC*DMODEL;         cvt_h<<<n/1024, 256>>>(tok_emb, eh, n);
    }

    embed_kernel<<<MTOK, 256>>>(idx, tok_emb, pos_emb, x);

    for (int l = 0; l < NL; l++) {
        // --- attention block ---
        layernorm_kernel<<<MTOK/8, 256>>>(x, h, ln1_w + l * DMODEL, ln1_b + l * DMODEL);
        gemm_f16<256,2,EPI_HILO><<<dim3(3*DMODEL/256, MTOK/128), 256, 81920>>>(
            h, wqh + (size_t)l*3*DMODEL*DMODEL, wql + (size_t)l*3*DMODEL*DMODEL,
            nullptr, qvh, qvl, MTOK, 3*DMODEL, DMODEL);
        flash_kernel<<<dim3(TSEQ/128, BATCH*NH), 256, 98304>>>(qvh, qvl, o);
        gemm_f16<128,2,EPI_ADD><<<dim3(DMODEL/128, MTOK/128), 256, 49152>>>(
            o, woh + (size_t)l*DMODEL*DMODEL, wol + (size_t)l*DMODEL*DMODEL,
            x, nullptr, nullptr, MTOK, DMODEL, DMODEL);
        // --- FFN block ---
        layernorm_kernel<<<MTOK/8, 256>>>(x, h, ln2_w + l * DMODEL, ln2_b + l * DMODEL);
        gemm_f16<256,2,EPI_GELU><<<dim3(DFF/256, MTOK/128), 256, 81920>>>(
            h, w1h + (size_t)l*DFF*DMODEL, w1l + (size_t)l*DFF*DMODEL,
            nullptr, f, nullptr, MTOK, DFF, DMODEL);
        gemm_f16<128,2,EPI_ADD><<<dim3(DMODEL/128, MTOK/128), 256, 49152>>>(
            f, w2h + (size_t)l*DMODEL*DFF, w2l + (size_t)l*DMODEL*DFF,
            x, nullptr, nullptr, MTOK, DMODEL, DFF);
    }

    layernorm_kernel<<<MTOK/8, 256>>>(x, h, lnf_w, lnf_b);
    gemm_f16<256,1,EPI_STORE><<<dim3(VOC/256, MTOK/128), 256, 49152>>>(
        h, eh, nullptr, out, nullptr, nullptr, MTOK, VOC, DMODEL);
}

// round 7
// speedup vs baseline: 1.1928x; 1.1928x over previous
#include <cuda_runtime.h>
#include <cuda_fp16.h>
#include <math.h>
#include <stdint.h>

// ---------------- problem constants ----------------
#define NL     6
#define DMODEL 1024
#define DFF    4096
#define VOC    32000
#define NH     16
#define HDIM   64
#define BATCH  2
#define TSEQ   1024
#define MTOK   (BATCH*TSEQ)   // 2048

// ---------------- scratch (static device globals; no allocation) ----------------
__device__ float g_x[MTOK * DMODEL];

__device__ __align__(16) half g_h [MTOK * DMODEL];
__device__ __align__(16) half g_qkvh[(size_t)MTOK * 3 * DMODEL], g_qkvl[(size_t)MTOK * 3 * DMODEL];
__device__ __align__(16) half g_o [MTOK * DMODEL];
__device__ __align__(16) half g_f [(size_t)MTOK * DFF];

__device__ __align__(16) half g_wqh[(size_t)NL*3*DMODEL*DMODEL], g_wql[(size_t)NL*3*DMODEL*DMODEL];
__device__ __align__(16) half g_woh[(size_t)NL*DMODEL*DMODEL],   g_wol[(size_t)NL*DMODEL*DMODEL];
__device__ __align__(16) half g_w1h[(size_t)NL*DFF*DMODEL],      g_w1l[(size_t)NL*DFF*DMODEL];
__device__ __align__(16) half g_w2h[(size_t)NL*DMODEL*DFF],      g_w2l[(size_t)NL*DMODEL*DFF];
__device__ __align__(16) half g_eh [(size_t)VOC*DMODEL];

// ---------------- helpers ----------------
__device__ __forceinline__ void f2hilo(float x, half& h, half& l) {
    h = __float2half(x);
    l = __float2half(x - __half2float(h));
}
__device__ __forceinline__ uint32_t packh(half a, half b) {
    __half2 t; t.x = a; t.y = b;
    return *(uint32_t*)&t;
}

__device__ __forceinline__ void cp_async16(uint32_t s, const void* g) {
    asm volatile("cp.async.cg.shared.global [%0], [%1], 16;\n" :: "r"(s), "l"(g));
}
__device__ __forceinline__ void cp_commit() { asm volatile("cp.async.commit_group;\n"); }
template<int N> __device__ __forceinline__ void cp_wait() {
    asm volatile("cp.async.wait_group %0;\n" :: "n"(N));
}

__device__ __forceinline__ void ldsm4(uint32_t* r, uint32_t addr) {
    asm volatile("ldmatrix.sync.aligned.m8n8.x4.shared.b16 {%0,%1,%2,%3}, [%4];\n"
        : "=r"(r[0]), "=r"(r[1]), "=r"(r[2]), "=r"(r[3]) : "r"(addr));
}
__device__ __forceinline__ void ldsm4t(uint32_t* r, uint32_t addr) {
    asm volatile("ldmatrix.sync.aligned.m8n8.x4.trans.shared.b16 {%0,%1,%2,%3}, [%4];\n"
        : "=r"(r[0]), "=r"(r[1]), "=r"(r[2]), "=r"(r[3]) : "r"(addr));
}

__device__ __forceinline__ void mma16816(float* c, const uint32_t* a, uint32_t b0, uint32_t b1) {
    asm volatile(
        "mma.sync.aligned.m16n8k16.row.col.f32.f16.f16.f32 "
        "{%0,%1,%2,%3}, {%4,%5,%6,%7}, {%8,%9}, {%0,%1,%2,%3};\n"
        : "+f"(c[0]), "+f"(c[1]), "+f"(c[2]), "+f"(c[3])
        : "r"(a[0]), "r"(a[1]), "r"(a[2]), "r"(a[3]), "r"(b0), "r"(b1));
}

// ---------------- fp32 -> (hi,lo) fp16 conversion ----------------
__global__ __launch_bounds__(256) void cvt_hilo(const float* __restrict__ x,
                                                half* __restrict__ h, half* __restrict__ l,
                                                int n)
{
    int i = (blockIdx.x * 256 + threadIdx.x) * 4;
    if (i >= n) return;
    float4 v = *(const float4*)(x + i);
    half h0, h1, h2, h3, l0, l1, l2, l3;
    f2hilo(v.x, h0, l0); f2hilo(v.y, h1, l1);
    f2hilo(v.z, h2, l2); f2hilo(v.w, h3, l3);
    *(uint32_t*)(h + i)     = packh(h0, h1);
    *(uint32_t*)(h + i + 2) = packh(h2, h3);
    *(uint32_t*)(l + i)     = packh(l0, l1);
    *(uint32_t*)(l + i + 2) = packh(l2, l3);
}

// fp32 -> single fp16
__global__ __launch_bounds__(256) void cvt_h(const float* __restrict__ x,
                                             half* __restrict__ h, int n)
{
    int i = (blockIdx.x * 256 + threadIdx.x) * 4;
    if (i >= n) return;
    float4 v = *(const float4*)(x + i);
    *(uint32_t*)(h + i)     = packh(__float2half(v.x), __float2half(v.y));
    *(uint32_t*)(h + i + 2) = packh(__float2half(v.z), __float2half(v.w));
}

// ---------------- fp16 GEMM (mma.sync) — R5 mainloop, templated on TERMS ----------------
// C[M,N] = A[M,K] * (Bh[+Bl])[N,K]^T
// 128x128 block, BK=32, 256 threads (8 warps, 2x4), warp tile 64x32.
#define EPI_STORE 0
#define EPI_ADD   1
#define EPI_GELU  2
#define EPI_HILO  3

template<int TERMS, int EPI>
__global__ __launch_bounds__(256) void gemm_f16(
    const half* __restrict__ A,
    const half* __restrict__ Bh, const half* __restrict__ Bl,
    float* __restrict__ C, half* __restrict__ Ch, half* __restrict__ Cl,
    int M, int N, int K)
{
    constexpr uint32_t STAGE = 8192u * (1 + TERMS);   // [A | Bh (| Bl)]

    extern __shared__ uint8_t smem[];
    const uint32_t smem_u32 = (uint32_t)__cvta_generic_to_shared(smem);

    const int tid  = threadIdx.x;
    const int lane = tid & 31;
    const int wid  = tid >> 5;
    const int wm   = wid & 1;
    const int wn   = wid >> 1;
    const int bm   = blockIdx.y * 128;
    const int bn   = blockIdx.x * 128;

    const half* Ab  = A  + (size_t)bm * K;
    const half* Bhb = Bh + (size_t)bn * K;
    const half* Blb = (TERMS == 2) ? (Bl + (size_t)bn * K) : nullptr;

    float acc[4][4][4];
#pragma unroll
    for (int a = 0; a < 4; a++)
#pragma unroll
        for (int b = 0; b < 4; b++)
#pragma unroll
            for (int c = 0; c < 4; c++) acc[a][b][c] = 0.f;

    const int ntiles = K >> 5;

    auto load_stage = [&](int st, int k0) {
        uint32_t base = smem_u32 + (uint32_t)st * STAGE;
#pragma unroll
        for (int i = 0; i < 2; i++) {
            int idx = tid * 2 + i;          // 0..511
            int r = idx >> 2, c = idx & 3;
            size_t go = (size_t)r * K + k0 + c * 8;
            uint32_t so = base + r * 64 + (((uint32_t)(c ^ (r & 3))) << 4);
            cp_async16(so,         Ab  + go);
            cp_async16(so + 8192,  Bhb + go);
            if (TERMS == 2) cp_async16(so + 16384, Blb + go);
        }
    };

    load_stage(0, 0);
    cp_commit();

    for (int t = 0; t < ntiles; t++) {
        if (t + 1 < ntiles) {
            load_stage((t + 1) & 1, (t + 1) << 5);
            cp_commit();
            cp_wait<1>();
        } else {
            cp_wait<0>();
        }
        __syncthreads();

        const uint32_t bA  = smem_u32 + (uint32_t)(t & 1) * STAGE;
        const uint32_t bBh = bA + 8192;
        const uint32_t bBl = bA + 16384;

#pragma unroll
        for (int s = 0; s < 2; s++) {
            uint32_t af[4][4];
#pragma unroll
            for (int mt = 0; mt < 4; mt++) {
                int row = wm * 64 + mt * 16 + (lane & 15);
                int ch  = 2 * s + (lane >> 4);
                uint32_t off = row * 64 + (((uint32_t)(ch ^ (row & 3))) << 4);
                ldsm4(af[mt], bA + off);
            }
            uint32_t bh[2][4], bl[2][4];
#pragma unroll
            for (int p = 0; p < 2; p++) {
                int row = wn * 32 + p * 16 + (lane & 15);
                int ch  = 2 * s + (lane >> 4);
                uint32_t off = row * 64 + (((uint32_t)(ch ^ (row & 3))) << 4);
                ldsm4(bh[p], bBh + off);
                if (TERMS == 2) ldsm4(bl[p], bBl + off);
            }
            // waves of 16 independent MMAs
#pragma unroll
            for (int mt = 0; mt < 4; mt++)
#pragma unroll
                for (int nt = 0; nt < 4; nt++) {
                    int p = nt >> 1, q = nt & 1;
                    mma16816(acc[mt][nt], af[mt], bh[p][q], bh[p][q + 2]);
                }
            if (TERMS == 2) {
#pragma unroll
                for (int mt = 0; mt < 4; mt++)
#pragma unroll
                    for (int nt = 0; nt < 4; nt++) {
                        int p = nt >> 1, q = nt & 1;
                        mma16816(acc[mt][nt], af[mt], bl[p][q], bl[p][q + 2]);
                    }
            }
        }
        __syncthreads();
    }

    // --- epilogue ---
#pragma unroll
    for (int mt = 0; mt < 4; mt++) {
#pragma unroll
        for (int nt = 0; nt < 4; nt++) {
            int row = bm + wm * 64 + mt * 16 + (lane >> 2);
            int col = bn + wn * 32 + nt * 8 + (lane & 3) * 2;
            size_t i0 = (size_t)row * N + col;
            size_t i1 = i0 + (size_t)8 * N;
            float* c = acc[mt][nt];
            if (EPI == EPI_STORE) {
                *(float2*)(C + i0) = make_float2(c[0], c[1]);
                *(float2*)(C + i1) = make_float2(c[2], c[3]);
            } else if (EPI == EPI_ADD) {
                C[i0]   += c[0]; C[i0+1] += c[1];
                C[i1]   += c[2]; C[i1+1] += c[3];
            } else if (EPI == EPI_GELU) {
#pragma unroll
                for (int e = 0; e < 4; e += 2) {
                    size_t ii = (e == 0) ? i0 : i1;
                    float v0 = c[e], v1 = c[e+1];
                    float q0 = 0.5f * v0 * (1.f + erff(v0 * 0.70710678118654752f));
                    float q1 = 0.5f * v1 * (1.f + erff(v1 * 0.70710678118654752f));
                    *(uint32_t*)(Ch + ii) = packh(__float2half(q0), __float2half(q1));
                }
            } else {  // EPI_HILO
#pragma unroll
                for (int e = 0; e < 4; e += 2) {
                    size_t ii = (e == 0) ? i0 : i1;
                    half h0, l0, h1, l1;
                    f2hilo(c[e], h0, l0); f2hilo(c[e+1], h1, l1);
                    *(uint32_t*)(Ch + ii) = packh(h0, h1);
                    *(uint32_t*)(Cl + ii) = packh(l0, l1);
                }
            }
        }
    }
}

// ---------------- flash attention (split-fp16 mma.sync) ----------------
__global__ __launch_bounds__(256) void flash_kernel(
    const half* __restrict__ qkvh, const half* __restrict__ qkvl,
    half* __restrict__ o)
{
    extern __shared__ uint8_t fsm[];
    const uint32_t sb  = (uint32_t)__cvta_generic_to_shared(fsm);
    const uint32_t sQh = sb, sQl = sb + 16384;
    const uint32_t sKV = sb + 32768;

    const int tid = threadIdx.x, lane = tid & 31, w = tid >> 5;
    const int qi = (int)gridDim.x - 1 - (int)blockIdx.x;
    const int bh = blockIdx.y;
    const int b = bh >> 4, h = bh & 15;
    const int qbase = qi * 128;
    const int nkb = (qbase + 128) >> 6;

    const size_t tb = (size_t)b * TSEQ;
    const half* Qh_ = qkvh + tb * 3 * DMODEL + h * HDIM;
    const half* Ql_ = qkvl + tb * 3 * DMODEL + h * HDIM;
    const half* Kh_ = Qh_ + DMODEL;
    const half* Kl_ = Ql_ + DMODEL;
    const half* Vh_ = Qh_ + 2 * DMODEL;
    const half* Vl_ = Ql_ + 2 * DMODEL;

    auto load_kv = [&](int buf, int kb) {
        uint32_t base = sKV + (uint32_t)buf * 32768;
#pragma unroll
        for (int i = 0; i < 2; i++) {
            int idx = tid * 2 + i;
            int r = idx >> 3, c = idx & 7;
            size_t go = (size_t)(kb * 64 + r) * 3 * DMODEL + c * 8;
            uint32_t so = r * 128 + (((uint32_t)(c ^ (r & 7))) << 4);
            cp_async16(base + so,         Kh_ + go);
            cp_async16(base + 8192 + so,  Kl_ + go);
            cp_async16(base + 16384 + so, Vh_ + go);
            cp_async16(base + 24576 + so, Vl_ + go);
        }
    };

#pragma unroll
    for (int i = 0; i < 4; i++) {
        int idx = tid * 4 + i;
        int r = idx >> 3, c = idx & 7;
        size_t go = (size_t)(qbase + r) * 3 * DMODEL + c * 8;
        uint32_t so = r * 128 + (((uint32_t)(c ^ (r & 7))) << 4);
        cp_async16(sQh + so, Qh_ + go);
        cp_async16(sQl + so, Ql_ + go);
    }
    load_kv(0, 0);
    cp_commit();
    if (nkb > 1) { load_kv(1, 1); cp_commit(); cp_wait<1>(); }
    else cp_wait<0>();
    __syncthreads();

    uint32_t qfh[4][4], qfl[4][4];
#pragma unroll
    for (int s = 0; s < 4; s++) {
        int r = 16 * w + (lane & 15);
        int c = 2 * s + (lane >> 4);
        uint32_t so = r * 128 + (((uint32_t)(c ^ (r & 7))) << 4);
        ldsm4(qfh[s], sQh + so);
        ldsm4(qfl[s], sQl + so);
    }

    float oacc[8][4];
#pragma unroll
    for (int j = 0; j < 8; j++)
#pragma unroll
        for (int c = 0; c < 4; c++) oacc[j][c] = 0.f;
    float mrow0 = -1e30f, mrow1 = -1e30f, lrow0 = 0.f, lrow1 = 0.f;
    const int r0 = qbase + 16 * w + (lane >> 2);

    for (int kb = 0; kb < nkb; kb++) {
        if (kb * 64 <= qbase + 16 * w + 15) {
            uint32_t base = sKV + (uint32_t)(kb & 1) * 32768;
            float sacc[8][4];
#pragma unroll
            for (int j = 0; j < 8; j++)
#pragma unroll
                for (int c = 0; c < 4; c++) sacc[j][c] = 0.f;

#pragma unroll
            for (int p = 0; p < 4; p++) {
                int rr = 16 * p + (lane & 15);
#pragma unroll
                for (int s = 0; s < 4; s++) {
                    int cc = 2 * s + (lane >> 4);
                    uint32_t so = rr * 128 + (((uint32_t)(cc ^ (rr & 7))) << 4);
                    uint32_t kh4[4], kl4[4];
                    ldsm4(kh4, base + so);
                    ldsm4(kl4, base + 8192 + so);
                    mma16816(sacc[2*p],   qfh[s], kh4[0], kh4[2]);
                    mma16816(sacc[2*p+1], qfh[s], kh4[1], kh4[3]);
                    mma16816(sacc[2*p],   qfh[s], kl4[0], kl4[2]);
                    mma16816(sacc[2*p+1], qfh[s], kl4[1], kl4[3]);
                    mma16816(sacc[2*p],   qfl[s], kh4[0], kh4[2]);
                    mma16816(sacc[2*p+1], qfl[s], kh4[1], kh4[3]);
                }
            }
            int cbase = kb * 64 + 2 * (lane & 3);
#pragma unroll
            for (int j = 0; j < 8; j++) {
                int c0 = cbase + 8 * j;
                sacc[j][0] = (c0     <= r0    ) ? sacc[j][0] * 0.125f : -1e30f;
                sacc[j][1] = (c0 + 1 <= r0    ) ? sacc[j][1] * 0.125f : -1e30f;
                sacc[j][2] = (c0     <= r0 + 8) ? sacc[j][2] * 0.125f : -1e30f;
                sacc[j][3] = (c0 + 1 <= r0 + 8) ? sacc[j][3] * 0.125f : -1e30f;
            }
            float mx0 = -1e30f, mx1 = -1e30f;
#pragma unroll
            for (int j = 0; j < 8; j++) {
                mx0 = fmaxf(mx0, fmaxf(sacc[j][0], sacc[j][1]));
                mx1 = fmaxf(mx1, fmaxf(sacc[j][2], sacc[j][3]));
            }
            mx0 = fmaxf(mx0, __shfl_xor_sync(0xffffffffu, mx0, 1));
            mx0 = fmaxf(mx0, __shfl_xor_sync(0xffffffffu, mx0, 2));
            mx1 = fmaxf(mx1, __shfl_xor_sync(0xffffffffu, mx1, 1));
            mx1 = fmaxf(mx1, __shfl_xor_sync(0xffffffffu, mx1, 2));
            float mn0 = fmaxf(mrow0, mx0), mn1 = fmaxf(mrow1, mx1);
            float al0 = __expf(mrow0 - mn0), al1 = __expf(mrow1 - mn1);
            mrow0 = mn0; mrow1 = mn1;

            uint32_t ph[8][2], pl[8][2];
            float ls0 = 0.f, ls1 = 0.f;
#pragma unroll
            for (int j = 0; j < 8; j++) {
                float p0 = __expf(sacc[j][0] - mn0);
                float p1 = __expf(sacc[j][1] - mn0);
                float p2 = __expf(sacc[j][2] - mn1);
                float p3 = __expf(sacc[j][3] - mn1);
                ls0 += p0 + p1; ls1 += p2 + p3;
                half h0, l0, h1, l1, h2, l2, h3, l3;
                f2hilo(p0, h0, l0); f2hilo(p1, h1, l1);
                f2hilo(p2, h2, l2); f2hilo(p3, h3, l3);
                ph[j][0] = packh(h0, h1); pl[j][0] = packh(l0, l1);
                ph[j][1] = packh(h2, h3); pl[j][1] = packh(l2, l3);
            }
            ls0 += __shfl_xor_sync(0xffffffffu, ls0, 1);
            ls0 += __shfl_xor_sync(0xffffffffu, ls0, 2);
            ls1 += __shfl_xor_sync(0xffffffffu, ls1, 1);
            ls1 += __shfl_xor_sync(0xffffffffu, ls1, 2);
            lrow0 = lrow0 * al0 + ls0;
            lrow1 = lrow1 * al1 + ls1;
#pragma unroll
            for (int j = 0; j < 8; j++) {
                oacc[j][0] *= al0; oacc[j][1] *= al0;
                oacc[j][2] *= al1; oacc[j][3] *= al1;
            }
#pragma unroll
            for (int pv = 0; pv < 4; pv++) {
#pragma unroll
                for (int s = 0; s < 4; s++) {
                    int tok = 16 * s + ((lane >> 3) & 1) * 8 + (lane & 7);
                    int dc  = 16 * pv + (lane >> 4) * 8;
                    uint32_t so = tok * 128 + ((((uint32_t)(dc >> 3)) ^ (uint32_t)(tok & 7)) << 4);
                    uint32_t v4h[4], v4l[4];
                    ldsm4t(v4h, base + 16384 + so);
                    ldsm4t(v4l, base + 24576 + so);
                    uint32_t pah[4] = {ph[2*s][0], ph[2*s][1], ph[2*s+1][0], ph[2*s+1][1]};
                    uint32_t pal[4] = {pl[2*s][0], pl[2*s][1], pl[2*s+1][0], pl[2*s+1][1]};
                    mma16816(oacc[2*pv],   pah, v4h[0], v4h[1]);
                    mma16816(oacc[2*pv+1], pah, v4h[2], v4h[3]);
                    mma16816(oacc[2*pv],   pah, v4l[0], v4l[1]);
                    mma16816(oacc[2*pv+1], pah, v4l[2], v4l[3]);
                    mma16816(oacc[2*pv],   pal, v4h[0], v4h[1]);
                    mma16816(oacc[2*pv+1], pal, v4h[2], v4h[3]);
                }
            }
        }
        __syncthreads();
        if (kb + 1 < nkb) {
            if (kb + 2 < nkb) { load_kv(kb & 1, kb + 2); cp_commit(); cp_wait<1>(); }
            else cp_wait<0>();
            __syncthreads();
        }
    }

    float rl0 = 1.f / lrow0, rl1 = 1.f / lrow1;
    size_t ob0 = (tb + r0) * (size_t)DMODEL + h * HDIM + 2 * (lane & 3);
    size_t ob1 = ob0 + 8 * (size_t)DMODEL;
#pragma unroll
    for (int j = 0; j < 8; j++) {
        *(uint32_t*)(o + ob0 + 8 * j) =
            packh(__float2half(oacc[j][0] * rl0), __float2half(oacc[j][1] * rl0));
        *(uint32_t*)(o + ob1 + 8 * j) =
            packh(__float2half(oacc[j][2] * rl1), __float2half(oacc[j][3] * rl1));
    }
}

// ---------------- embedding ----------------
__global__ void embed_kernel(const int* __restrict__ idx,
                             const float* __restrict__ tok,
                             const float* __restrict__ pos,
                             float* __restrict__ x)
{
    int t = blockIdx.x;
    int token = idx[t];
    const float* tr = tok + (size_t)token * DMODEL;
    const float* pr = pos + (size_t)(t & (TSEQ - 1)) * DMODEL;
    float* xr = x + (size_t)t * DMODEL;
    for (int d = threadIdx.x; d < DMODEL; d += blockDim.x)
        xr[d] = tr[d] + pr[d];
}

// ---------------- layernorm: warp per row, 8 rows/CTA ----------------
__global__ __launch_bounds__(256) void layernorm_kernel(
    const float* __restrict__ x, half* __restrict__ y,
    const float* __restrict__ w, const float* __restrict__ bvec)
{
    int lane = threadIdx.x & 31, wid = threadIdx.x >> 5;
    int row = blockIdx.x * 8 + wid;
    const float4* px = (const float4*)(x + (size_t)row * DMODEL);

    float4 v[8];
    float s = 0.f, ss = 0.f;
#pragma unroll
    for (int c = 0; c < 8; c++) {
        v[c] = px[lane + c * 32];
        s  += v[c].x + v[c].y + v[c].z + v[c].w;
        ss += v[c].x*v[c].x + v[c].y*v[c].y + v[c].z*v[c].z + v[c].w*v[c].w;
    }
#pragma unroll
    for (int o = 16; o; o >>= 1) {
        s  += __shfl_xor_sync(0xffffffffu, s,  o);
        ss += __shfl_xor_sync(0xffffffffu, ss, o);
    }
    float mean = s * (1.f / DMODEL);
    float var  = ss * (1.f / DMODEL) - mean * mean;
    float inv  = rsqrtf(var + 1e-5f);

    half* py = y + (size_t)row * DMODEL;
#pragma unroll
    for (int c = 0; c < 8; c++) {
        int j = (lane + c * 32) * 4;
        float4 wv = *(const float4*)(w + j);
        float4 bv = *(const float4*)(bvec + j);
        float y0 = (v[c].x - mean) * inv * wv.x + bv.x;
        float y1 = (v[c].y - mean) * inv * wv.y + bv.y;
        float y2 = (v[c].z - mean) * inv * wv.z + bv.z;
        float y3 = (v[c].w - mean) * inv * wv.w + bv.w;
        uint2 pk;
        pk.x = packh(__float2half(y0), __float2half(y1));
        pk.y = packh(__float2half(y2), __float2half(y3));
        *(uint2*)(py + j) = pk;
    }
}

// ---------------- launch ----------------
extern "C" void kernel_launch(void* const* d_in, const int* in_sizes, int n_in,
                              void* d_out, int out_size)
{
    (void)in_sizes; (void)n_in; (void)out_size;
    const int*   idx     = (const int*)  d_in[0];
    const float* tok_emb = (const float*)d_in[1];
    const float* pos_emb = (const float*)d_in[2];
    const float* ln1_w   = (const float*)d_in[3];
    const float* ln1_b   = (const float*)d_in[4];
    const float* qkv_w   = (const float*)d_in[5];
    const float* out_w   = (const float*)d_in[6];
    const float* ln2_w   = (const float*)d_in[7];
    const float* ln2_b   = (const float*)d_in[8];
    const float* ffn1_w  = (const float*)d_in[9];
    const float* ffn2_w  = (const float*)d_in[10];
    const float* lnf_w   = (const float*)d_in[11];
    const float* lnf_b   = (const float*)d_in[12];
    float* out = (float*)d_out;

    float *x;
    half *h, *qvh, *qvl, *o, *f;
    half *wqh, *wql, *woh, *wol, *w1h, *w1l, *w2h, *w2l, *eh;
    cudaGetSymbolAddress((void**)&x,    g_x);
    cudaGetSymbolAddress((void**)&h,    g_h);
    cudaGetSymbolAddress((void**)&qvh,  g_qkvh); cudaGetSymbolAddress((void**)&qvl, g_qkvl);
    cudaGetSymbolAddress((void**)&o,    g_o);
    cudaGetSymbolAddress((void**)&f,    g_f);
    cudaGetSymbolAddress((void**)&wqh,  g_wqh);  cudaGetSymbolAddress((void**)&wql, g_wql);
    cudaGetSymbolAddress((void**)&woh,  g_woh);  cudaGetSymbolAddress((void**)&wol, g_wol);
    cudaGetSymbolAddress((void**)&w1h,  g_w1h);  cudaGetSymbolAddress((void**)&w1l, g_w1l);
    cudaGetSymbolAddress((void**)&w2h,  g_w2h);  cudaGetSymbolAddress((void**)&w2l, g_w2l);
    cudaGetSymbolAddress((void**)&eh,   g_eh);

    cudaFuncSetAttribute(gemm_f16<2,EPI_HILO>,  cudaFuncAttributeMaxDynamicSharedMemorySize, 49152);
    cudaFuncSetAttribute(gemm_f16<2,EPI_ADD>,   cudaFuncAttributeMaxDynamicSharedMemorySize, 49152);
    cudaFuncSetAttribute(gemm_f16<2,EPI_GELU>,  cudaFuncAttributeMaxDynamicSharedMemorySize, 49152);
    cudaFuncSetAttribute(gemm_f16<1,EPI_STORE>, cudaFuncAttributeMaxDynamicSharedMemorySize, 32768);
    cudaFuncSetAttribute(flash_kernel,          cudaFuncAttributeMaxDynamicSharedMemorySize, 98304);

    // weight conversions
    {
        int n;
        n = NL*3*DMODEL*DMODEL; cvt_hilo<<<n/1024, 256>>>(qkv_w,  wqh, wql, n);
        n = NL*DMODEL*DMODEL;   cvt_hilo<<<n/1024, 256>>>(out_w,  woh, wol, n);
        n = NL*DFF*DMODEL;      cvt_hilo<<<n/1024, 256>>>(ffn1_w, w1h, w1l, n);
        n = NL*DMODEL*DFF;      cvt_hilo<<<n/1024, 256>>>(ffn2_w, w2h, w2l, n);
        n = VOC*DMODEL;         cvt_h<<<n/1024, 256>>>(tok_emb, eh, n);
    }

    embed_kernel<<<MTOK, 256>>>(idx, tok_emb, pos_emb, x);

    for (int l = 0; l < NL; l++) {
        // --- attention block ---
        layernorm_kernel<<<MTOK/8, 256>>>(x, h, ln1_w + l * DMODEL, ln1_b + l * DMODEL);
        gemm_f16<2,EPI_HILO><<<dim3(3*DMODEL/128, MTOK/128), 256, 49152>>>(
            h, wqh + (size_t)l*3*DMODEL*DMODEL, wql + (size_t)l*3*DMODEL*DMODEL,
            nullptr, qvh, qvl, MTOK, 3*DMODEL, DMODEL);
        flash_kernel<<<dim3(TSEQ/128, BATCH*NH), 256, 98304>>>(qvh, qvl, o);
        gemm_f16<2,EPI_ADD><<<dim3(DMODEL/128, MTOK/128), 256, 49152>>>(
            o, woh + (size_t)l*DMODEL*DMODEL, wol + (size_t)l*DMODEL*DMODEL,
            x, nullptr, nullptr, MTOK, DMODEL, DMODEL);
        // --- FFN block ---
        layernorm_kernel<<<MTOK/8, 256>>>(x, h, ln2_w + l * DMODEL, ln2_b + l * DMODEL);
        gemm_f16<2,EPI_GELU><<<dim3(DFF/128, MTOK/128), 256, 49152>>>(
            h, w1h + (size_t)l*DFF*DMODEL, w1l + (size_t)l*DFF*DMODEL,
            nullptr, f, nullptr, MTOK, DFF, DMODEL);
        gemm_f16<2,EPI_ADD><<<dim3(DMODEL/128, MTOK/128), 256, 49152>>>(
            f, w2h + (size_t)l*DMODEL*DFF, w2l + (size_t)l*DMODEL*DFF,
            x, nullptr, nullptr, MTOK, DMODEL, DFF);
    }

    layernorm_kernel<<<MTOK/8, 256>>>(x, h, lnf_w, lnf_b);
    gemm_f16<1,EPI_STORE><<<dim3(VOC/128, MTOK/128), 256, 32768>>>(
        h, eh, nullptr, out, nullptr, nullptr, MTOK, VOC, DMODEL);
}

// round 9
// speedup vs baseline: 1.7372x; 1.4564x over previous
#include <cuda_runtime.h>
#include <cuda_fp16.h>
#include <math.h>
#include <stdint.h>

// ---------------- problem constants ----------------
#define NL     6
#define DMODEL 1024
#define DFF    4096
#define VOC    32000
#define NH     16
#define HDIM   64
#define BATCH  2
#define TSEQ   1024
#define MTOK   (BATCH*TSEQ)   // 2048

// ---------------- scratch (static device globals; no allocation) ----------------
__device__ float g_x[MTOK * DMODEL];

__device__ __align__(16) half g_h  [MTOK * DMODEL];
__device__ __align__(16) half g_qkv[(size_t)MTOK * 3 * DMODEL];
__device__ __align__(16) half g_o  [MTOK * DMODEL];
__device__ __align__(16) half g_f  [(size_t)MTOK * DFF];

__device__ __align__(16) half g_wq[(size_t)NL*3*DMODEL*DMODEL];
__device__ __align__(16) half g_wo[(size_t)NL*DMODEL*DMODEL];
__device__ __align__(16) half g_w1[(size_t)NL*DFF*DMODEL];
__device__ __align__(16) half g_w2[(size_t)NL*DMODEL*DFF];
__device__ __align__(16) half g_eh[(size_t)VOC*DMODEL];

// ---------------- helpers ----------------
__device__ __forceinline__ uint32_t packh(half a, half b) {
    __half2 t; t.x = a; t.y = b;
    return *(uint32_t*)&t;
}

__device__ __forceinline__ void cp_async16(uint32_t s, const void* g) {
    asm volatile("cp.async.cg.shared.global [%0], [%1], 16;\n" :: "r"(s), "l"(g));
}
__device__ __forceinline__ void cp_commit() { asm volatile("cp.async.commit_group;\n"); }
template<int N> __device__ __forceinline__ void cp_wait() {
    asm volatile("cp.async.wait_group %0;\n" :: "n"(N));
}

__device__ __forceinline__ void ldsm4(uint32_t* r, uint32_t addr) {
    asm volatile("ldmatrix.sync.aligned.m8n8.x4.shared.b16 {%0,%1,%2,%3}, [%4];\n"
        : "=r"(r[0]), "=r"(r[1]), "=r"(r[2]), "=r"(r[3]) : "r"(addr));
}
__device__ __forceinline__ void ldsm4t(uint32_t* r, uint32_t addr) {
    asm volatile("ldmatrix.sync.aligned.m8n8.x4.trans.shared.b16 {%0,%1,%2,%3}, [%4];\n"
        : "=r"(r[0]), "=r"(r[1]), "=r"(r[2]), "=r"(r[3]) : "r"(addr));
}

__device__ __forceinline__ void mma16816(float* c, const uint32_t* a, uint32_t b0, uint32_t b1) {
    asm volatile(
        "mma.sync.aligned.m16n8k16.row.col.f32.f16.f16.f32 "
        "{%0,%1,%2,%3}, {%4,%5,%6,%7}, {%8,%9}, {%0,%1,%2,%3};\n"
        : "+f"(c[0]), "+f"(c[1]), "+f"(c[2]), "+f"(c[3])
        : "r"(a[0]), "r"(a[1]), "r"(a[2]), "r"(a[3]), "r"(b0), "r"(b1));
}

// ---------------- fp32 -> fp16 conversion ----------------
__global__ __launch_bounds__(256) void cvt_h(const float* __restrict__ x,
                                             half* __restrict__ h, int n)
{
    int i = (blockIdx.x * 256 + threadIdx.x) * 4;
    if (i >= n) return;
    float4 v = *(const float4*)(x + i);
    *(uint32_t*)(h + i)     = packh(__float2half(v.x), __float2half(v.y));
    *(uint32_t*)(h + i + 2) = packh(__float2half(v.z), __float2half(v.w));
}

// ---------------- fp16 GEMM (mma.sync), single-term weights ----------------
// C[M,N] = A[M,K] * B[N,K]^T
// 128x128 block, BK=32, 256 threads (8 warps, 2x4), warp tile 64x32.
#define EPI_STORE  0
#define EPI_ADD    1
#define EPI_GELU   2
#define EPI_STOREH 3

template<int EPI>
__global__ __launch_bounds__(256) void gemm_f16(
    const half* __restrict__ A, const half* __restrict__ B,
    float* __restrict__ C, half* __restrict__ Ch,
    int M, int N, int K)
{
    constexpr uint32_t STAGE = 16384u;   // [A 8KB | B 8KB]

    extern __shared__ uint8_t smem[];
    const uint32_t smem_u32 = (uint32_t)__cvta_generic_to_shared(smem);

    const int tid  = threadIdx.x;
    const int lane = tid & 31;
    const int wid  = tid >> 5;
    const int wm   = wid & 1;
    const int wn   = wid >> 1;
    const int bm   = blockIdx.y * 128;
    const int bn   = blockIdx.x * 128;

    const half* Ab = A + (size_t)bm * K;
    const half* Bb = B + (size_t)bn * K;

    float acc[4][4][4];
#pragma unroll
    for (int a = 0; a < 4; a++)
#pragma unroll
        for (int b = 0; b < 4; b++)
#pragma unroll
            for (int c = 0; c < 4; c++) acc[a][b][c] = 0.f;

    const int ntiles = K >> 5;

    auto load_stage = [&](int st, int k0) {
        uint32_t base = smem_u32 + (uint32_t)st * STAGE;
#pragma unroll
        for (int i = 0; i < 2; i++) {
            int idx = tid * 2 + i;          // 0..511
            int r = idx >> 2, c = idx & 3;
            size_t go = (size_t)r * K + k0 + c * 8;
            uint32_t so = base + r * 64 + (((uint32_t)(c ^ (r & 3))) << 4);
            cp_async16(so,        Ab + go);
            cp_async16(so + 8192, Bb + go);
        }
    };

    load_stage(0, 0);
    cp_commit();

    for (int t = 0; t < ntiles; t++) {
        if (t + 1 < ntiles) {
            load_stage((t + 1) & 1, (t + 1) << 5);
            cp_commit();
            cp_wait<1>();
        } else {
            cp_wait<0>();
        }
        __syncthreads();

        const uint32_t bA = smem_u32 + (uint32_t)(t & 1) * STAGE;
        const uint32_t bB = bA + 8192;

#pragma unroll
        for (int s = 0; s < 2; s++) {
            uint32_t af[4][4];
#pragma unroll
            for (int mt = 0; mt < 4; mt++) {
                int row = wm * 64 + mt * 16 + (lane & 15);
                int ch  = 2 * s + (lane >> 4);
                uint32_t off = row * 64 + (((uint32_t)(ch ^ (row & 3))) << 4);
                ldsm4(af[mt], bA + off);
            }
            uint32_t bf[2][4];
#pragma unroll
            for (int p = 0; p < 2; p++) {
                int row = wn * 32 + p * 16 + (lane & 15);
                int ch  = 2 * s + (lane >> 4);
                uint32_t off = row * 64 + (((uint32_t)(ch ^ (row & 3))) << 4);
                ldsm4(bf[p], bB + off);
            }
#pragma unroll
            for (int mt = 0; mt < 4; mt++)
#pragma unroll
                for (int nt = 0; nt < 4; nt++) {
                    int p = nt >> 1, q = nt & 1;
                    mma16816(acc[mt][nt], af[mt], bf[p][q], bf[p][q + 2]);
                }
        }
        __syncthreads();
    }

    // --- epilogue ---
#pragma unroll
    for (int mt = 0; mt < 4; mt++) {
#pragma unroll
        for (int nt = 0; nt < 4; nt++) {
            int row = bm + wm * 64 + mt * 16 + (lane >> 2);
            int col = bn + wn * 32 + nt * 8 + (lane & 3) * 2;
            size_t i0 = (size_t)row * N + col;
            size_t i1 = i0 + (size_t)8 * N;
            float* c = acc[mt][nt];
            if (EPI == EPI_STORE) {
                *(float2*)(C + i0) = make_float2(c[0], c[1]);
                *(float2*)(C + i1) = make_float2(c[2], c[3]);
            } else if (EPI == EPI_ADD) {
                C[i0]   += c[0]; C[i0+1] += c[1];
                C[i1]   += c[2]; C[i1+1] += c[3];
            } else if (EPI == EPI_GELU) {
#pragma unroll
                for (int e = 0; e < 4; e += 2) {
                    size_t ii = (e == 0) ? i0 : i1;
                    float v0 = c[e], v1 = c[e+1];
                    float q0 = 0.5f * v0 * (1.f + erff(v0 * 0.70710678118654752f));
                    float q1 = 0.5f * v1 * (1.f + erff(v1 * 0.70710678118654752f));
                    *(uint32_t*)(Ch + ii) = packh(__float2half(q0), __float2half(q1));
                }
            } else {  // EPI_STOREH
                *(uint32_t*)(Ch + i0) = packh(__float2half(c[0]), __float2half(c[1]));
                *(uint32_t*)(Ch + i1) = packh(__float2half(c[2]), __float2half(c[3]));
            }
        }
    }
}

// ---------------- flash attention (single fp16, mma.sync) ----------------
// q-tile 128 (8 warps x 16 rows), key blocks of 64, online softmax.
__global__ __launch_bounds__(256) void flash_kernel(
    const half* __restrict__ qkv, half* __restrict__ o)
{
    extern __shared__ uint8_t fsm[];
    const uint32_t sb  = (uint32_t)__cvta_generic_to_shared(fsm);
    const uint32_t sQ  = sb;                  // 128 x 64 halves = 16KB
    const uint32_t sKV = sb + 16384;          // + stage*16384 : [K 8KB | V 8KB]

    const int tid = threadIdx.x, lane = tid & 31, w = tid >> 5;
    const int qi = (int)gridDim.x - 1 - (int)blockIdx.x;   // big tiles first
    const int bh = blockIdx.y;
    const int b = bh >> 4, h = bh & 15;
    const int qbase = qi * 128;
    const int nkb = (qbase + 128) >> 6;

    const size_t tb = (size_t)b * TSEQ;
    const half* Q_ = qkv + tb * 3 * DMODEL + h * HDIM;
    const half* K_ = Q_ + DMODEL;
    const half* V_ = Q_ + 2 * DMODEL;

    auto load_kv = [&](int buf, int kb) {
        uint32_t base = sKV + (uint32_t)buf * 16384;
#pragma unroll
        for (int i = 0; i < 2; i++) {
            int idx = tid * 2 + i;          // 0..511
            int r = idx >> 3, c = idx & 7;
            size_t go = (size_t)(kb * 64 + r) * 3 * DMODEL + c * 8;
            uint32_t so = r * 128 + (((uint32_t)(c ^ (r & 7))) << 4);
            cp_async16(base + so,        K_ + go);
            cp_async16(base + 8192 + so, V_ + go);
        }
    };

    // Q tile: 128 rows x 64 cols
#pragma unroll
    for (int i = 0; i < 4; i++) {
        int idx = tid * 4 + i;              // 0..1023
        int r = idx >> 3, c = idx & 7;
        size_t go = (size_t)(qbase + r) * 3 * DMODEL + c * 8;
        uint32_t so = r * 128 + (((uint32_t)(c ^ (r & 7))) << 4);
        cp_async16(sQ + so, Q_ + go);
    }
    load_kv(0, 0);
    cp_commit();
    if (nkb > 1) { load_kv(1, 1); cp_commit(); cp_wait<1>(); }
    else cp_wait<0>();
    __syncthreads();

    uint32_t qf[4][4];
#pragma unroll
    for (int s = 0; s < 4; s++) {
        int r = 16 * w + (lane & 15);
        int c = 2 * s + (lane >> 4);
        uint32_t so = r * 128 + (((uint32_t)(c ^ (r & 7))) << 4);
        ldsm4(qf[s], sQ + so);
    }

    float oacc[8][4];
#pragma unroll
    for (int j = 0; j < 8; j++)
#pragma unroll
        for (int c = 0; c < 4; c++) oacc[j][c] = 0.f;
    float mrow0 = -1e30f, mrow1 = -1e30f, lrow0 = 0.f, lrow1 = 0.f;
    const int r0 = qbase + 16 * w + (lane >> 2);

    for (int kb = 0; kb < nkb; kb++) {
        if (kb * 64 <= qbase + 16 * w + 15) {
            uint32_t base = sKV + (uint32_t)(kb & 1) * 16384;
            float sacc[8][4];
#pragma unroll
            for (int j = 0; j < 8; j++)
#pragma unroll
                for (int c = 0; c < 4; c++) sacc[j][c] = 0.f;

#pragma unroll
            for (int p = 0; p < 4; p++) {
                int rr = 16 * p + (lane & 15);
#pragma unroll
                for (int s = 0; s < 4; s++) {
                    int cc = 2 * s + (lane >> 4);
                    uint32_t so = rr * 128 + (((uint32_t)(cc ^ (rr & 7))) << 4);
                    uint32_t k4[4];
                    ldsm4(k4, base + so);
                    mma16816(sacc[2*p],   qf[s], k4[0], k4[2]);
                    mma16816(sacc[2*p+1], qf[s], k4[1], k4[3]);
                }
            }
            int cbase = kb * 64 + 2 * (lane & 3);
#pragma unroll
            for (int j = 0; j < 8; j++) {
                int c0 = cbase + 8 * j;
                sacc[j][0] = (c0     <= r0    ) ? sacc[j][0] * 0.125f : -1e30f;
                sacc[j][1] = (c0 + 1 <= r0    ) ? sacc[j][1] * 0.125f : -1e30f;
                sacc[j][2] = (c0     <= r0 + 8) ? sacc[j][2] * 0.125f : -1e30f;
                sacc[j][3] = (c0 + 1 <= r0 + 8) ? sacc[j][3] * 0.125f : -1e30f;
            }
            float mx0 = -1e30f, mx1 = -1e30f;
#pragma unroll
            for (int j = 0; j < 8; j++) {
                mx0 = fmaxf(mx0, fmaxf(sacc[j][0], sacc[j][1]));
                mx1 = fmaxf(mx1, fmaxf(sacc[j][2], sacc[j][3]));
            }
            mx0 = fmaxf(mx0, __shfl_xor_sync(0xffffffffu, mx0, 1));
            mx0 = fmaxf(mx0, __shfl_xor_sync(0xffffffffu, mx0, 2));
            mx1 = fmaxf(mx1, __shfl_xor_sync(0xffffffffu, mx1, 1));
            mx1 = fmaxf(mx1, __shfl_xor_sync(0xffffffffu, mx1, 2));
            float mn0 = fmaxf(mrow0, mx0), mn1 = fmaxf(mrow1, mx1);
            float al0 = __expf(mrow0 - mn0), al1 = __expf(mrow1 - mn1);
            mrow0 = mn0; mrow1 = mn1;

            uint32_t ph[8][2];
            float ls0 = 0.f, ls1 = 0.f;
#pragma unroll
            for (int j = 0; j < 8; j++) {
                float p0 = __expf(sacc[j][0] - mn0);
                float p1 = __expf(sacc[j][1] - mn0);
                float p2 = __expf(sacc[j][2] - mn1);
                float p3 = __expf(sacc[j][3] - mn1);
                ls0 += p0 + p1; ls1 += p2 + p3;
                ph[j][0] = packh(__float2half(p0), __float2half(p1));
                ph[j][1] = packh(__float2half(p2), __float2half(p3));
            }
            ls0 += __shfl_xor_sync(0xffffffffu, ls0, 1);
            ls0 += __shfl_xor_sync(0xffffffffu, ls0, 2);
            ls1 += __shfl_xor_sync(0xffffffffu, ls1, 1);
            ls1 += __shfl_xor_sync(0xffffffffu, ls1, 2);
            lrow0 = lrow0 * al0 + ls0;
            lrow1 = lrow1 * al1 + ls1;
#pragma unroll
            for (int j = 0; j < 8; j++) {
                oacc[j][0] *= al0; oacc[j][1] *= al0;
                oacc[j][2] *= al1; oacc[j][3] *= al1;
            }
            // P @ V
#pragma unroll
            for (int pv = 0; pv < 4; pv++) {
#pragma unroll
                for (int s = 0; s < 4; s++) {
                    int tok = 16 * s + ((lane >> 3) & 1) * 8 + (lane & 7);
                    int dc  = 16 * pv + (lane >> 4) * 8;
                    uint32_t so = tok * 128 + ((((uint32_t)(dc >> 3)) ^ (uint32_t)(tok & 7)) << 4);
                    uint32_t v4[4];
                    ldsm4t(v4, base + 8192 + so);
                    uint32_t pa[4] = {ph[2*s][0], ph[2*s][1], ph[2*s+1][0], ph[2*s+1][1]};
                    mma16816(oacc[2*pv],   pa, v4[0], v4[1]);
                    mma16816(oacc[2*pv+1], pa, v4[2], v4[3]);
                }
            }
        }
        __syncthreads();
        if (kb + 1 < nkb) {
            if (kb + 2 < nkb) { load_kv(kb & 1, kb + 2); cp_commit(); cp_wait<1>(); }
            else cp_wait<0>();
            __syncthreads();
        }
    }

    float rl0 = 1.f / lrow0, rl1 = 1.f / lrow1;
    size_t ob0 = (tb + r0) * (size_t)DMODEL + h * HDIM + 2 * (lane & 3);
    size_t ob1 = ob0 + 8 * (size_t)DMODEL;
#pragma unroll
    for (int j = 0; j < 8; j++) {
        *(uint32_t*)(o + ob0 + 8 * j) =
            packh(__float2half(oacc[j][0] * rl0), __float2half(oacc[j][1] * rl0));
        *(uint32_t*)(o + ob1 + 8 * j) =
            packh(__float2half(oacc[j][2] * rl1), __float2half(oacc[j][3] * rl1));
    }
}

// ---------------- embedding ----------------
__global__ void embed_kernel(const int* __restrict__ idx,
                             const float* __restrict__ tok,
                             const float* __restrict__ pos,
                             float* __restrict__ x)
{
    int t = blockIdx.x;
    int token = idx[t];
    const float* tr = tok + (size_t)token * DMODEL;
    const float* pr = pos + (size_t)(t & (TSEQ - 1)) * DMODEL;
    float* xr = x + (size_t)t * DMODEL;
    for (int d = threadIdx.x; d < DMODEL; d += blockDim.x)
        xr[d] = tr[d] + pr[d];
}

// ---------------- layernorm: warp per row, 8 rows/CTA ----------------
__global__ __launch_bounds__(256) void layernorm_kernel(
    const float* __restrict__ x, half* __restrict__ y,
    const float* __restrict__ w, const float* __restrict__ bvec)
{
    int lane = threadIdx.x & 31, wid = threadIdx.x >> 5;
    int row = blockIdx.x * 8 + wid;
    const float4* px = (const float4*)(x + (size_t)row * DMODEL);

    float4 v[8];
    float s = 0.f, ss = 0.f;
#pragma unroll
    for (int c = 0; c < 8; c++) {
        v[c] = px[lane + c * 32];
        s  += v[c].x + v[c].y + v[c].z + v[c].w;
        ss += v[c].x*v[c].x + v[c].y*v[c].y + v[c].z*v[c].z + v[c].w*v[c].w;
    }
#pragma unroll
    for (int o = 16; o; o >>= 1) {
        s  += __shfl_xor_sync(0xffffffffu, s,  o);
        ss += __shfl_xor_sync(0xffffffffu, ss, o);
    }
    float mean = s * (1.f / DMODEL);
    float var  = ss * (1.f / DMODEL) - mean * mean;
    float inv  = rsqrtf(var + 1e-5f);

    half* py = y + (size_t)row * DMODEL;
#pragma unroll
    for (int c = 0; c < 8; c++) {
        int j = (lane + c * 32) * 4;
        float4 wv = *(const float4*)(w + j);
        float4 bv = *(const float4*)(bvec + j);
        float y0 = (v[c].x - mean) * inv * wv.x + bv.x;
        float y1 = (v[c].y - mean) * inv * wv.y + bv.y;
        float y2 = (v[c].z - mean) * inv * wv.z + bv.z;
        float y3 = (v[c].w - mean) * inv * wv.w + bv.w;
        uint2 pk;
        pk.x = packh(__float2half(y0), __float2half(y1));
        pk.y = packh(__float2half(y2), __float2half(y3));
        *(uint2*)(py + j) = pk;
    }
}

// ---------------- launch ----------------
extern "C" void kernel_launch(void* const* d_in, const int* in_sizes, int n_in,
                              void* d_out, int out_size)
{
    (void)in_sizes; (void)n_in; (void)out_size;
    const int*   idx     = (const int*)  d_in[0];
    const float* tok_emb = (const float*)d_in[1];
    const float* pos_emb = (const float*)d_in[2];
    const float* ln1_w   = (const float*)d_in[3];
    const float* ln1_b   = (const float*)d_in[4];
    const float* qkv_w   = (const float*)d_in[5];
    const float* out_w   = (const float*)d_in[6];
    const float* ln2_w   = (const float*)d_in[7];
    const float* ln2_b   = (const float*)d_in[8];
    const float* ffn1_w  = (const float*)d_in[9];
    const float* ffn2_w  = (const float*)d_in[10];
    const float* lnf_w   = (const float*)d_in[11];
    const float* lnf_b   = (const float*)d_in[12];
    float* out = (float*)d_out;

    float *x;
    half *h, *qv, *o, *f, *wq, *wo, *w1, *w2, *eh;
    cudaGetSymbolAddress((void**)&x,   g_x);
    cudaGetSymbolAddress((void**)&h,   g_h);
    cudaGetSymbolAddress((void**)&qv,  g_qkv);
    cudaGetSymbolAddress((void**)&o,   g_o);
    cudaGetSymbolAddress((void**)&f,   g_f);
    cudaGetSymbolAddress((void**)&wq,  g_wq);
    cudaGetSymbolAddress((void**)&wo,  g_wo);
    cudaGetSymbolAddress((void**)&w1,  g_w1);
    cudaGetSymbolAddress((void**)&w2,  g_w2);
    cudaGetSymbolAddress((void**)&eh,  g_eh);

    cudaFuncSetAttribute(gemm_f16<EPI_STOREH>, cudaFuncAttributeMaxDynamicSharedMemorySize, 32768);
    cudaFuncSetAttribute(gemm_f16<EPI_ADD>,    cudaFuncAttributeMaxDynamicSharedMemorySize, 32768);
    cudaFuncSetAttribute(gemm_f16<EPI_GELU>,   cudaFuncAttributeMaxDynamicSharedMemorySize, 32768);
    cudaFuncSetAttribute(gemm_f16<EPI_STORE>,  cudaFuncAttributeMaxDynamicSharedMemorySize, 32768);
    cudaFuncSetAttribute(flash_kernel,         cudaFuncAttributeMaxDynamicSharedMemorySize, 49152);

    // weight conversions (single fp16)
    {
        int n;
        n = NL*3*DMODEL*DMODEL; cvt_h<<<n/1024, 256>>>(qkv_w,  wq, n);
        n = NL*DMODEL*DMODEL;   cvt_h<<<n/1024, 256>>>(out_w,  wo, n);
        n = NL*DFF*DMODEL;      cvt_h<<<n/1024, 256>>>(ffn1_w, w1, n);
        n = NL*DMODEL*DFF;      cvt_h<<<n/1024, 256>>>(ffn2_w, w2, n);
        n = VOC*DMODEL;         cvt_h<<<n/1024, 256>>>(tok_emb, eh, n);
    }

    embed_kernel<<<MTOK, 256>>>(idx, tok_emb, pos_emb, x);

    for (int l = 0; l < NL; l++) {
        // --- attention block ---
        layernorm_kernel<<<MTOK/8, 256>>>(x, h, ln1_w + l * DMODEL, ln1_b + l * DMODEL);
        gemm_f16<EPI_STOREH><<<dim3(3*DMODEL/128, MTOK/128), 256, 32768>>>(
            h, wq + (size_t)l*3*DMODEL*DMODEL, nullptr, qv, MTOK, 3*DMODEL, DMODEL);
        flash_kernel<<<dim3(TSEQ/128, BATCH*NH), 256, 49152>>>(qv, o);
        gemm_f16<EPI_ADD><<<dim3(DMODEL/128, MTOK/128), 256, 32768>>>(
            o, wo + (size_t)l*DMODEL*DMODEL, x, nullptr, MTOK, DMODEL, DMODEL);
        // --- FFN block ---
        layernorm_kernel<<<MTOK/8, 256>>>(x, h, ln2_w + l * DMODEL, ln2_b + l * DMODEL);
        gemm_f16<EPI_GELU><<<dim3(DFF/128, MTOK/128), 256, 32768>>>(
            h, w1 + (size_t)l*DFF*DMODEL, nullptr, f, MTOK, DFF, DMODEL);
        gemm_f16<EPI_ADD><<<dim3(DMODEL/128, MTOK/128), 256, 32768>>>(
            f, w2 + (size_t)l*DMODEL*DFF, x, nullptr, MTOK, DMODEL, DFF);
    }

    layernorm_kernel<<<MTOK/8, 256>>>(x, h, lnf_w, lnf_b);
    gemm_f16<EPI_STORE><<<dim3(VOC/128, MTOK/128), 256, 32768>>>(
        h, eh, out, nullptr, MTOK, VOC, DMODEL);
}

// round 10
// speedup vs baseline: 1.8116x; 1.0428x over previous
#include <cuda_runtime.h>
#include <cuda_fp16.h>
#include <math.h>
#include <stdint.h>

// ---------------- problem constants ----------------
#define NL     6
#define DMODEL 1024
#define DFF    4096
#define VOC    32000
#define NH     16
#define HDIM   64
#define BATCH  2
#define TSEQ   1024
#define MTOK   (BATCH*TSEQ)   // 2048

// ---------------- scratch (static device globals; no allocation) ----------------
__device__ float g_x[MTOK * DMODEL];

__device__ __align__(16) half g_h  [MTOK * DMODEL];
__device__ __align__(16) half g_qkv[(size_t)MTOK * 3 * DMODEL];
__device__ __align__(16) half g_o  [MTOK * DMODEL];
__device__ __align__(16) half g_f  [(size_t)MTOK * DFF];

__device__ __align__(16) half g_wq[(size_t)NL*3*DMODEL*DMODEL];
__device__ __align__(16) half g_wo[(size_t)NL*DMODEL*DMODEL];
__device__ __align__(16) half g_w1[(size_t)NL*DFF*DMODEL];
__device__ __align__(16) half g_w2[(size_t)NL*DMODEL*DFF];
__device__ __align__(16) half g_eh[(size_t)VOC*DMODEL];

// ---------------- helpers ----------------
__device__ __forceinline__ uint32_t packh(half a, half b) {
    __half2 t; t.x = a; t.y = b;
    return *(uint32_t*)&t;
}

__device__ __forceinline__ void cp_async16(uint32_t s, const void* g) {
    asm volatile("cp.async.cg.shared.global [%0], [%1], 16;\n" :: "r"(s), "l"(g));
}
__device__ __forceinline__ void cp_commit() { asm volatile("cp.async.commit_group;\n"); }
template<int N> __device__ __forceinline__ void cp_wait() {
    asm volatile("cp.async.wait_group %0;\n" :: "n"(N));
}

__device__ __forceinline__ void ldsm4(uint32_t* r, uint32_t addr) {
    asm volatile("ldmatrix.sync.aligned.m8n8.x4.shared.b16 {%0,%1,%2,%3}, [%4];\n"
        : "=r"(r[0]), "=r"(r[1]), "=r"(r[2]), "=r"(r[3]) : "r"(addr));
}
__device__ __forceinline__ void ldsm4t(uint32_t* r, uint32_t addr) {
    asm volatile("ldmatrix.sync.aligned.m8n8.x4.trans.shared.b16 {%0,%1,%2,%3}, [%4];\n"
        : "=r"(r[0]), "=r"(r[1]), "=r"(r[2]), "=r"(r[3]) : "r"(addr));
}

__device__ __forceinline__ void mma16816(float* c, const uint32_t* a, uint32_t b0, uint32_t b1) {
    asm volatile(
        "mma.sync.aligned.m16n8k16.row.col.f32.f16.f16.f32 "
        "{%0,%1,%2,%3}, {%4,%5,%6,%7}, {%8,%9}, {%0,%1,%2,%3};\n"
        : "+f"(c[0]), "+f"(c[1]), "+f"(c[2]), "+f"(c[3])
        : "r"(a[0]), "r"(a[1]), "r"(a[2]), "r"(a[3]), "r"(b0), "r"(b1));
}

// ---------------- fp32 -> fp16 conversion ----------------
__global__ __launch_bounds__(256) void cvt_h(const float* __restrict__ x,
                                             half* __restrict__ h, int n)
{
    int i = (blockIdx.x * 256 + threadIdx.x) * 4;
    if (i >= n) return;
    float4 v = *(const float4*)(x + i);
    *(uint32_t*)(h + i)     = packh(__float2half(v.x), __float2half(v.y));
    *(uint32_t*)(h + i + 2) = packh(__float2half(v.z), __float2half(v.w));
}

// ---------------- fp16 GEMM (mma.sync), 4-stage cp.async pipeline ----------------
// C[M,N] = A[M,K] * B[N,K]^T
// 128x128 block, BK=32, 256 threads (8 warps, 2x4), warp tile 64x32.
#define EPI_STORE  0
#define EPI_ADD    1
#define EPI_GELU   2
#define EPI_STOREH 3

template<int EPI>
__global__ __launch_bounds__(256) void gemm_f16(
    const half* __restrict__ A, const half* __restrict__ B,
    float* __restrict__ C, half* __restrict__ Ch,
    int M, int N, int K)
{
    constexpr int NS = 4;                 // pipeline stages
    constexpr uint32_t STAGE = 16384u;    // [A 8KB | B 8KB]

    extern __shared__ uint8_t smem[];
    const uint32_t smem_u32 = (uint32_t)__cvta_generic_to_shared(smem);

    const int tid  = threadIdx.x;
    const int lane = tid & 31;
    const int wid  = tid >> 5;
    const int wm   = wid & 1;
    const int wn   = wid >> 1;
    const int bm   = blockIdx.y * 128;
    const int bn   = blockIdx.x * 128;

    const half* Ab = A + (size_t)bm * K;
    const half* Bb = B + (size_t)bn * K;

    float acc[4][4][4];
#pragma unroll
    for (int a = 0; a < 4; a++)
#pragma unroll
        for (int b = 0; b < 4; b++)
#pragma unroll
            for (int c = 0; c < 4; c++) acc[a][b][c] = 0.f;

    const int ntiles = K >> 5;

    auto load_stage = [&](int st, int k0) {
        uint32_t base = smem_u32 + (uint32_t)st * STAGE;
#pragma unroll
        for (int i = 0; i < 2; i++) {
            int idx = tid * 2 + i;          // 0..511
            int r = idx >> 2, c = idx & 3;
            size_t go = (size_t)r * K + k0 + c * 8;
            uint32_t so = base + r * 64 + (((uint32_t)(c ^ (r & 3))) << 4);
            cp_async16(so,        Ab + go);
            cp_async16(so + 8192, Bb + go);
        }
    };

    // prologue: fill NS-1 stages, one commit group each (group g == stage g)
#pragma unroll
    for (int t = 0; t < NS - 1; t++) {
        load_stage(t, t << 5);
        cp_commit();
    }

    for (int t = 0; t < ntiles; t++) {
        cp_wait<NS - 2>();                 // stage t's group complete
        __syncthreads();                   // all warps done reading stage (t-1)&3

        int tn = t + NS - 1;               // prefetch into stage (t+3)&3 == (t-1)&3
        if (tn < ntiles) load_stage(tn & (NS - 1), tn << 5);
        cp_commit();                       // always commit (empty groups in tail)

        const uint32_t bA = smem_u32 + (uint32_t)(t & (NS - 1)) * STAGE;
        const uint32_t bB = bA + 8192;

#pragma unroll
        for (int s = 0; s < 2; s++) {
            uint32_t af[4][4];
#pragma unroll
            for (int mt = 0; mt < 4; mt++) {
                int row = wm * 64 + mt * 16 + (lane & 15);
                int ch  = 2 * s + (lane >> 4);
                uint32_t off = row * 64 + (((uint32_t)(ch ^ (row & 3))) << 4);
                ldsm4(af[mt], bA + off);
            }
            uint32_t bf[2][4];
#pragma unroll
            for (int p = 0; p < 2; p++) {
                int row = wn * 32 + p * 16 + (lane & 15);
                int ch  = 2 * s + (lane >> 4);
                uint32_t off = row * 64 + (((uint32_t)(ch ^ (row & 3))) << 4);
                ldsm4(bf[p], bB + off);
            }
#pragma unroll
            for (int mt = 0; mt < 4; mt++)
#pragma unroll
                for (int nt = 0; nt < 4; nt++) {
                    int p = nt >> 1, q = nt & 1;
                    mma16816(acc[mt][nt], af[mt], bf[p][q], bf[p][q + 2]);
                }
        }
    }

    __syncthreads();

    // --- epilogue ---
#pragma unroll
    for (int mt = 0; mt < 4; mt++) {
#pragma unroll
        for (int nt = 0; nt < 4; nt++) {
            int row = bm + wm * 64 + mt * 16 + (lane >> 2);
            int col = bn + wn * 32 + nt * 8 + (lane & 3) * 2;
            size_t i0 = (size_t)row * N + col;
            size_t i1 = i0 + (size_t)8 * N;
            float* c = acc[mt][nt];
            if (EPI == EPI_STORE) {
                *(float2*)(C + i0) = make_float2(c[0], c[1]);
                *(float2*)(C + i1) = make_float2(c[2], c[3]);
            } else if (EPI == EPI_ADD) {
                C[i0]   += c[0]; C[i0+1] += c[1];
                C[i1]   += c[2]; C[i1+1] += c[3];
            } else if (EPI == EPI_GELU) {
#pragma unroll
                for (int e = 0; e < 4; e += 2) {
                    size_t ii = (e == 0) ? i0 : i1;
                    float v0 = c[e], v1 = c[e+1];
                    float q0 = 0.5f * v0 * (1.f + erff(v0 * 0.70710678118654752f));
                    float q1 = 0.5f * v1 * (1.f + erff(v1 * 0.70710678118654752f));
                    *(uint32_t*)(Ch + ii) = packh(__float2half(q0), __float2half(q1));
                }
            } else {  // EPI_STOREH
                *(uint32_t*)(Ch + i0) = packh(__float2half(c[0]), __float2half(c[1]));
                *(uint32_t*)(Ch + i1) = packh(__float2half(c[2]), __float2half(c[3]));
            }
        }
    }
}

// ---------------- flash attention (single fp16, mma.sync) ----------------
// q-tile 128 (8 warps x 16 rows), key blocks of 64, online softmax.
__global__ __launch_bounds__(256) void flash_kernel(
    const half* __restrict__ qkv, half* __restrict__ o)
{
    extern __shared__ uint8_t fsm[];
    const uint32_t sb  = (uint32_t)__cvta_generic_to_shared(fsm);
    const uint32_t sQ  = sb;                  // 128 x 64 halves = 16KB
    const uint32_t sKV = sb + 16384;          // + stage*16384 : [K 8KB | V 8KB]

    const int tid = threadIdx.x, lane = tid & 31, w = tid >> 5;
    const int qi = (int)gridDim.x - 1 - (int)blockIdx.x;   // big tiles first
    const int bh = blockIdx.y;
    const int b = bh >> 4, h = bh & 15;
    const int qbase = qi * 128;
    const int nkb = (qbase + 128) >> 6;

    const size_t tb = (size_t)b * TSEQ;
    const half* Q_ = qkv + tb * 3 * DMODEL + h * HDIM;
    const half* K_ = Q_ + DMODEL;
    const half* V_ = Q_ + 2 * DMODEL;

    auto load_kv = [&](int buf, int kb) {
        uint32_t base = sKV + (uint32_t)buf * 16384;
#pragma unroll
        for (int i = 0; i < 2; i++) {
            int idx = tid * 2 + i;          // 0..511
            int r = idx >> 3, c = idx & 7;
            size_t go = (size_t)(kb * 64 + r) * 3 * DMODEL + c * 8;
            uint32_t so = r * 128 + (((uint32_t)(c ^ (r & 7))) << 4);
            cp_async16(base + so,        K_ + go);
            cp_async16(base + 8192 + so, V_ + go);
        }
    };

    // Q tile: 128 rows x 64 cols
#pragma unroll
    for (int i = 0; i < 4; i++) {
        int idx = tid * 4 + i;              // 0..1023
        int r = idx >> 3, c = idx & 7;
        size_t go = (size_t)(qbase + r) * 3 * DMODEL + c * 8;
        uint32_t so = r * 128 + (((uint32_t)(c ^ (r & 7))) << 4);
        cp_async16(sQ + so, Q_ + go);
    }
    load_kv(0, 0);
    cp_commit();
    if (nkb > 1) { load_kv(1, 1); cp_commit(); cp_wait<1>(); }
    else cp_wait<0>();
    __syncthreads();

    uint32_t qf[4][4];
#pragma unroll
    for (int s = 0; s < 4; s++) {
        int r = 16 * w + (lane & 15);
        int c = 2 * s + (lane >> 4);
        uint32_t so = r * 128 + (((uint32_t)(c ^ (r & 7))) << 4);
        ldsm4(qf[s], sQ + so);
    }

    float oacc[8][4];
#pragma unroll
    for (int j = 0; j < 8; j++)
#pragma unroll
        for (int c = 0; c < 4; c++) oacc[j][c] = 0.f;
    float mrow0 = -1e30f, mrow1 = -1e30f, lrow0 = 0.f, lrow1 = 0.f;
    const int r0 = qbase + 16 * w + (lane >> 2);

    for (int kb = 0; kb < nkb; kb++) {
        if (kb * 64 <= qbase + 16 * w + 15) {
            uint32_t base = sKV + (uint32_t)(kb & 1) * 16384;
            float sacc[8][4];
#pragma unroll
            for (int j = 0; j < 8; j++)
#pragma unroll
                for (int c = 0; c < 4; c++) sacc[j][c] = 0.f;

#pragma unroll
            for (int p = 0; p < 4; p++) {
                int rr = 16 * p + (lane & 15);
#pragma unroll
                for (int s = 0; s < 4; s++) {
                    int cc = 2 * s + (lane >> 4);
                    uint32_t so = rr * 128 + (((uint32_t)(cc ^ (rr & 7))) << 4);
                    uint32_t k4[4];
                    ldsm4(k4, base + so);
                    mma16816(sacc[2*p],   qf[s], k4[0], k4[2]);
                    mma16816(sacc[2*p+1], qf[s], k4[1], k4[3]);
                }
            }
            int cbase = kb * 64 + 2 * (lane & 3);
#pragma unroll
            for (int j = 0; j < 8; j++) {
                int c0 = cbase + 8 * j;
                sacc[j][0] = (c0     <= r0    ) ? sacc[j][0] * 0.125f : -1e30f;
                sacc[j][1] = (c0 + 1 <= r0    ) ? sacc[j][1] * 0.125f : -1e30f;
                sacc[j][2] = (c0     <= r0 + 8) ? sacc[j][2] * 0.125f : -1e30f;
                sacc[j][3] = (c0 + 1 <= r0 + 8) ? sacc[j][3] * 0.125f : -1e30f;
            }
            float mx0 = -1e30f, mx1 = -1e30f;
#pragma unroll
            for (int j = 0; j < 8; j++) {
                mx0 = fmaxf(mx0, fmaxf(sacc[j][0], sacc[j][1]));
                mx1 = fmaxf(mx1, fmaxf(sacc[j][2], sacc[j][3]));
            }
            mx0 = fmaxf(mx0, __shfl_xor_sync(0xffffffffu, mx0, 1));
            mx0 = fmaxf(mx0, __shfl_xor_sync(0xffffffffu, mx0, 2));
            mx1 = fmaxf(mx1, __shfl_xor_sync(0xffffffffu, mx1, 1));
            mx1 = fmaxf(mx1, __shfl_xor_sync(0xffffffffu, mx1, 2));
            float mn0 = fmaxf(mrow0, mx0), mn1 = fmaxf(mrow1, mx1);
            float al0 = __expf(mrow0 - mn0), al1 = __expf(mrow1 - mn1);
            mrow0 = mn0; mrow1 = mn1;

            uint32_t ph[8][2];
            float ls0 = 0.f, ls1 = 0.f;
#pragma unroll
            for (int j = 0; j < 8; j++) {
                float p0 = __expf(sacc[j][0] - mn0);
                float p1 = __expf(sacc[j][1] - mn0);
                float p2 = __expf(sacc[j][2] - mn1);
                float p3 = __expf(sacc[j][3] - mn1);
                ls0 += p0 + p1; ls1 += p2 + p3;
                ph[j][0] = packh(__float2half(p0), __float2half(p1));
                ph[j][1] = packh(__float2half(p2), __float2half(p3));
            }
            ls0 += __shfl_xor_sync(0xffffffffu, ls0, 1);
            ls0 += __shfl_xor_sync(0xffffffffu, ls0, 2);
            ls1 += __shfl_xor_sync(0xffffffffu, ls1, 1);
            ls1 += __shfl_xor_sync(0xffffffffu, ls1, 2);
            lrow0 = lrow0 * al0 + ls0;
            lrow1 = lrow1 * al1 + ls1;
#pragma unroll
            for (int j = 0; j < 8; j++) {
                oacc[j][0] *= al0; oacc[j][1] *= al0;
                oacc[j][2] *= al1; oacc[j][3] *= al1;
            }
            // P @ V
#pragma unroll
            for (int pv = 0; pv < 4; pv++) {
#pragma unroll
                for (int s = 0; s < 4; s++) {
                    int tok = 16 * s + ((lane >> 3) & 1) * 8 + (lane & 7);
                    int dc  = 16 * pv + (lane >> 4) * 8;
                    uint32_t so = tok * 128 + ((((uint32_t)(dc >> 3)) ^ (uint32_t)(tok & 7)) << 4);
                    uint32_t v4[4];
                    ldsm4t(v4, base + 8192 + so);
                    uint32_t pa[4] = {ph[2*s][0], ph[2*s][1], ph[2*s+1][0], ph[2*s+1][1]};
                    mma16816(oacc[2*pv],   pa, v4[0], v4[1]);
                    mma16816(oacc[2*pv+1], pa, v4[2], v4[3]);
                }
            }
        }
        __syncthreads();
        if (kb + 1 < nkb) {
            if (kb + 2 < nkb) { load_kv(kb & 1, kb + 2); cp_commit(); cp_wait<1>(); }
            else cp_wait<0>();
            __syncthreads();
        }
    }

    float rl0 = 1.f / lrow0, rl1 = 1.f / lrow1;
    size_t ob0 = (tb + r0) * (size_t)DMODEL + h * HDIM + 2 * (lane & 3);
    size_t ob1 = ob0 + 8 * (size_t)DMODEL;
#pragma unroll
    for (int j = 0; j < 8; j++) {
        *(uint32_t*)(o + ob0 + 8 * j) =
            packh(__float2half(oacc[j][0] * rl0), __float2half(oacc[j][1] * rl0));
        *(uint32_t*)(o + ob1 + 8 * j) =
            packh(__float2half(oacc[j][2] * rl1), __float2half(oacc[j][3] * rl1));
    }
}

// ---------------- embedding ----------------
__global__ void embed_kernel(const int* __restrict__ idx,
                             const float* __restrict__ tok,
                             const float* __restrict__ pos,
                             float* __restrict__ x)
{
    int t = blockIdx.x;
    int token = idx[t];
    const float* tr = tok + (size_t)token * DMODEL;
    const float* pr = pos + (size_t)(t & (TSEQ - 1)) * DMODEL;
    float* xr = x + (size_t)t * DMODEL;
    for (int d = threadIdx.x; d < DMODEL; d += blockDim.x)
        xr[d] = tr[d] + pr[d];
}

// ---------------- layernorm: warp per row, 8 rows/CTA ----------------
__global__ __launch_bounds__(256) void layernorm_kernel(
    const float* __restrict__ x, half* __restrict__ y,
    const float* __restrict__ w, const float* __restrict__ bvec)
{
    int lane = threadIdx.x & 31, wid = threadIdx.x >> 5;
    int row = blockIdx.x * 8 + wid;
    const float4* px = (const float4*)(x + (size_t)row * DMODEL);

    float4 v[8];
    float s = 0.f, ss = 0.f;
#pragma unroll
    for (int c = 0; c < 8; c++) {
        v[c] = px[lane + c * 32];
        s  += v[c].x + v[c].y + v[c].z + v[c].w;
        ss += v[c].x*v[c].x + v[c].y*v[c].y + v[c].z*v[c].z + v[c].w*v[c].w;
    }
#pragma unroll
    for (int o = 16; o; o >>= 1) {
        s  += __shfl_xor_sync(0xffffffffu, s,  o);
        ss += __shfl_xor_sync(0xffffffffu, ss, o);
    }
    float mean = s * (1.f / DMODEL);
    float var  = ss * (1.f / DMODEL) - mean * mean;
    float inv  = rsqrtf(var + 1e-5f);

    half* py = y + (size_t)row * DMODEL;
#pragma unroll
    for (int c = 0; c < 8; c++) {
        int j = (lane + c * 32) * 4;
        float4 wv = *(const float4*)(w + j);
        float4 bv = *(const float4*)(bvec + j);
        float y0 = (v[c].x - mean) * inv * wv.x + bv.x;
        float y1 = (v[c].y - mean) * inv * wv.y + bv.y;
        float y2 = (v[c].z - mean) * inv * wv.z + bv.z;
        float y3 = (v[c].w - mean) * inv * wv.w + bv.w;
        uint2 pk;
        pk.x = packh(__float2half(y0), __float2half(y1));
        pk.y = packh(__float2half(y2), __float2half(y3));
        *(uint2*)(py + j) = pk;
    }
}

// ---------------- launch ----------------
extern "C" void kernel_launch(void* const* d_in, const int* in_sizes, int n_in,
                              void* d_out, int out_size)
{
    (void)in_sizes; (void)n_in; (void)out_size;
    const int*   idx     = (const int*)  d_in[0];
    const float* tok_emb = (const float*)d_in[1];
    const float* pos_emb = (const float*)d_in[2];
    const float* ln1_w   = (const float*)d_in[3];
    const float* ln1_b   = (const float*)d_in[4];
    const float* qkv_w   = (const float*)d_in[5];
    const float* out_w   = (const float*)d_in[6];
    const float* ln2_w   = (const float*)d_in[7];
    const float* ln2_b   = (const float*)d_in[8];
    const float* ffn1_w  = (const float*)d_in[9];
    const float* ffn2_w  = (const float*)d_in[10];
    const float* lnf_w   = (const float*)d_in[11];
    const float* lnf_b   = (const float*)d_in[12];
    float* out = (float*)d_out;

    float *x;
    half *h, *qv, *o, *f, *wq, *wo, *w1, *w2, *eh;
    cudaGetSymbolAddress((void**)&x,   g_x);
    cudaGetSymbolAddress((void**)&h,   g_h);
    cudaGetSymbolAddress((void**)&qv,  g_qkv);
    cudaGetSymbolAddress((void**)&o,   g_o);
    cudaGetSymbolAddress((void**)&f,   g_f);
    cudaGetSymbolAddress((void**)&wq,  g_wq);
    cudaGetSymbolAddress((void**)&wo,  g_wo);
    cudaGetSymbolAddress((void**)&w1,  g_w1);
    cudaGetSymbolAddress((void**)&w2,  g_w2);
    cudaGetSymbolAddress((void**)&eh,  g_eh);

    cudaFuncSetAttribute(gemm_f16<EPI_STOREH>, cudaFuncAttributeMaxDynamicSharedMemorySize, 65536);
    cudaFuncSetAttribute(gemm_f16<EPI_ADD>,    cudaFuncAttributeMaxDynamicSharedMemorySize, 65536);
    cudaFuncSetAttribute(gemm_f16<EPI_GELU>,   cudaFuncAttributeMaxDynamicSharedMemorySize, 65536);
    cudaFuncSetAttribute(gemm_f16<EPI_STORE>,  cudaFuncAttributeMaxDynamicSharedMemorySize, 65536);
    cudaFuncSetAttribute(flash_kernel,         cudaFuncAttributeMaxDynamicSharedMemorySize, 49152);

    // weight conversions (single fp16)
    {
        int n;
        n = NL*3*DMODEL*DMODEL; cvt_h<<<n/1024, 256>>>(qkv_w,  wq, n);
        n = NL*DMODEL*DMODEL;   cvt_h<<<n/1024, 256>>>(out_w,  wo, n);
        n = NL*DFF*DMODEL;      cvt_h<<<n/1024, 256>>>(ffn1_w, w1, n);
        n = NL*DMODEL*DFF;      cvt_h<<<n/1024, 256>>>(ffn2_w, w2, n);
        n = VOC*DMODEL;         cvt_h<<<n/1024, 256>>>(tok_emb, eh, n);
    }

    embed_kernel<<<MTOK, 256>>>(idx, tok_emb, pos_emb, x);

    for (int l = 0; l < NL; l++) {
        // --- attention block ---
        layernorm_kernel<<<MTOK/8, 256>>>(x, h, ln1_w + l * DMODEL, ln1_b + l * DMODEL);
        gemm_f16<EPI_STOREH><<<dim3(3*DMODEL/128, MTOK/128), 256, 65536>>>(
            h, wq + (size_t)l*3*DMODEL*DMODEL, nullptr, qv, MTOK, 3*DMODEL, DMODEL);
        flash_kernel<<<dim3(TSEQ/128, BATCH*NH), 256, 49152>>>(qv, o);
        gemm_f16<EPI_ADD><<<dim3(DMODEL/128, MTOK/128), 256, 65536>>>(
            o, wo + (size_t)l*DMODEL*DMODEL, x, nullptr, MTOK, DMODEL, DMODEL);
        // --- FFN block ---
        layernorm_kernel<<<MTOK/8, 256>>>(x, h, ln2_w + l * DMODEL, ln2_b + l * DMODEL);
        gemm_f16<EPI_GELU><<<dim3(DFF/128, MTOK/128), 256, 65536>>>(
            h, w1 + (size_t)l*DFF*DMODEL, nullptr, f, MTOK, DFF, DMODEL);
        gemm_f16<EPI_ADD><<<dim3(DMODEL/128, MTOK/128), 256, 65536>>>(
            f, w2 + (size_t)l*DMODEL*DFF, x, nullptr, MTOK, DMODEL, DFF);
    }

    layernorm_kernel<<<MTOK/8, 256>>>(x, h, lnf_w, lnf_b);
    gemm_f16<EPI_STORE><<<dim3(VOC/128, MTOK/128), 256, 65536>>>(
        h, eh, out, nullptr, MTOK, VOC, DMODEL);
}

// round 11
// speedup vs baseline: 2.0003x; 1.1042x over previous
#include <cuda_runtime.h>
#include <cuda_fp16.h>
#include <math.h>
#include <stdint.h>

// ---------------- problem constants ----------------
#define NL     6
#define DMODEL 1024
#define DFF    4096
#define VOC    32000
#define NH     16
#define HDIM   64
#define BATCH  2
#define TSEQ   1024
#define MTOK   (BATCH*TSEQ)   // 2048

// ---------------- scratch (static device globals; no allocation) ----------------
__device__ float g_x[MTOK * DMODEL];

__device__ __align__(16) half g_h  [MTOK * DMODEL];
__device__ __align__(16) half g_qkv[(size_t)MTOK * 3 * DMODEL];
__device__ __align__(16) half g_o  [MTOK * DMODEL];
__device__ __align__(16) half g_f  [(size_t)MTOK * DFF];

__device__ __align__(16) half g_wq[(size_t)NL*3*DMODEL*DMODEL];
__device__ __align__(16) half g_wo[(size_t)NL*DMODEL*DMODEL];
__device__ __align__(16) half g_w1[(size_t)NL*DFF*DMODEL];
__device__ __align__(16) half g_w2[(size_t)NL*DMODEL*DFF];
__device__ __align__(16) half g_eh[(size_t)VOC*DMODEL];

// ---------------- helpers ----------------
__device__ __forceinline__ uint32_t packh(half a, half b) {
    __half2 t; t.x = a; t.y = b;
    return *(uint32_t*)&t;
}

__device__ __forceinline__ void cp_async16(uint32_t s, const void* g) {
    asm volatile("cp.async.cg.shared.global [%0], [%1], 16;\n" :: "r"(s), "l"(g));
}
__device__ __forceinline__ void cp_commit() { asm volatile("cp.async.commit_group;\n"); }
template<int N> __device__ __forceinline__ void cp_wait() {
    asm volatile("cp.async.wait_group %0;\n" :: "n"(N));
}

__device__ __forceinline__ void ldsm4(uint32_t* r, uint32_t addr) {
    asm volatile("ldmatrix.sync.aligned.m8n8.x4.shared.b16 {%0,%1,%2,%3}, [%4];\n"
        : "=r"(r[0]), "=r"(r[1]), "=r"(r[2]), "=r"(r[3]) : "r"(addr));
}
__device__ __forceinline__ void ldsm4t(uint32_t* r, uint32_t addr) {
    asm volatile("ldmatrix.sync.aligned.m8n8.x4.trans.shared.b16 {%0,%1,%2,%3}, [%4];\n"
        : "=r"(r[0]), "=r"(r[1]), "=r"(r[2]), "=r"(r[3]) : "r"(addr));
}

__device__ __forceinline__ void mma16816(float* c, const uint32_t* a, uint32_t b0, uint32_t b1) {
    asm volatile(
        "mma.sync.aligned.m16n8k16.row.col.f32.f16.f16.f32 "
        "{%0,%1,%2,%3}, {%4,%5,%6,%7}, {%8,%9}, {%0,%1,%2,%3};\n"
        : "+f"(c[0]), "+f"(c[1]), "+f"(c[2]), "+f"(c[3])
        : "r"(a[0]), "r"(a[1]), "r"(a[2]), "r"(a[3]), "r"(b0), "r"(b1));
}

// ---------------- fp32 -> fp16 conversion ----------------
__global__ __launch_bounds__(256) void cvt_h(const float* __restrict__ x,
                                             half* __restrict__ h, int n)
{
    int i = (blockIdx.x * 256 + threadIdx.x) * 4;
    if (i >= n) return;
    float4 v = *(const float4*)(x + i);
    *(uint32_t*)(h + i)     = packh(__float2half(v.x), __float2half(v.y));
    *(uint32_t*)(h + i + 2) = packh(__float2half(v.z), __float2half(v.w));
}

// ---------------- fp16 GEMM (mma.sync), BK=64, 3-stage cp.async ----------------
// C[M,N] = A[M,K] * B[N,K]^T
// 128x128 block, BK=64, 256 threads (8 warps, 2x4), warp tile 64x32.
#define EPI_STORE  0
#define EPI_ADD    1
#define EPI_GELU   2
#define EPI_STOREH 3

template<int EPI>
__global__ __launch_bounds__(256) void gemm_f16(
    const half* __restrict__ A, const half* __restrict__ B,
    float* __restrict__ C, half* __restrict__ Ch,
    int M, int N, int K)
{
    constexpr int NS = 3;                 // pipeline stages
    constexpr uint32_t STAGE = 32768u;    // [A 16KB | B 16KB]  (128 rows x 128B)

    extern __shared__ uint8_t smem[];
    const uint32_t smem_u32 = (uint32_t)__cvta_generic_to_shared(smem);

    const int tid  = threadIdx.x;
    const int lane = tid & 31;
    const int wid  = tid >> 5;
    const int wm   = wid & 1;
    const int wn   = wid >> 1;
    const int bm   = blockIdx.y * 128;
    const int bn   = blockIdx.x * 128;

    const half* Ab = A + (size_t)bm * K;
    const half* Bb = B + (size_t)bn * K;

    float acc[4][4][4];
#pragma unroll
    for (int a = 0; a < 4; a++)
#pragma unroll
        for (int b = 0; b < 4; b++)
#pragma unroll
            for (int c = 0; c < 4; c++) acc[a][b][c] = 0.f;

    const int ntiles = K >> 6;

    auto load_stage = [&](int st, int k0) {
        uint32_t base = smem_u32 + (uint32_t)st * STAGE;
#pragma unroll
        for (int i = 0; i < 4; i++) {
            int idx = tid * 4 + i;          // 0..1023
            int r = idx >> 3, c = idx & 7;
            size_t go = (size_t)r * K + k0 + c * 8;
            uint32_t so = base + r * 128 + (((uint32_t)(c ^ (r & 7))) << 4);
            cp_async16(so,         Ab + go);
            cp_async16(so + 16384, Bb + go);
        }
    };

    // prologue: fill NS-1 stages, one commit group each
#pragma unroll
    for (int t = 0; t < NS - 1; t++) {
        load_stage(t, t << 6);
        cp_commit();
    }

    int st = 0, stn = NS - 1;
    for (int t = 0; t < ntiles; t++) {
        cp_wait<NS - 2>();                 // stage t's group complete
        __syncthreads();                   // all warps done reading prev stage

        int tn = t + NS - 1;
        if (tn < ntiles) load_stage(stn, tn << 6);
        cp_commit();                       // always commit (empty groups in tail)

        const uint32_t bA = smem_u32 + (uint32_t)st * STAGE;
        const uint32_t bB = bA + 16384;

#pragma unroll
        for (int s = 0; s < 4; s++) {
            uint32_t af[4][4];
#pragma unroll
            for (int mt = 0; mt < 4; mt++) {
                int row = wm * 64 + mt * 16 + (lane & 15);
                int ch  = 2 * s + (lane >> 4);
                uint32_t off = row * 128 + (((uint32_t)(ch ^ (row & 7))) << 4);
                ldsm4(af[mt], bA + off);
            }
            uint32_t bf[2][4];
#pragma unroll
            for (int p = 0; p < 2; p++) {
                int row = wn * 32 + p * 16 + (lane & 15);
                int ch  = 2 * s + (lane >> 4);
                uint32_t off = row * 128 + (((uint32_t)(ch ^ (row & 7))) << 4);
                ldsm4(bf[p], bB + off);
            }
#pragma unroll
            for (int mt = 0; mt < 4; mt++)
#pragma unroll
                for (int nt = 0; nt < 4; nt++) {
                    int p = nt >> 1, q = nt & 1;
                    mma16816(acc[mt][nt], af[mt], bf[p][q], bf[p][q + 2]);
                }
        }

        if (++st == NS) st = 0;
        if (++stn == NS) stn = 0;
    }

    __syncthreads();

    // --- epilogue ---
#pragma unroll
    for (int mt = 0; mt < 4; mt++) {
#pragma unroll
        for (int nt = 0; nt < 4; nt++) {
            int row = bm + wm * 64 + mt * 16 + (lane >> 2);
            int col = bn + wn * 32 + nt * 8 + (lane & 3) * 2;
            size_t i0 = (size_t)row * N + col;
            size_t i1 = i0 + (size_t)8 * N;
            float* c = acc[mt][nt];
            if (EPI == EPI_STORE) {
                *(float2*)(C + i0) = make_float2(c[0], c[1]);
                *(float2*)(C + i1) = make_float2(c[2], c[3]);
            } else if (EPI == EPI_ADD) {
                C[i0]   += c[0]; C[i0+1] += c[1];
                C[i1]   += c[2]; C[i1+1] += c[3];
            } else if (EPI == EPI_GELU) {
#pragma unroll
                for (int e = 0; e < 4; e += 2) {
                    size_t ii = (e == 0) ? i0 : i1;
                    float v0 = c[e], v1 = c[e+1];
                    float q0 = 0.5f * v0 * (1.f + erff(v0 * 0.70710678118654752f));
                    float q1 = 0.5f * v1 * (1.f + erff(v1 * 0.70710678118654752f));
                    *(uint32_t*)(Ch + ii) = packh(__float2half(q0), __float2half(q1));
                }
            } else {  // EPI_STOREH
                *(uint32_t*)(Ch + i0) = packh(__float2half(c[0]), __float2half(c[1]));
                *(uint32_t*)(Ch + i1) = packh(__float2half(c[2]), __float2half(c[3]));
            }
        }
    }
}

// ---------------- flash attention (single fp16, mma.sync) ----------------
// q-tile 128 (8 warps x 16 rows), key blocks of 64, online softmax.
__global__ __launch_bounds__(256) void flash_kernel(
    const half* __restrict__ qkv, half* __restrict__ o)
{
    extern __shared__ uint8_t fsm[];
    const uint32_t sb  = (uint32_t)__cvta_generic_to_shared(fsm);
    const uint32_t sQ  = sb;                  // 128 x 64 halves = 16KB
    const uint32_t sKV = sb + 16384;          // + stage*16384 : [K 8KB | V 8KB]

    const int tid = threadIdx.x, lane = tid & 31, w = tid >> 5;
    const int qi = (int)gridDim.x - 1 - (int)blockIdx.x;   // big tiles first
    const int bh = blockIdx.y;
    const int b = bh >> 4, h = bh & 15;
    const int qbase = qi * 128;
    const int nkb = (qbase + 128) >> 6;

    const size_t tb = (size_t)b * TSEQ;
    const half* Q_ = qkv + tb * 3 * DMODEL + h * HDIM;
    const half* K_ = Q_ + DMODEL;
    const half* V_ = Q_ + 2 * DMODEL;

    auto load_kv = [&](int buf, int kb) {
        uint32_t base = sKV + (uint32_t)buf * 16384;
#pragma unroll
        for (int i = 0; i < 2; i++) {
            int idx = tid * 2 + i;          // 0..511
            int r = idx >> 3, c = idx & 7;
            size_t go = (size_t)(kb * 64 + r) * 3 * DMODEL + c * 8;
            uint32_t so = r * 128 + (((uint32_t)(c ^ (r & 7))) << 4);
            cp_async16(base + so,        K_ + go);
            cp_async16(base + 8192 + so, V_ + go);
        }
    };

    // Q tile: 128 rows x 64 cols
#pragma unroll
    for (int i = 0; i < 4; i++) {
        int idx = tid * 4 + i;              // 0..1023
        int r = idx >> 3, c = idx & 7;
        size_t go = (size_t)(qbase + r) * 3 * DMODEL + c * 8;
        uint32_t so = r * 128 + (((uint32_t)(c ^ (r & 7))) << 4);
        cp_async16(sQ + so, Q_ + go);
    }
    load_kv(0, 0);
    cp_commit();
    if (nkb > 1) { load_kv(1, 1); cp_commit(); cp_wait<1>(); }
    else cp_wait<0>();
    __syncthreads();

    uint32_t qf[4][4];
#pragma unroll
    for (int s = 0; s < 4; s++) {
        int r = 16 * w + (lane & 15);
        int c = 2 * s + (lane >> 4);
        uint32_t so = r * 128 + (((uint32_t)(c ^ (r & 7))) << 4);
        ldsm4(qf[s], sQ + so);
    }

    float oacc[8][4];
#pragma unroll
    for (int j = 0; j < 8; j++)
#pragma unroll
        for (int c = 0; c < 4; c++) oacc[j][c] = 0.f;
    float mrow0 = -1e30f, mrow1 = -1e30f, lrow0 = 0.f, lrow1 = 0.f;
    const int r0 = qbase + 16 * w + (lane >> 2);

    for (int kb = 0; kb < nkb; kb++) {
        if (kb * 64 <= qbase + 16 * w + 15) {
            uint32_t base = sKV + (uint32_t)(kb & 1) * 16384;
            float sacc[8][4];
#pragma unroll
            for (int j = 0; j < 8; j++)
#pragma unroll
                for (int c = 0; c < 4; c++) sacc[j][c] = 0.f;

#pragma unroll
            for (int p = 0; p < 4; p++) {
                int rr = 16 * p + (lane & 15);
#pragma unroll
                for (int s = 0; s < 4; s++) {
                    int cc = 2 * s + (lane >> 4);
                    uint32_t so = rr * 128 + (((uint32_t)(cc ^ (rr & 7))) << 4);
                    uint32_t k4[4];
                    ldsm4(k4, base + so);
                    mma16816(sacc[2*p],   qf[s], k4[0], k4[2]);
                    mma16816(sacc[2*p+1], qf[s], k4[1], k4[3]);
                }
            }
            int cbase = kb * 64 + 2 * (lane & 3);
#pragma unroll
            for (int j = 0; j < 8; j++) {
                int c0 = cbase + 8 * j;
                sacc[j][0] = (c0     <= r0    ) ? sacc[j][0] * 0.125f : -1e30f;
                sacc[j][1] = (c0 + 1 <= r0    ) ? sacc[j][1] * 0.125f : -1e30f;
                sacc[j][2] = (c0     <= r0 + 8) ? sacc[j][2] * 0.125f : -1e30f;
                sacc[j][3] = (c0 + 1 <= r0 + 8) ? sacc[j][3] * 0.125f : -1e30f;
            }
            float mx0 = -1e30f, mx1 = -1e30f;
#pragma unroll
            for (int j = 0; j < 8; j++) {
                mx0 = fmaxf(mx0, fmaxf(sacc[j][0], sacc[j][1]));
                mx1 = fmaxf(mx1, fmaxf(sacc[j][2], sacc[j][3]));
            }
            mx0 = fmaxf(mx0, __shfl_xor_sync(0xffffffffu, mx0, 1));
            mx0 = fmaxf(mx0, __shfl_xor_sync(0xffffffffu, mx0, 2));
            mx1 = fmaxf(mx1, __shfl_xor_sync(0xffffffffu, mx1, 1));
            mx1 = fmaxf(mx1, __shfl_xor_sync(0xffffffffu, mx1, 2));
            float mn0 = fmaxf(mrow0, mx0), mn1 = fmaxf(mrow1, mx1);
            float al0 = __expf(mrow0 - mn0), al1 = __expf(mrow1 - mn1);
            mrow0 = mn0; mrow1 = mn1;

            uint32_t ph[8][2];
            float ls0 = 0.f, ls1 = 0.f;
#pragma unroll
            for (int j = 0; j < 8; j++) {
                float p0 = __expf(sacc[j][0] - mn0);
                float p1 = __expf(sacc[j][1] - mn0);
                float p2 = __expf(sacc[j][2] - mn1);
                float p3 = __expf(sacc[j][3] - mn1);
                ls0 += p0 + p1; ls1 += p2 + p3;
                ph[j][0] = packh(__float2half(p0), __float2half(p1));
                ph[j][1] = packh(__float2half(p2), __float2half(p3));
            }
            ls0 += __shfl_xor_sync(0xffffffffu, ls0, 1);
            ls0 += __shfl_xor_sync(0xffffffffu, ls0, 2);
            ls1 += __shfl_xor_sync(0xffffffffu, ls1, 1);
            ls1 += __shfl_xor_sync(0xffffffffu, ls1, 2);
            lrow0 = lrow0 * al0 + ls0;
            lrow1 = lrow1 * al1 + ls1;
#pragma unroll
            for (int j = 0; j < 8; j++) {
                oacc[j][0] *= al0; oacc[j][1] *= al0;
                oacc[j][2] *= al1; oacc[j][3] *= al1;
            }
            // P @ V
#pragma unroll
            for (int pv = 0; pv < 4; pv++) {
#pragma unroll
                for (int s = 0; s < 4; s++) {
                    int tok = 16 * s + ((lane >> 3) & 1) * 8 + (lane & 7);
                    int dc  = 16 * pv + (lane >> 4) * 8;
                    uint32_t so = tok * 128 + ((((uint32_t)(dc >> 3)) ^ (uint32_t)(tok & 7)) << 4);
                    uint32_t v4[4];
                    ldsm4t(v4, base + 8192 + so);
                    uint32_t pa[4] = {ph[2*s][0], ph[2*s][1], ph[2*s+1][0], ph[2*s+1][1]};
                    mma16816(oacc[2*pv],   pa, v4[0], v4[1]);
                    mma16816(oacc[2*pv+1], pa, v4[2], v4[3]);
                }
            }
        }
        __syncthreads();
        if (kb + 1 < nkb) {
            if (kb + 2 < nkb) { load_kv(kb & 1, kb + 2); cp_commit(); cp_wait<1>(); }
            else cp_wait<0>();
            __syncthreads();
        }
    }

    float rl0 = 1.f / lrow0, rl1 = 1.f / lrow1;
    size_t ob0 = (tb + r0) * (size_t)DMODEL + h * HDIM + 2 * (lane & 3);
    size_t ob1 = ob0 + 8 * (size_t)DMODEL;
#pragma unroll
    for (int j = 0; j < 8; j++) {
        *(uint32_t*)(o + ob0 + 8 * j) =
            packh(__float2half(oacc[j][0] * rl0), __float2half(oacc[j][1] * rl0));
        *(uint32_t*)(o + ob1 + 8 * j) =
            packh(__float2half(oacc[j][2] * rl1), __float2half(oacc[j][3] * rl1));
    }
}

// ---------------- embedding ----------------
__global__ void embed_kernel(const int* __restrict__ idx,
                             const float* __restrict__ tok,
                             const float* __restrict__ pos,
                             float* __restrict__ x)
{
    int t = blockIdx.x;
    int token = idx[t];
    const float* tr = tok + (size_t)token * DMODEL;
    const float* pr = pos + (size_t)(t & (TSEQ - 1)) * DMODEL;
    float* xr = x + (size_t)t * DMODEL;
    for (int d = threadIdx.x; d < DMODEL; d += blockDim.x)
        xr[d] = tr[d] + pr[d];
}

// ---------------- layernorm: warp per row, 8 rows/CTA ----------------
__global__ __launch_bounds__(256) void layernorm_kernel(
    const float* __restrict__ x, half* __restrict__ y,
    const float* __restrict__ w, const float* __restrict__ bvec)
{
    int lane = threadIdx.x & 31, wid = threadIdx.x >> 5;
    int row = blockIdx.x * 8 + wid;
    const float4* px = (const float4*)(x + (size_t)row * DMODEL);

    float4 v[8];
    float s = 0.f, ss = 0.f;
#pragma unroll
    for (int c = 0; c < 8; c++) {
        v[c] = px[lane + c * 32];
        s  += v[c].x + v[c].y + v[c].z + v[c].w;
        ss += v[c].x*v[c].x + v[c].y*v[c].y + v[c].z*v[c].z + v[c].w*v[c].w;
    }
#pragma unroll
    for (int o = 16; o; o >>= 1) {
        s  += __shfl_xor_sync(0xffffffffu, s,  o);
        ss += __shfl_xor_sync(0xffffffffu, ss, o);
    }
    float mean = s * (1.f / DMODEL);
    float var  = ss * (1.f / DMODEL) - mean * mean;
    float inv  = rsqrtf(var + 1e-5f);

    half* py = y + (size_t)row * DMODEL;
#pragma unroll
    for (int c = 0; c < 8; c++) {
        int j = (lane + c * 32) * 4;
        float4 wv = *(const float4*)(w + j);
        float4 bv = *(const float4*)(bvec + j);
        float y0 = (v[c].x - mean) * inv * wv.x + bv.x;
        float y1 = (v[c].y - mean) * inv * wv.y + bv.y;
        float y2 = (v[c].z - mean) * inv * wv.z + bv.z;
        float y3 = (v[c].w - mean) * inv * wv.w + bv.w;
        uint2 pk;
        pk.x = packh(__float2half(y0), __float2half(y1));
        pk.y = packh(__float2half(y2), __float2half(y3));
        *(uint2*)(py + j) = pk;
    }
}

// ---------------- launch ----------------
extern "C" void kernel_launch(void* const* d_in, const int* in_sizes, int n_in,
                              void* d_out, int out_size)
{
    (void)in_sizes; (void)n_in; (void)out_size;
    const int*   idx     = (const int*)  d_in[0];
    const float* tok_emb = (const float*)d_in[1];
    const float* pos_emb = (const float*)d_in[2];
    const float* ln1_w   = (const float*)d_in[3];
    const float* ln1_b   = (const float*)d_in[4];
    const float* qkv_w   = (const float*)d_in[5];
    const float* out_w   = (const float*)d_in[6];
    const float* ln2_w   = (const float*)d_in[7];
    const float* ln2_b   = (const float*)d_in[8];
    const float* ffn1_w  = (const float*)d_in[9];
    const float* ffn2_w  = (const float*)d_in[10];
    const float* lnf_w   = (const float*)d_in[11];
    const float* lnf_b   = (const float*)d_in[12];
    float* out = (float*)d_out;

    float *x;
    half *h, *qv, *o, *f, *wq, *wo, *w1, *w2, *eh;
    cudaGetSymbolAddress((void**)&x,   g_x);
    cudaGetSymbolAddress((void**)&h,   g_h);
    cudaGetSymbolAddress((void**)&qv,  g_qkv);
    cudaGetSymbolAddress((void**)&o,   g_o);
    cudaGetSymbolAddress((void**)&f,   g_f);
    cudaGetSymbolAddress((void**)&wq,  g_wq);
    cudaGetSymbolAddress((void**)&wo,  g_wo);
    cudaGetSymbolAddress((void**)&w1,  g_w1);
    cudaGetSymbolAddress((void**)&w2,  g_w2);
    cudaGetSymbolAddress((void**)&eh,  g_eh);

    cudaFuncSetAttribute(gemm_f16<EPI_STOREH>, cudaFuncAttributeMaxDynamicSharedMemorySize, 98304);
    cudaFuncSetAttribute(gemm_f16<EPI_ADD>,    cudaFuncAttributeMaxDynamicSharedMemorySize, 98304);
    cudaFuncSetAttribute(gemm_f16<EPI_GELU>,   cudaFuncAttributeMaxDynamicSharedMemorySize, 98304);
    cudaFuncSetAttribute(gemm_f16<EPI_STORE>,  cudaFuncAttributeMaxDynamicSharedMemorySize, 98304);
    cudaFuncSetAttribute(flash_kernel,         cudaFuncAttributeMaxDynamicSharedMemorySize, 49152);

    // weight conversions (single fp16)
    {
        int n;
        n = NL*3*DMODEL*DMODEL; cvt_h<<<n/1024, 256>>>(qkv_w,  wq, n);
        n = NL*DMODEL*DMODEL;   cvt_h<<<n/1024, 256>>>(out_w,  wo, n);
        n = NL*DFF*DMODEL;      cvt_h<<<n/1024, 256>>>(ffn1_w, w1, n);
        n = NL*DMODEL*DFF;      cvt_h<<<n/1024, 256>>>(ffn2_w, w2, n);
        n = VOC*DMODEL;         cvt_h<<<n/1024, 256>>>(tok_emb, eh, n);
    }

    embed_kernel<<<MTOK, 256>>>(idx, tok_emb, pos_emb, x);

    for (int l = 0; l < NL; l++) {
        // --- attention block ---
        layernorm_kernel<<<MTOK/8, 256>>>(x, h, ln1_w + l * DMODEL, ln1_b + l * DMODEL);
        gemm_f16<EPI_STOREH><<<dim3(3*DMODEL/128, MTOK/128), 256, 98304>>>(
            h, wq + (size_t)l*3*DMODEL*DMODEL, nullptr, qv, MTOK, 3*DMODEL, DMODEL);
        flash_kernel<<<dim3(TSEQ/128, BATCH*NH), 256, 49152>>>(qv, o);
        gemm_f16<EPI_ADD><<<dim3(DMODEL/128, MTOK/128), 256, 98304>>>(
            o, wo + (size_t)l*DMODEL*DMODEL, x, nullptr, MTOK, DMODEL, DMODEL);
        // --- FFN block ---
        layernorm_kernel<<<MTOK/8, 256>>>(x, h, ln2_w + l * DMODEL, ln2_b + l * DMODEL);
        gemm_f16<EPI_GELU><<<dim3(DFF/128, MTOK/128), 256, 98304>>>(
            h, w1 + (size_t)l*DFF*DMODEL, nullptr, f, MTOK, DFF, DMODEL);
        gemm_f16<EPI_ADD><<<dim3(DMODEL/128, MTOK/128), 256, 98304>>>(
            f, w2 + (size_t)l*DMODEL*DFF, x, nullptr, MTOK, DMODEL, DFF);
    }

    layernorm_kernel<<<MTOK/8, 256>>>(x, h, lnf_w, lnf_b);
    gemm_f16<EPI_STORE><<<dim3(VOC/128, MTOK/128), 256, 98304>>>(
        h, eh, out, nullptr, MTOK, VOC, DMODEL);
}

// round 12
// speedup vs baseline: 2.0026x; 1.0011x over previous
#include <cuda_runtime.h>
#include <cuda_fp16.h>
#include <math.h>
#include <stdint.h>

// ---------------- problem constants ----------------
#define NL     6
#define DMODEL 1024
#define DFF    4096
#define VOC    32000
#define NH     16
#define HDIM   64
#define BATCH  2
#define TSEQ   1024
#define MTOK   (BATCH*TSEQ)   // 2048

// ---------------- scratch (static device globals; no allocation) ----------------
__device__ float g_x[MTOK * DMODEL];

__device__ __align__(16) half g_h  [MTOK * DMODEL];
__device__ __align__(16) half g_qkv[(size_t)MTOK * 3 * DMODEL];
__device__ __align__(16) half g_o  [MTOK * DMODEL];
__device__ __align__(16) half g_f  [(size_t)MTOK * DFF];

__device__ __align__(16) half g_wq[(size_t)NL*3*DMODEL*DMODEL];
__device__ __align__(16) half g_wo[(size_t)NL*DMODEL*DMODEL];
__device__ __align__(16) half g_w1[(size_t)NL*DFF*DMODEL];
__device__ __align__(16) half g_w2[(size_t)NL*DMODEL*DFF];
__device__ __align__(16) half g_eh[(size_t)VOC*DMODEL];

// ---------------- helpers ----------------
__device__ __forceinline__ uint32_t packh(half a, half b) {
    __half2 t; t.x = a; t.y = b;
    return *(uint32_t*)&t;
}

__device__ __forceinline__ void cp_async16(uint32_t s, const void* g) {
    asm volatile("cp.async.cg.shared.global [%0], [%1], 16;\n" :: "r"(s), "l"(g));
}
__device__ __forceinline__ void cp_commit() { asm volatile("cp.async.commit_group;\n"); }
template<int N> __device__ __forceinline__ void cp_wait() {
    asm volatile("cp.async.wait_group %0;\n" :: "n"(N));
}

__device__ __forceinline__ void ldsm4(uint32_t* r, uint32_t addr) {
    asm volatile("ldmatrix.sync.aligned.m8n8.x4.shared.b16 {%0,%1,%2,%3}, [%4];\n"
        : "=r"(r[0]), "=r"(r[1]), "=r"(r[2]), "=r"(r[3]) : "r"(addr));
}
__device__ __forceinline__ void ldsm4t(uint32_t* r, uint32_t addr) {
    asm volatile("ldmatrix.sync.aligned.m8n8.x4.trans.shared.b16 {%0,%1,%2,%3}, [%4];\n"
        : "=r"(r[0]), "=r"(r[1]), "=r"(r[2]), "=r"(r[3]) : "r"(addr));
}

__device__ __forceinline__ void mma16816(float* c, const uint32_t* a, uint32_t b0, uint32_t b1) {
    asm volatile(
        "mma.sync.aligned.m16n8k16.row.col.f32.f16.f16.f32 "
        "{%0,%1,%2,%3}, {%4,%5,%6,%7}, {%8,%9}, {%0,%1,%2,%3};\n"
        : "+f"(c[0]), "+f"(c[1]), "+f"(c[2]), "+f"(c[3])
        : "r"(a[0]), "r"(a[1]), "r"(a[2]), "r"(a[3]), "r"(b0), "r"(b1));
}

// ---------------- fp32 -> fp16 conversion ----------------
__global__ __launch_bounds__(256) void cvt_h(const float* __restrict__ x,
                                             half* __restrict__ h, int n)
{
    int i = (blockIdx.x * 256 + threadIdx.x) * 4;
    if (i >= n) return;
    float4 v = *(const float4*)(x + i);
    *(uint32_t*)(h + i)     = packh(__float2half(v.x), __float2half(v.y));
    *(uint32_t*)(h + i + 2) = packh(__float2half(v.z), __float2half(v.w));
}

// ---------------- fp16 GEMM (mma.sync), BK=64, 3-stage cp.async ----------------
// C[M,N] = A[M,K] * B[N,K]^T
// BM x 128 block, BK=64, 256 threads (8 warps, 2x4), warp tile (BM/2) x 32.
#define EPI_STORE  0
#define EPI_ADD    1
#define EPI_GELU   2
#define EPI_STOREH 3

template<int BM, int EPI>
__global__ __launch_bounds__(256) void gemm_f16(
    const half* __restrict__ A, const half* __restrict__ B,
    float* __restrict__ C, half* __restrict__ Ch,
    int M, int N, int K)
{
    constexpr int NS = 3;                        // pipeline stages
    constexpr int MT = BM / 32;                  // m-tiles (16-row) per warp
    constexpr uint32_t ABYTES = (uint32_t)BM * 128;
    constexpr uint32_t STAGE  = ABYTES + 16384u; // [A | B 16KB] (rows x 128B)

    extern __shared__ uint8_t smem[];
    const uint32_t smem_u32 = (uint32_t)__cvta_generic_to_shared(smem);

    const int tid  = threadIdx.x;
    const int lane = tid & 31;
    const int wid  = tid >> 5;
    const int wm   = wid & 1;
    const int wn   = wid >> 1;
    const int bm   = blockIdx.y * BM;
    const int bn   = blockIdx.x * 128;

    const half* Ab = A + (size_t)bm * K;
    const half* Bb = B + (size_t)bn * K;

    float acc[MT][4][4];
#pragma unroll
    for (int a = 0; a < MT; a++)
#pragma unroll
        for (int b = 0; b < 4; b++)
#pragma unroll
            for (int c = 0; c < 4; c++) acc[a][b][c] = 0.f;

    const int ntiles = K >> 6;

    auto load_stage = [&](int st, int k0) {
        uint32_t base = smem_u32 + (uint32_t)st * STAGE;
#pragma unroll
        for (int i = 0; i < BM/32; i++) {            // A: BM*8 chunks
            int idx = tid * (BM/32) + i;
            int r = idx >> 3, c = idx & 7;
            size_t go = (size_t)r * K + k0 + c * 8;
            uint32_t so = base + r * 128 + (((uint32_t)(c ^ (r & 7))) << 4);
            cp_async16(so, Ab + go);
        }
#pragma unroll
        for (int i = 0; i < 4; i++) {                // B: 1024 chunks
            int idx = tid * 4 + i;
            int r = idx >> 3, c = idx & 7;
            size_t go = (size_t)r * K + k0 + c * 8;
            uint32_t so = base + ABYTES + r * 128 + (((uint32_t)(c ^ (r & 7))) << 4);
            cp_async16(so, Bb + go);
        }
    };

    // prologue: fill NS-1 stages, one commit group each
#pragma unroll
    for (int t = 0; t < NS - 1; t++) {
        load_stage(t, t << 6);
        cp_commit();
    }

    int st = 0, stn = NS - 1;
    for (int t = 0; t < ntiles; t++) {
        cp_wait<NS - 2>();                 // stage t's group complete
        __syncthreads();                   // all warps done reading prev stage

        int tn = t + NS - 1;
        if (tn < ntiles) load_stage(stn, tn << 6);
        cp_commit();                       // always commit (empty groups in tail)

        const uint32_t bA = smem_u32 + (uint32_t)st * STAGE;
        const uint32_t bB = bA + ABYTES;

#pragma unroll
        for (int s = 0; s < 4; s++) {
            uint32_t af[MT][4];
#pragma unroll
            for (int mt = 0; mt < MT; mt++) {
                int row = wm * (BM/2) + mt * 16 + (lane & 15);
                int ch  = 2 * s + (lane >> 4);
                uint32_t off = row * 128 + (((uint32_t)(ch ^ (row & 7))) << 4);
                ldsm4(af[mt], bA + off);
            }
            uint32_t bf[2][4];
#pragma unroll
            for (int p = 0; p < 2; p++) {
                int row = wn * 32 + p * 16 + (lane & 15);
                int ch  = 2 * s + (lane >> 4);
                uint32_t off = row * 128 + (((uint32_t)(ch ^ (row & 7))) << 4);
                ldsm4(bf[p], bB + off);
            }
#pragma unroll
            for (int mt = 0; mt < MT; mt++)
#pragma unroll
                for (int nt = 0; nt < 4; nt++) {
                    int p = nt >> 1, q = nt & 1;
                    mma16816(acc[mt][nt], af[mt], bf[p][q], bf[p][q + 2]);
                }
        }

        if (++st == NS) st = 0;
        if (++stn == NS) stn = 0;
    }

    __syncthreads();

    // --- epilogue ---
#pragma unroll
    for (int mt = 0; mt < MT; mt++) {
#pragma unroll
        for (int nt = 0; nt < 4; nt++) {
            int row = bm + wm * (BM/2) + mt * 16 + (lane >> 2);
            int col = bn + wn * 32 + nt * 8 + (lane & 3) * 2;
            size_t i0 = (size_t)row * N + col;
            size_t i1 = i0 + (size_t)8 * N;
            float* c = acc[mt][nt];
            if (EPI == EPI_STORE) {
                *(float2*)(C + i0) = make_float2(c[0], c[1]);
                *(float2*)(C + i1) = make_float2(c[2], c[3]);
            } else if (EPI == EPI_ADD) {
                C[i0]   += c[0]; C[i0+1] += c[1];
                C[i1]   += c[2]; C[i1+1] += c[3];
            } else if (EPI == EPI_GELU) {
#pragma unroll
                for (int e = 0; e < 4; e += 2) {
                    size_t ii = (e == 0) ? i0 : i1;
                    float v0 = c[e], v1 = c[e+1];
                    float q0 = 0.5f * v0 * (1.f + erff(v0 * 0.70710678118654752f));
                    float q1 = 0.5f * v1 * (1.f + erff(v1 * 0.70710678118654752f));
                    *(uint32_t*)(Ch + ii) = packh(__float2half(q0), __float2half(q1));
                }
            } else {  // EPI_STOREH
                *(uint32_t*)(Ch + i0) = packh(__float2half(c[0]), __float2half(c[1]));
                *(uint32_t*)(Ch + i1) = packh(__float2half(c[2]), __float2half(c[3]));
            }
        }
    }
}

// ---------------- flash attention (single fp16, mma.sync) ----------------
// q-tile 128 (8 warps x 16 rows), key blocks of 64, online softmax.
__global__ __launch_bounds__(256) void flash_kernel(
    const half* __restrict__ qkv, half* __restrict__ o)
{
    extern __shared__ uint8_t fsm[];
    const uint32_t sb  = (uint32_t)__cvta_generic_to_shared(fsm);
    const uint32_t sQ  = sb;                  // 128 x 64 halves = 16KB
    const uint32_t sKV = sb + 16384;          // + stage*16384 : [K 8KB | V 8KB]

    const int tid = threadIdx.x, lane = tid & 31, w = tid >> 5;
    const int qi = (int)gridDim.x - 1 - (int)blockIdx.x;   // big tiles first
    const int bh = blockIdx.y;
    const int b = bh >> 4, h = bh & 15;
    const int qbase = qi * 128;
    const int nkb = (qbase + 128) >> 6;

    const size_t tb = (size_t)b * TSEQ;
    const half* Q_ = qkv + tb * 3 * DMODEL + h * HDIM;
    const half* K_ = Q_ + DMODEL;
    const half* V_ = Q_ + 2 * DMODEL;

    auto load_kv = [&](int buf, int kb) {
        uint32_t base = sKV + (uint32_t)buf * 16384;
#pragma unroll
        for (int i = 0; i < 2; i++) {
            int idx = tid * 2 + i;          // 0..511
            int r = idx >> 3, c = idx & 7;
            size_t go = (size_t)(kb * 64 + r) * 3 * DMODEL + c * 8;
            uint32_t so = r * 128 + (((uint32_t)(c ^ (r & 7))) << 4);
            cp_async16(base + so,        K_ + go);
            cp_async16(base + 8192 + so, V_ + go);
        }
    };

    // Q tile: 128 rows x 64 cols
#pragma unroll
    for (int i = 0; i < 4; i++) {
        int idx = tid * 4 + i;              // 0..1023
        int r = idx >> 3, c = idx & 7;
        size_t go = (size_t)(qbase + r) * 3 * DMODEL + c * 8;
        uint32_t so = r * 128 + (((uint32_t)(c ^ (r & 7))) << 4);
        cp_async16(sQ + so, Q_ + go);
    }
    load_kv(0, 0);
    cp_commit();
    if (nkb > 1) { load_kv(1, 1); cp_commit(); cp_wait<1>(); }
    else cp_wait<0>();
    __syncthreads();

    uint32_t qf[4][4];
#pragma unroll
    for (int s = 0; s < 4; s++) {
        int r = 16 * w + (lane & 15);
        int c = 2 * s + (lane >> 4);
        uint32_t so = r * 128 + (((uint32_t)(c ^ (r & 7))) << 4);
        ldsm4(qf[s], sQ + so);
    }

    float oacc[8][4];
#pragma unroll
    for (int j = 0; j < 8; j++)
#pragma unroll
        for (int c = 0; c < 4; c++) oacc[j][c] = 0.f;
    float mrow0 = -1e30f, mrow1 = -1e30f, lrow0 = 0.f, lrow1 = 0.f;
    const int r0 = qbase + 16 * w + (lane >> 2);

    for (int kb = 0; kb < nkb; kb++) {
        if (kb * 64 <= qbase + 16 * w + 15) {
            uint32_t base = sKV + (uint32_t)(kb & 1) * 16384;
            float sacc[8][4];
#pragma unroll
            for (int j = 0; j < 8; j++)
#pragma unroll
                for (int c = 0; c < 4; c++) sacc[j][c] = 0.f;

#pragma unroll
            for (int p = 0; p < 4; p++) {
                int rr = 16 * p + (lane & 15);
#pragma unroll
                for (int s = 0; s < 4; s++) {
                    int cc = 2 * s + (lane >> 4);
                    uint32_t so = rr * 128 + (((uint32_t)(cc ^ (rr & 7))) << 4);
                    uint32_t k4[4];
                    ldsm4(k4, base + so);
                    mma16816(sacc[2*p],   qf[s], k4[0], k4[2]);
                    mma16816(sacc[2*p+1], qf[s], k4[1], k4[3]);
                }
            }
            int cbase = kb * 64 + 2 * (lane & 3);
#pragma unroll
            for (int j = 0; j < 8; j++) {
                int c0 = cbase + 8 * j;
                sacc[j][0] = (c0     <= r0    ) ? sacc[j][0] * 0.125f : -1e30f;
                sacc[j][1] = (c0 + 1 <= r0    ) ? sacc[j][1] * 0.125f : -1e30f;
                sacc[j][2] = (c0     <= r0 + 8) ? sacc[j][2] * 0.125f : -1e30f;
                sacc[j][3] = (c0 + 1 <= r0 + 8) ? sacc[j][3] * 0.125f : -1e30f;
            }
            float mx0 = -1e30f, mx1 = -1e30f;
#pragma unroll
            for (int j = 0; j < 8; j++) {
                mx0 = fmaxf(mx0, fmaxf(sacc[j][0], sacc[j][1]));
                mx1 = fmaxf(mx1, fmaxf(sacc[j][2], sacc[j][3]));
            }
            mx0 = fmaxf(mx0, __shfl_xor_sync(0xffffffffu, mx0, 1));
            mx0 = fmaxf(mx0, __shfl_xor_sync(0xffffffffu, mx0, 2));
            mx1 = fmaxf(mx1, __shfl_xor_sync(0xffffffffu, mx1, 1));
            mx1 = fmaxf(mx1, __shfl_xor_sync(0xffffffffu, mx1, 2));
            float mn0 = fmaxf(mrow0, mx0), mn1 = fmaxf(mrow1, mx1);
            float al0 = __expf(mrow0 - mn0), al1 = __expf(mrow1 - mn1);
            mrow0 = mn0; mrow1 = mn1;

            uint32_t ph[8][2];
            float ls0 = 0.f, ls1 = 0.f;
#pragma unroll
            for (int j = 0; j < 8; j++) {
                float p0 = __expf(sacc[j][0] - mn0);
                float p1 = __expf(sacc[j][1] - mn0);
                float p2 = __expf(sacc[j][2] - mn1);
                float p3 = __expf(sacc[j][3] - mn1);
                ls0 += p0 + p1; ls1 += p2 + p3;
                ph[j][0] = packh(__float2half(p0), __float2half(p1));
                ph[j][1] = packh(__float2half(p2), __float2half(p3));
            }
            ls0 += __shfl_xor_sync(0xffffffffu, ls0, 1);
            ls0 += __shfl_xor_sync(0xffffffffu, ls0, 2);
            ls1 += __shfl_xor_sync(0xffffffffu, ls1, 1);
            ls1 += __shfl_xor_sync(0xffffffffu, ls1, 2);
            lrow0 = lrow0 * al0 + ls0;
            lrow1 = lrow1 * al1 + ls1;
#pragma unroll
            for (int j = 0; j < 8; j++) {
                oacc[j][0] *= al0; oacc[j][1] *= al0;
                oacc[j][2] *= al1; oacc[j][3] *= al1;
            }
            // P @ V
#pragma unroll
            for (int pv = 0; pv < 4; pv++) {
#pragma unroll
                for (int s = 0; s < 4; s++) {
                    int tok = 16 * s + ((lane >> 3) & 1) * 8 + (lane & 7);
                    int dc  = 16 * pv + (lane >> 4) * 8;
                    uint32_t so = tok * 128 + ((((uint32_t)(dc >> 3)) ^ (uint32_t)(tok & 7)) << 4);
                    uint32_t v4[4];
                    ldsm4t(v4, base + 8192 + so);
                    uint32_t pa[4] = {ph[2*s][0], ph[2*s][1], ph[2*s+1][0], ph[2*s+1][1]};
                    mma16816(oacc[2*pv],   pa, v4[0], v4[1]);
                    mma16816(oacc[2*pv+1], pa, v4[2], v4[3]);
                }
            }
        }
        __syncthreads();
        if (kb + 1 < nkb) {
            if (kb + 2 < nkb) { load_kv(kb & 1, kb + 2); cp_commit(); cp_wait<1>(); }
            else cp_wait<0>();
            __syncthreads();
        }
    }

    float rl0 = 1.f / lrow0, rl1 = 1.f / lrow1;
    size_t ob0 = (tb + r0) * (size_t)DMODEL + h * HDIM + 2 * (lane & 3);
    size_t ob1 = ob0 + 8 * (size_t)DMODEL;
#pragma unroll
    for (int j = 0; j < 8; j++) {
        *(uint32_t*)(o + ob0 + 8 * j) =
            packh(__float2half(oacc[j][0] * rl0), __float2half(oacc[j][1] * rl0));
        *(uint32_t*)(o + ob1 + 8 * j) =
            packh(__float2half(oacc[j][2] * rl1), __float2half(oacc[j][3] * rl1));
    }
}

// ---------------- embedding ----------------
__global__ void embed_kernel(const int* __restrict__ idx,
                             const float* __restrict__ tok,
                             const float* __restrict__ pos,
                             float* __restrict__ x)
{
    int t = blockIdx.x;
    int token = idx[t];
    const float* tr = tok + (size_t)token * DMODEL;
    const float* pr = pos + (size_t)(t & (TSEQ - 1)) * DMODEL;
    float* xr = x + (size_t)t * DMODEL;
    for (int d = threadIdx.x; d < DMODEL; d += blockDim.x)
        xr[d] = tr[d] + pr[d];
}

// ---------------- layernorm: warp per row, 8 rows/CTA ----------------
__global__ __launch_bounds__(256) void layernorm_kernel(
    const float* __restrict__ x, half* __restrict__ y,
    const float* __restrict__ w, const float* __restrict__ bvec)
{
    int lane = threadIdx.x & 31, wid = threadIdx.x >> 5;
    int row = blockIdx.x * 8 + wid;
    const float4* px = (const float4*)(x + (size_t)row * DMODEL);

    float4 v[8];
    float s = 0.f, ss = 0.f;
#pragma unroll
    for (int c = 0; c < 8; c++) {
        v[c] = px[lane + c * 32];
        s  += v[c].x + v[c].y + v[c].z + v[c].w;
        ss += v[c].x*v[c].x + v[c].y*v[c].y + v[c].z*v[c].z + v[c].w*v[c].w;
    }
#pragma unroll
    for (int o = 16; o; o >>= 1) {
        s  += __shfl_xor_sync(0xffffffffu, s,  o);
        ss += __shfl_xor_sync(0xffffffffu, ss, o);
    }
    float mean = s * (1.f / DMODEL);
    float var  = ss * (1.f / DMODEL) - mean * mean;
    float inv  = rsqrtf(var + 1e-5f);

    half* py = y + (size_t)row * DMODEL;
#pragma unroll
    for (int c = 0; c < 8; c++) {
        int j = (lane + c * 32) * 4;
        float4 wv = *(const float4*)(w + j);
        float4 bv = *(const float4*)(bvec + j);
        float y0 = (v[c].x - mean) * inv * wv.x + bv.x;
        float y1 = (v[c].y - mean) * inv * wv.y + bv.y;
        float y2 = (v[c].z - mean) * inv * wv.z + bv.z;
        float y3 = (v[c].w - mean) * inv * wv.w + bv.w;
        uint2 pk;
        pk.x = packh(__float2half(y0), __float2half(y1));
        pk.y = packh(__float2half(y2), __float2half(y3));
        *(uint2*)(py + j) = pk;
    }
}

// ---------------- launch ----------------
extern "C" void kernel_launch(void* const* d_in, const int* in_sizes, int n_in,
                              void* d_out, int out_size)
{
    (void)in_sizes; (void)n_in; (void)out_size;
    const int*   idx     = (const int*)  d_in[0];
    const float* tok_emb = (const float*)d_in[1];
    const float* pos_emb = (const float*)d_in[2];
    const float* ln1_w   = (const float*)d_in[3];
    const float* ln1_b   = (const float*)d_in[4];
    const float* qkv_w   = (const float*)d_in[5];
    const float* out_w   = (const float*)d_in[6];
    const float* ln2_w   = (const float*)d_in[7];
    const float* ln2_b   = (const float*)d_in[8];
    const float* ffn1_w  = (const float*)d_in[9];
    const float* ffn2_w  = (const float*)d_in[10];
    const float* lnf_w   = (const float*)d_in[11];
    const float* lnf_b   = (const float*)d_in[12];
    float* out = (float*)d_out;

    float *x;
    half *h, *qv, *o, *f, *wq, *wo, *w1, *w2, *eh;
    cudaGetSymbolAddress((void**)&x,   g_x);
    cudaGetSymbolAddress((void**)&h,   g_h);
    cudaGetSymbolAddress((void**)&qv,  g_qkv);
    cudaGetSymbolAddress((void**)&o,   g_o);
    cudaGetSymbolAddress((void**)&f,   g_f);
    cudaGetSymbolAddress((void**)&wq,  g_wq);
    cudaGetSymbolAddress((void**)&wo,  g_wo);
    cudaGetSymbolAddress((void**)&w1,  g_w1);
    cudaGetSymbolAddress((void**)&w2,  g_w2);
    cudaGetSymbolAddress((void**)&eh,  g_eh);

    cudaFuncSetAttribute(gemm_f16<128,EPI_STOREH>, cudaFuncAttributeMaxDynamicSharedMemorySize, 98304);
    cudaFuncSetAttribute(gemm_f16<64, EPI_ADD>,    cudaFuncAttributeMaxDynamicSharedMemorySize, 73728);
    cudaFuncSetAttribute(gemm_f16<128,EPI_GELU>,   cudaFuncAttributeMaxDynamicSharedMemorySize, 98304);
    cudaFuncSetAttribute(gemm_f16<128,EPI_STORE>,  cudaFuncAttributeMaxDynamicSharedMemorySize, 98304);
    cudaFuncSetAttribute(flash_kernel,             cudaFuncAttributeMaxDynamicSharedMemorySize, 49152);

    // weight conversions (single fp16)
    {
        int n;
        n = NL*3*DMODEL*DMODEL; cvt_h<<<n/1024, 256>>>(qkv_w,  wq, n);
        n = NL*DMODEL*DMODEL;   cvt_h<<<n/1024, 256>>>(out_w,  wo, n);
        n = NL*DFF*DMODEL;      cvt_h<<<n/1024, 256>>>(ffn1_w, w1, n);
        n = NL*DMODEL*DFF;      cvt_h<<<n/1024, 256>>>(ffn2_w, w2, n);
        n = VOC*DMODEL;         cvt_h<<<n/1024, 256>>>(tok_emb, eh, n);
    }

    embed_kernel<<<MTOK, 256>>>(idx, tok_emb, pos_emb, x);

    for (int l = 0; l < NL; l++) {
        // --- attention block ---
        layernorm_kernel<<<MTOK/8, 256>>>(x, h, ln1_w + l * DMODEL, ln1_b + l * DMODEL);
        gemm_f16<128,EPI_STOREH><<<dim3(3*DMODEL/128, MTOK/128), 256, 98304>>>(
            h, wq + (size_t)l*3*DMODEL*DMODEL, nullptr, qv, MTOK, 3*DMODEL, DMODEL);
        flash_kernel<<<dim3(TSEQ/128, BATCH*NH), 256, 49152>>>(qv, o);
        gemm_f16<64,EPI_ADD><<<dim3(DMODEL/128, MTOK/64), 256, 73728>>>(
            o, wo + (size_t)l*DMODEL*DMODEL, x, nullptr, MTOK, DMODEL, DMODEL);
        // --- FFN block ---
        layernorm_kernel<<<MTOK/8, 256>>>(x, h, ln2_w + l * DMODEL, ln2_b + l * DMODEL);
        gemm_f16<128,EPI_GELU><<<dim3(DFF/128, MTOK/128), 256, 98304>>>(
            h, w1 + (size_t)l*DFF*DMODEL, nullptr, f, MTOK, DFF, DMODEL);
        gemm_f16<64,EPI_ADD><<<dim3(DMODEL/128, MTOK/64), 256, 73728>>>(
            f, w2 + (size_t)l*DMODEL*DFF, x, nullptr, MTOK, DMODEL, DFF);
    }

    layernorm_kernel<<<MTOK/8, 256>>>(x, h, lnf_w, lnf_b);
    gemm_f16<128,EPI_STORE><<<dim3(VOC/128, MTOK/128), 256, 98304>>>(
        h, eh, out, nullptr, MTOK, VOC, DMODEL);
}

// round 13
// speedup vs baseline: 2.0504x; 1.0239x over previous
#include <cuda_runtime.h>
#include <cuda_fp16.h>
#include <math.h>
#include <stdint.h>

// ---------------- problem constants ----------------
#define NL     6
#define DMODEL 1024
#define DFF    4096
#define VOC    32000
#define NH     16
#define HDIM   64
#define BATCH  2
#define TSEQ   1024
#define MTOK   (BATCH*TSEQ)   // 2048

// ---------------- scratch (static device globals; no allocation) ----------------
__device__ float g_x[MTOK * DMODEL];

__device__ __align__(16) half g_h  [MTOK * DMODEL];
__device__ __align__(16) half g_qkv[(size_t)MTOK * 3 * DMODEL];
__device__ __align__(16) half g_o  [MTOK * DMODEL];
__device__ __align__(16) half g_f  [(size_t)MTOK * DFF];

__device__ __align__(16) half g_wq[(size_t)NL*3*DMODEL*DMODEL];
__device__ __align__(16) half g_wo[(size_t)NL*DMODEL*DMODEL];
__device__ __align__(16) half g_w1[(size_t)NL*DFF*DMODEL];
__device__ __align__(16) half g_w2[(size_t)NL*DMODEL*DFF];
__device__ __align__(16) half g_eh[(size_t)VOC*DMODEL];

// ---------------- helpers ----------------
__device__ __forceinline__ uint32_t packh(half a, half b) {
    __half2 t; t.x = a; t.y = b;
    return *(uint32_t*)&t;
}

__device__ __forceinline__ void cp_async16(uint32_t s, const void* g) {
    asm volatile("cp.async.cg.shared.global [%0], [%1], 16;\n" :: "r"(s), "l"(g));
}
__device__ __forceinline__ void cp_commit() { asm volatile("cp.async.commit_group;\n"); }
template<int N> __device__ __forceinline__ void cp_wait() {
    asm volatile("cp.async.wait_group %0;\n" :: "n"(N));
}

__device__ __forceinline__ void ldsm4(uint32_t* r, uint32_t addr) {
    asm volatile("ldmatrix.sync.aligned.m8n8.x4.shared.b16 {%0,%1,%2,%3}, [%4];\n"
        : "=r"(r[0]), "=r"(r[1]), "=r"(r[2]), "=r"(r[3]) : "r"(addr));
}
__device__ __forceinline__ void ldsm4t(uint32_t* r, uint32_t addr) {
    asm volatile("ldmatrix.sync.aligned.m8n8.x4.trans.shared.b16 {%0,%1,%2,%3}, [%4];\n"
        : "=r"(r[0]), "=r"(r[1]), "=r"(r[2]), "=r"(r[3]) : "r"(addr));
}

__device__ __forceinline__ void mma16816(float* c, const uint32_t* a, uint32_t b0, uint32_t b1) {
    asm volatile(
        "mma.sync.aligned.m16n8k16.row.col.f32.f16.f16.f32 "
        "{%0,%1,%2,%3}, {%4,%5,%6,%7}, {%8,%9}, {%0,%1,%2,%3};\n"
        : "+f"(c[0]), "+f"(c[1]), "+f"(c[2]), "+f"(c[3])
        : "r"(a[0]), "r"(a[1]), "r"(a[2]), "r"(a[3]), "r"(b0), "r"(b1));
}

// ---------------- fused fp32 -> fp16 conversion of all weights ----------------
__global__ __launch_bounds__(256) void cvt_all(
    const float* __restrict__ x0, half* __restrict__ h0, size_t n0,
    const float* __restrict__ x1, half* __restrict__ h1, size_t n1,
    const float* __restrict__ x2, half* __restrict__ h2, size_t n2,
    const float* __restrict__ x3, half* __restrict__ h3, size_t n3,
    const float* __restrict__ x4, half* __restrict__ h4, size_t n4)
{
    size_t i = ((size_t)blockIdx.x * 256 + threadIdx.x) * 4;
    const float* s; half* d;
    if (i < n0)              { s = x0; d = h0; }
    else if ((i -= n0) < n1) { s = x1; d = h1; }
    else if ((i -= n1) < n2) { s = x2; d = h2; }
    else if ((i -= n2) < n3) { s = x3; d = h3; }
    else { i -= n3; if (i >= n4) return; s = x4; d = h4; }
    float4 v = *(const float4*)(s + i);
    *(uint32_t*)(d + i)     = packh(__float2half(v.x), __float2half(v.y));
    *(uint32_t*)(d + i + 2) = packh(__float2half(v.z), __float2half(v.w));
}

// ---------------- fp16 GEMM (mma.sync), BK=64, 3-stage cp.async ----------------
// C[M,N] = A[M,K] * B[N,K]^T
// BM x 128 block, BK=64, 256 threads (8 warps, 2x4), warp tile (BM/2) x 32.
#define EPI_STORE  0
#define EPI_ADD    1
#define EPI_GELU   2
#define EPI_STOREH 3

template<int BM, int EPI>
__global__ __launch_bounds__(256) void gemm_f16(
    const half* __restrict__ A, const half* __restrict__ B,
    float* __restrict__ C, half* __restrict__ Ch,
    int M, int N, int K)
{
    constexpr int NS = 3;                        // pipeline stages
    constexpr int MT = BM / 32;                  // m-tiles (16-row) per warp
    constexpr uint32_t ABYTES = (uint32_t)BM * 128;
    constexpr uint32_t STAGE  = ABYTES + 16384u; // [A | B 16KB] (rows x 128B)

    extern __shared__ uint8_t smem[];
    const uint32_t smem_u32 = (uint32_t)__cvta_generic_to_shared(smem);

    const int tid  = threadIdx.x;
    const int lane = tid & 31;
    const int wid  = tid >> 5;
    const int wm   = wid & 1;
    const int wn   = wid >> 1;
    const int bm   = blockIdx.y * BM;
    const int bn   = blockIdx.x * 128;

    const half* Ab = A + (size_t)bm * K;
    const half* Bb = B + (size_t)bn * K;

    float acc[MT][4][4];
#pragma unroll
    for (int a = 0; a < MT; a++)
#pragma unroll
        for (int b = 0; b < 4; b++)
#pragma unroll
            for (int c = 0; c < 4; c++) acc[a][b][c] = 0.f;

    const int ntiles = K >> 6;

    auto load_stage = [&](int st, int k0) {
        uint32_t base = smem_u32 + (uint32_t)st * STAGE;
#pragma unroll
        for (int i = 0; i < BM/32; i++) {            // A: BM*8 chunks
            int idx = tid * (BM/32) + i;
            int r = idx >> 3, c = idx & 7;
            size_t go = (size_t)r * K + k0 + c * 8;
            uint32_t so = base + r * 128 + (((uint32_t)(c ^ (r & 7))) << 4);
            cp_async16(so, Ab + go);
        }
#pragma unroll
        for (int i = 0; i < 4; i++) {                // B: 1024 chunks
            int idx = tid * 4 + i;
            int r = idx >> 3, c = idx & 7;
            size_t go = (size_t)r * K + k0 + c * 8;
            uint32_t so = base + ABYTES + r * 128 + (((uint32_t)(c ^ (r & 7))) << 4);
            cp_async16(so, Bb + go);
        }
    };

    // prologue: fill NS-1 stages, one commit group each
#pragma unroll
    for (int t = 0; t < NS - 1; t++) {
        load_stage(t, t << 6);
        cp_commit();
    }

    int st = 0, stn = NS - 1;
    for (int t = 0; t < ntiles; t++) {
        cp_wait<NS - 2>();                 // stage t's group complete
        __syncthreads();                   // all warps done reading prev stage

        int tn = t + NS - 1;
        if (tn < ntiles) load_stage(stn, tn << 6);
        cp_commit();                       // always commit (empty groups in tail)

        const uint32_t bA = smem_u32 + (uint32_t)st * STAGE;
        const uint32_t bB = bA + ABYTES;

#pragma unroll
        for (int s = 0; s < 4; s++) {
            uint32_t af[MT][4];
#pragma unroll
            for (int mt = 0; mt < MT; mt++) {
                int row = wm * (BM/2) + mt * 16 + (lane & 15);
                int ch  = 2 * s + (lane >> 4);
                uint32_t off = row * 128 + (((uint32_t)(ch ^ (row & 7))) << 4);
                ldsm4(af[mt], bA + off);
            }
            uint32_t bf[2][4];
#pragma unroll
            for (int p = 0; p < 2; p++) {
                int row = wn * 32 + p * 16 + (lane & 15);
                int ch  = 2 * s + (lane >> 4);
                uint32_t off = row * 128 + (((uint32_t)(ch ^ (row & 7))) << 4);
                ldsm4(bf[p], bB + off);
            }
#pragma unroll
            for (int mt = 0; mt < MT; mt++)
#pragma unroll
                for (int nt = 0; nt < 4; nt++) {
                    int p = nt >> 1, q = nt & 1;
                    mma16816(acc[mt][nt], af[mt], bf[p][q], bf[p][q + 2]);
                }
        }

        if (++st == NS) st = 0;
        if (++stn == NS) stn = 0;
    }

    __syncthreads();

    // --- epilogue ---
#pragma unroll
    for (int mt = 0; mt < MT; mt++) {
#pragma unroll
        for (int nt = 0; nt < 4; nt++) {
            int row = bm + wm * (BM/2) + mt * 16 + (lane >> 2);
            int col = bn + wn * 32 + nt * 8 + (lane & 3) * 2;
            size_t i0 = (size_t)row * N + col;
            size_t i1 = i0 + (size_t)8 * N;
            float* c = acc[mt][nt];
            if (EPI == EPI_STORE) {
                *(float2*)(C + i0) = make_float2(c[0], c[1]);
                *(float2*)(C + i1) = make_float2(c[2], c[3]);
            } else if (EPI == EPI_ADD) {
                float2 o0 = *(const float2*)(C + i0);
                float2 o1 = *(const float2*)(C + i1);
                o0.x += c[0]; o0.y += c[1];
                o1.x += c[2]; o1.y += c[3];
                *(float2*)(C + i0) = o0;
                *(float2*)(C + i1) = o1;
            } else if (EPI == EPI_GELU) {
#pragma unroll
                for (int e = 0; e < 4; e += 2) {
                    size_t ii = (e == 0) ? i0 : i1;
                    float v0 = c[e], v1 = c[e+1];
                    float q0 = 0.5f * v0 * (1.f + erff(v0 * 0.70710678118654752f));
                    float q1 = 0.5f * v1 * (1.f + erff(v1 * 0.70710678118654752f));
                    *(uint32_t*)(Ch + ii) = packh(__float2half(q0), __float2half(q1));
                }
            } else {  // EPI_STOREH
                *(uint32_t*)(Ch + i0) = packh(__float2half(c[0]), __float2half(c[1]));
                *(uint32_t*)(Ch + i1) = packh(__float2half(c[2]), __float2half(c[3]));
            }
        }
    }
}

// ---------------- flash attention (single fp16, mma.sync) ----------------
// q-tile 128 (8 warps x 16 rows), key blocks of 64, online softmax.
__global__ __launch_bounds__(256) void flash_kernel(
    const half* __restrict__ qkv, half* __restrict__ o)
{
    extern __shared__ uint8_t fsm[];
    const uint32_t sb  = (uint32_t)__cvta_generic_to_shared(fsm);
    const uint32_t sQ  = sb;                  // 128 x 64 halves = 16KB
    const uint32_t sKV = sb + 16384;          // + stage*16384 : [K 8KB | V 8KB]

    const int tid = threadIdx.x, lane = tid & 31, w = tid >> 5;
    const int qi = (int)gridDim.x - 1 - (int)blockIdx.x;   // big tiles first
    const int bh = blockIdx.y;
    const int b = bh >> 4, h = bh & 15;
    const int qbase = qi * 128;
    const int nkb = (qbase + 128) >> 6;

    const size_t tb = (size_t)b * TSEQ;
    const half* Q_ = qkv + tb * 3 * DMODEL + h * HDIM;
    const half* K_ = Q_ + DMODEL;
    const half* V_ = Q_ + 2 * DMODEL;

    auto load_kv = [&](int buf, int kb) {
        uint32_t base = sKV + (uint32_t)buf * 16384;
#pragma unroll
        for (int i = 0; i < 2; i++) {
            int idx = tid * 2 + i;          // 0..511
            int r = idx >> 3, c = idx & 7;
            size_t go = (size_t)(kb * 64 + r) * 3 * DMODEL + c * 8;
            uint32_t so = r * 128 + (((uint32_t)(c ^ (r & 7))) << 4);
            cp_async16(base + so,        K_ + go);
            cp_async16(base + 8192 + so, V_ + go);
        }
    };

    // Q tile: 128 rows x 64 cols
#pragma unroll
    for (int i = 0; i < 4; i++) {
        int idx = tid * 4 + i;              // 0..1023
        int r = idx >> 3, c = idx & 7;
        size_t go = (size_t)(qbase + r) * 3 * DMODEL + c * 8;
        uint32_t so = r * 128 + (((uint32_t)(c ^ (r & 7))) << 4);
        cp_async16(sQ + so, Q_ + go);
    }
    load_kv(0, 0);
    cp_commit();
    if (nkb > 1) { load_kv(1, 1); cp_commit(); cp_wait<1>(); }
    else cp_wait<0>();
    __syncthreads();

    uint32_t qf[4][4];
#pragma unroll
    for (int s = 0; s < 4; s++) {
        int r = 16 * w + (lane & 15);
        int c = 2 * s + (lane >> 4);
        uint32_t so = r * 128 + (((uint32_t)(c ^ (r & 7))) << 4);
        ldsm4(qf[s], sQ + so);
    }

    float oacc[8][4];
#pragma unroll
    for (int j = 0; j < 8; j++)
#pragma unroll
        for (int c = 0; c < 4; c++) oacc[j][c] = 0.f;
    float mrow0 = -1e30f, mrow1 = -1e30f, lrow0 = 0.f, lrow1 = 0.f;
    const int r0 = qbase + 16 * w + (lane >> 2);

    for (int kb = 0; kb < nkb; kb++) {
        if (kb * 64 <= qbase + 16 * w + 15) {
            uint32_t base = sKV + (uint32_t)(kb & 1) * 16384;
            float sacc[8][4];
#pragma unroll
            for (int j = 0; j < 8; j++)
#pragma unroll
                for (int c = 0; c < 4; c++) sacc[j][c] = 0.f;

#pragma unroll
            for (int p = 0; p < 4; p++) {
                int rr = 16 * p + (lane & 15);
#pragma unroll
                for (int s = 0; s < 4; s++) {
                    int cc = 2 * s + (lane >> 4);
                    uint32_t so = rr * 128 + (((uint32_t)(cc ^ (rr & 7))) << 4);
                    uint32_t k4[4];
                    ldsm4(k4, base + so);
                    mma16816(sacc[2*p],   qf[s], k4[0], k4[2]);
                    mma16816(sacc[2*p+1], qf[s], k4[1], k4[3]);
                }
            }
            int cbase = kb * 64 + 2 * (lane & 3);
#pragma unroll
            for (int j = 0; j < 8; j++) {
                int c0 = cbase + 8 * j;
                sacc[j][0] = (c0     <= r0    ) ? sacc[j][0] * 0.125f : -1e30f;
                sacc[j][1] = (c0 + 1 <= r0    ) ? sacc[j][1] * 0.125f : -1e30f;
                sacc[j][2] = (c0     <= r0 + 8) ? sacc[j][2] * 0.125f : -1e30f;
                sacc[j][3] = (c0 + 1 <= r0 + 8) ? sacc[j][3] * 0.125f : -1e30f;
            }
            float mx0 = -1e30f, mx1 = -1e30f;
#pragma unroll
            for (int j = 0; j < 8; j++) {
                mx0 = fmaxf(mx0, fmaxf(sacc[j][0], sacc[j][1]));
                mx1 = fmaxf(mx1, fmaxf(sacc[j][2], sacc[j][3]));
            }
            mx0 = fmaxf(mx0, __shfl_xor_sync(0xffffffffu, mx0, 1));
            mx0 = fmaxf(mx0, __shfl_xor_sync(0xffffffffu, mx0, 2));
            mx1 = fmaxf(mx1, __shfl_xor_sync(0xffffffffu, mx1, 1));
            mx1 = fmaxf(mx1, __shfl_xor_sync(0xffffffffu, mx1, 2));
            float mn0 = fmaxf(mrow0, mx0), mn1 = fmaxf(mrow1, mx1);
            float al0 = __expf(mrow0 - mn0), al1 = __expf(mrow1 - mn1);
            mrow0 = mn0; mrow1 = mn1;

            uint32_t ph[8][2];
            float ls0 = 0.f, ls1 = 0.f;
#pragma unroll
            for (int j = 0; j < 8; j++) {
                float p0 = __expf(sacc[j][0] - mn0);
                float p1 = __expf(sacc[j][1] - mn0);
                float p2 = __expf(sacc[j][2] - mn1);
                float p3 = __expf(sacc[j][3] - mn1);
                ls0 += p0 + p1; ls1 += p2 + p3;
                ph[j][0] = packh(__float2half(p0), __float2half(p1));
                ph[j][1] = packh(__float2half(p2), __float2half(p3));
            }
            ls0 += __shfl_xor_sync(0xffffffffu, ls0, 1);
            ls0 += __shfl_xor_sync(0xffffffffu, ls0, 2);
            ls1 += __shfl_xor_sync(0xffffffffu, ls1, 1);
            ls1 += __shfl_xor_sync(0xffffffffu, ls1, 2);
            lrow0 = lrow0 * al0 + ls0;
            lrow1 = lrow1 * al1 + ls1;
#pragma unroll
            for (int j = 0; j < 8; j++) {
                oacc[j][0] *= al0; oacc[j][1] *= al0;
                oacc[j][2] *= al1; oacc[j][3] *= al1;
            }
            // P @ V
#pragma unroll
            for (int pv = 0; pv < 4; pv++) {
#pragma unroll
                for (int s = 0; s < 4; s++) {
                    int tok = 16 * s + ((lane >> 3) & 1) * 8 + (lane & 7);
                    int dc  = 16 * pv + (lane >> 4) * 8;
                    uint32_t so = tok * 128 + ((((uint32_t)(dc >> 3)) ^ (uint32_t)(tok & 7)) << 4);
                    uint32_t v4[4];
                    ldsm4t(v4, base + 8192 + so);
                    uint32_t pa[4] = {ph[2*s][0], ph[2*s][1], ph[2*s+1][0], ph[2*s+1][1]};
                    mma16816(oacc[2*pv],   pa, v4[0], v4[1]);
                    mma16816(oacc[2*pv+1], pa, v4[2], v4[3]);
                }
            }
        }
        __syncthreads();
        if (kb + 1 < nkb) {
            if (kb + 2 < nkb) { load_kv(kb & 1, kb + 2); cp_commit(); cp_wait<1>(); }
            else cp_wait<0>();
            __syncthreads();
        }
    }

    float rl0 = 1.f / lrow0, rl1 = 1.f / lrow1;
    size_t ob0 = (tb + r0) * (size_t)DMODEL + h * HDIM + 2 * (lane & 3);
    size_t ob1 = ob0 + 8 * (size_t)DMODEL;
#pragma unroll
    for (int j = 0; j < 8; j++) {
        *(uint32_t*)(o + ob0 + 8 * j) =
            packh(__float2half(oacc[j][0] * rl0), __float2half(oacc[j][1] * rl0));
        *(uint32_t*)(o + ob1 + 8 * j) =
            packh(__float2half(oacc[j][2] * rl1), __float2half(oacc[j][3] * rl1));
    }
}

// ---------------- embedding ----------------
__global__ void embed_kernel(const int* __restrict__ idx,
                             const float* __restrict__ tok,
                             const float* __restrict__ pos,
                             float* __restrict__ x)
{
    int t = blockIdx.x;
    int token = idx[t];
    const float* tr = tok + (size_t)token * DMODEL;
    const float* pr = pos + (size_t)(t & (TSEQ - 1)) * DMODEL;
    float* xr = x + (size_t)t * DMODEL;
    for (int d = threadIdx.x; d < DMODEL; d += blockDim.x)
        xr[d] = tr[d] + pr[d];
}

// ---------------- layernorm: warp per row, 8 rows/CTA ----------------
__global__ __launch_bounds__(256) void layernorm_kernel(
    const float* __restrict__ x, half* __restrict__ y,
    const float* __restrict__ w, const float* __restrict__ bvec)
{
    int lane = threadIdx.x & 31, wid = threadIdx.x >> 5;
    int row = blockIdx.x * 8 + wid;
    const float4* px = (const float4*)(x + (size_t)row * DMODEL);

    float4 v[8];
    float s = 0.f, ss = 0.f;
#pragma unroll
    for (int c = 0; c < 8; c++) {
        v[c] = px[lane + c * 32];
        s  += v[c].x + v[c].y + v[c].z + v[c].w;
        ss += v[c].x*v[c].x + v[c].y*v[c].y + v[c].z*v[c].z + v[c].w*v[c].w;
    }
#pragma unroll
    for (int o = 16; o; o >>= 1) {
        s  += __shfl_xor_sync(0xffffffffu, s,  o);
        ss += __shfl_xor_sync(0xffffffffu, ss, o);
    }
    float mean = s * (1.f / DMODEL);
    float var  = ss * (1.f / DMODEL) - mean * mean;
    float inv  = rsqrtf(var + 1e-5f);

    half* py = y + (size_t)row * DMODEL;
#pragma unroll
    for (int c = 0; c < 8; c++) {
        int j = (lane + c * 32) * 4;
        float4 wv = *(const float4*)(w + j);
        float4 bv = *(const float4*)(bvec + j);
        float y0 = (v[c].x - mean) * inv * wv.x + bv.x;
        float y1 = (v[c].y - mean) * inv * wv.y + bv.y;
        float y2 = (v[c].z - mean) * inv * wv.z + bv.z;
        float y3 = (v[c].w - mean) * inv * wv.w + bv.w;
        uint2 pk;
        pk.x = packh(__float2half(y0), __float2half(y1));
        pk.y = packh(__float2half(y2), __float2half(y3));
        *(uint2*)(py + j) = pk;
    }
}

// ---------------- launch ----------------
extern "C" void kernel_launch(void* const* d_in, const int* in_sizes, int n_in,
                              void* d_out, int out_size)
{
    (void)in_sizes; (void)n_in; (void)out_size;
    const int*   idx     = (const int*)  d_in[0];
    const float* tok_emb = (const float*)d_in[1];
    const float* pos_emb = (const float*)d_in[2];
    const float* ln1_w   = (const float*)d_in[3];
    const float* ln1_b   = (const float*)d_in[4];
    const float* qkv_w   = (const float*)d_in[5];
    const float* out_w   = (const float*)d_in[6];
    const float* ln2_w   = (const float*)d_in[7];
    const float* ln2_b   = (const float*)d_in[8];
    const float* ffn1_w  = (const float*)d_in[9];
    const float* ffn2_w  = (const float*)d_in[10];
    const float* lnf_w   = (const float*)d_in[11];
    const float* lnf_b   = (const float*)d_in[12];
    float* out = (float*)d_out;

    float *x;
    half *h, *qv, *o, *f, *wq, *wo, *w1, *w2, *eh;
    cudaGetSymbolAddress((void**)&x,   g_x);
    cudaGetSymbolAddress((void**)&h,   g_h);
    cudaGetSymbolAddress((void**)&qv,  g_qkv);
    cudaGetSymbolAddress((void**)&o,   g_o);
    cudaGetSymbolAddress((void**)&f,   g_f);
    cudaGetSymbolAddress((void**)&wq,  g_wq);
    cudaGetSymbolAddress((void**)&wo,  g_wo);
    cudaGetSymbolAddress((void**)&w1,  g_w1);
    cudaGetSymbolAddress((void**)&w2,  g_w2);
    cudaGetSymbolAddress((void**)&eh,  g_eh);

    cudaFuncSetAttribute(gemm_f16<64, EPI_STOREH>, cudaFuncAttributeMaxDynamicSharedMemorySize, 73728);
    cudaFuncSetAttribute(gemm_f16<64, EPI_ADD>,    cudaFuncAttributeMaxDynamicSharedMemorySize, 73728);
    cudaFuncSetAttribute(gemm_f16<128,EPI_GELU>,   cudaFuncAttributeMaxDynamicSharedMemorySize, 98304);
    cudaFuncSetAttribute(gemm_f16<128,EPI_STORE>,  cudaFuncAttributeMaxDynamicSharedMemorySize, 98304);
    cudaFuncSetAttribute(flash_kernel,             cudaFuncAttributeMaxDynamicSharedMemorySize, 49152);

    // fused weight conversion (single fp16) — one kernel, one tail
    {
        const size_t n0 = (size_t)NL*3*DMODEL*DMODEL;  // 18,874,368
        const size_t n1 = (size_t)NL*DMODEL*DMODEL;    //  6,291,456
        const size_t n2 = (size_t)NL*DFF*DMODEL;       // 25,165,824
        const size_t n3 = (size_t)NL*DMODEL*DFF;       // 25,165,824
        const size_t n4 = (size_t)VOC*DMODEL;          // 32,768,000
        const size_t total = n0 + n1 + n2 + n3 + n4;   // 108,265,472
        int blocks = (int)(total / 4 / 256);           // exact: 105,728
        cvt_all<<<blocks, 256>>>(qkv_w, wq, n0, out_w, wo, n1,
                                 ffn1_w, w1, n2, ffn2_w, w2, n3,
                                 tok_emb, eh, n4);
    }

    embed_kernel<<<MTOK, 256>>>(idx, tok_emb, pos_emb, x);

    for (int l = 0; l < NL; l++) {
        // --- attention block ---
        layernorm_kernel<<<MTOK/8, 256>>>(x, h, ln1_w + l * DMODEL, ln1_b + l * DMODEL);
        gemm_f16<64,EPI_STOREH><<<dim3(3*DMODEL/128, MTOK/64), 256, 73728>>>(
            h, wq + (size_t)l*3*DMODEL*DMODEL, nullptr, qv, MTOK, 3*DMODEL, DMODEL);
        flash_kernel<<<dim3(TSEQ/128, BATCH*NH), 256, 49152>>>(qv, o);
        gemm_f16<64,EPI_ADD><<<dim3(DMODEL/128, MTOK/64), 256, 73728>>>(
            o, wo + (size_t)l*DMODEL*DMODEL, x, nullptr, MTOK, DMODEL, DMODEL);
        // --- FFN block ---
        layernorm_kernel<<<MTOK/8, 256>>>(x, h, ln2_w + l * DMODEL, ln2_b + l * DMODEL);
        gemm_f16<128,EPI_GELU><<<dim3(DFF/128, MTOK/128), 256, 98304>>>(
            h, w1 + (size_t)l*DFF*DMODEL, nullptr, f, MTOK, DFF, DMODEL);
        gemm_f16<64,EPI_ADD><<<dim3(DMODEL/128, MTOK/64), 256, 73728>>>(
            f, w2 + (size_t)l*DMODEL*DFF, x, nullptr, MTOK, DMODEL, DFF);
    }

    layernorm_kernel<<<MTOK/8, 256>>>(x, h, lnf_w, lnf_b);
    gemm_f16<128,EPI_STORE><<<dim3(VOC/128, MTOK/128), 256, 98304>>>(
        h, eh, out, nullptr, MTOK, VOC, DMODEL);
}

// round 14
// speedup vs baseline: 2.0702x; 1.0097x over previous
#include <cuda_runtime.h>
#include <cuda_fp16.h>
#include <math.h>
#include <stdint.h>

// ---------------- problem constants ----------------
#define NL     6
#define DMODEL 1024
#define DFF    4096
#define VOC    32000
#define NH     16
#define HDIM   64
#define BATCH  2
#define TSEQ   1024
#define MTOK   (BATCH*TSEQ)   // 2048

// ---------------- scratch (static device globals; no allocation) ----------------
__device__ float g_x[MTOK * DMODEL];

__device__ __align__(16) half g_h  [MTOK * DMODEL];
__device__ __align__(16) half g_qkv[(size_t)MTOK * 3 * DMODEL];
__device__ __align__(16) half g_o  [MTOK * DMODEL];
__device__ __align__(16) half g_f  [(size_t)MTOK * DFF];

__device__ __align__(16) half g_wq[(size_t)NL*3*DMODEL*DMODEL];
__device__ __align__(16) half g_wo[(size_t)NL*DMODEL*DMODEL];
__device__ __align__(16) half g_w1[(size_t)NL*DFF*DMODEL];
__device__ __align__(16) half g_w2[(size_t)NL*DMODEL*DFF];
__device__ __align__(16) half g_eh[(size_t)VOC*DMODEL];

// ---------------- helpers ----------------
__device__ __forceinline__ uint32_t packh(half a, half b) {
    __half2 t; t.x = a; t.y = b;
    return *(uint32_t*)&t;
}

__device__ __forceinline__ void cp_async16(uint32_t s, const void* g) {
    asm volatile("cp.async.cg.shared.global [%0], [%1], 16;\n" :: "r"(s), "l"(g));
}
__device__ __forceinline__ void cp_commit() { asm volatile("cp.async.commit_group;\n"); }
template<int N> __device__ __forceinline__ void cp_wait() {
    asm volatile("cp.async.wait_group %0;\n" :: "n"(N));
}

__device__ __forceinline__ void ldsm4(uint32_t* r, uint32_t addr) {
    asm volatile("ldmatrix.sync.aligned.m8n8.x4.shared.b16 {%0,%1,%2,%3}, [%4];\n"
        : "=r"(r[0]), "=r"(r[1]), "=r"(r[2]), "=r"(r[3]) : "r"(addr));
}
__device__ __forceinline__ void ldsm4t(uint32_t* r, uint32_t addr) {
    asm volatile("ldmatrix.sync.aligned.m8n8.x4.trans.shared.b16 {%0,%1,%2,%3}, [%4];\n"
        : "=r"(r[0]), "=r"(r[1]), "=r"(r[2]), "=r"(r[3]) : "r"(addr));
}

__device__ __forceinline__ void mma16816(float* c, const uint32_t* a, uint32_t b0, uint32_t b1) {
    asm volatile(
        "mma.sync.aligned.m16n8k16.row.col.f32.f16.f16.f32 "
        "{%0,%1,%2,%3}, {%4,%5,%6,%7}, {%8,%9}, {%0,%1,%2,%3};\n"
        : "+f"(c[0]), "+f"(c[1]), "+f"(c[2]), "+f"(c[3])
        : "r"(a[0]), "r"(a[1]), "r"(a[2]), "r"(a[3]), "r"(b0), "r"(b1));
}

// ---------------- fused fp32 -> fp16 conversion (8 elems/thread, MLP=2) ----------------
__global__ __launch_bounds__(256) void cvt_all(
    const float* __restrict__ x0, half* __restrict__ h0, size_t n0,
    const float* __restrict__ x1, half* __restrict__ h1, size_t n1,
    const float* __restrict__ x2, half* __restrict__ h2, size_t n2,
    const float* __restrict__ x3, half* __restrict__ h3, size_t n3,
    const float* __restrict__ x4, half* __restrict__ h4, size_t n4)
{
    size_t i = ((size_t)blockIdx.x * 256 + threadIdx.x) * 8;
    const float* s; half* d;
    if (i < n0)              { s = x0; d = h0; }
    else if ((i -= n0) < n1) { s = x1; d = h1; }
    else if ((i -= n1) < n2) { s = x2; d = h2; }
    else if ((i -= n2) < n3) { s = x3; d = h3; }
    else { i -= n3; if (i >= n4) return; s = x4; d = h4; }
    float4 va = *(const float4*)(s + i);
    float4 vb = *(const float4*)(s + i + 4);
    uint4 o;
    o.x = packh(__float2half(va.x), __float2half(va.y));
    o.y = packh(__float2half(va.z), __float2half(va.w));
    o.z = packh(__float2half(vb.x), __float2half(vb.y));
    o.w = packh(__float2half(vb.z), __float2half(vb.w));
    *(uint4*)(d + i) = o;
}

// ---------------- fp16 GEMM (mma.sync), BK=64, 3-stage cp.async ----------------
// C[M,N] = A[M,K] * B[N,K]^T
// BM x 128 block, BK=64, 256 threads (8 warps, 2x4), warp tile (BM/2) x 32.
#define EPI_STORE  0
#define EPI_ADD    1
#define EPI_GELU   2
#define EPI_STOREH 3

template<int BM, int EPI>
__global__ __launch_bounds__(256) void gemm_f16(
    const half* __restrict__ A, const half* __restrict__ B,
    float* __restrict__ C, half* __restrict__ Ch,
    int M, int N, int K)
{
    constexpr int NS = 3;                        // pipeline stages
    constexpr int MT = BM / 32;                  // m-tiles (16-row) per warp
    constexpr uint32_t ABYTES = (uint32_t)BM * 128;
    constexpr uint32_t STAGE  = ABYTES + 16384u; // [A | B 16KB] (rows x 128B)

    extern __shared__ uint8_t smem[];
    const uint32_t smem_u32 = (uint32_t)__cvta_generic_to_shared(smem);

    const int tid  = threadIdx.x;
    const int lane = tid & 31;
    const int wid  = tid >> 5;
    const int wm   = wid & 1;
    const int wn   = wid >> 1;
    const int bm   = blockIdx.y * BM;
    const int bn   = blockIdx.x * 128;

    const half* Ab = A + (size_t)bm * K;
    const half* Bb = B + (size_t)bn * K;

    float acc[MT][4][4];
#pragma unroll
    for (int a = 0; a < MT; a++)
#pragma unroll
        for (int b = 0; b < 4; b++)
#pragma unroll
            for (int c = 0; c < 4; c++) acc[a][b][c] = 0.f;

    const int ntiles = K >> 6;

    auto load_stage = [&](int st, int k0) {
        uint32_t base = smem_u32 + (uint32_t)st * STAGE;
#pragma unroll
        for (int i = 0; i < BM/32; i++) {            // A: BM*8 chunks
            int idx = tid * (BM/32) + i;
            int r = idx >> 3, c = idx & 7;
            size_t go = (size_t)r * K + k0 + c * 8;
            uint32_t so = base + r * 128 + (((uint32_t)(c ^ (r & 7))) << 4);
            cp_async16(so, Ab + go);
        }
#pragma unroll
        for (int i = 0; i < 4; i++) {                // B: 1024 chunks
            int idx = tid * 4 + i;
            int r = idx >> 3, c = idx & 7;
            size_t go = (size_t)r * K + k0 + c * 8;
            uint32_t so = base + ABYTES + r * 128 + (((uint32_t)(c ^ (r & 7))) << 4);
            cp_async16(so, Bb + go);
        }
    };

    // prologue: fill NS-1 stages, one commit group each
#pragma unroll
    for (int t = 0; t < NS - 1; t++) {
        load_stage(t, t << 6);
        cp_commit();
    }

    int st = 0, stn = NS - 1;
    for (int t = 0; t < ntiles; t++) {
        cp_wait<NS - 2>();                 // stage t's group complete
        __syncthreads();                   // all warps done reading prev stage

        int tn = t + NS - 1;
        if (tn < ntiles) load_stage(stn, tn << 6);
        cp_commit();                       // always commit (empty groups in tail)

        const uint32_t bA = smem_u32 + (uint32_t)st * STAGE;
        const uint32_t bB = bA + ABYTES;

#pragma unroll
        for (int s = 0; s < 4; s++) {
            uint32_t af[MT][4];
#pragma unroll
            for (int mt = 0; mt < MT; mt++) {
                int row = wm * (BM/2) + mt * 16 + (lane & 15);
                int ch  = 2 * s + (lane >> 4);
                uint32_t off = row * 128 + (((uint32_t)(ch ^ (row & 7))) << 4);
                ldsm4(af[mt], bA + off);
            }
            uint32_t bf[2][4];
#pragma unroll
            for (int p = 0; p < 2; p++) {
                int row = wn * 32 + p * 16 + (lane & 15);
                int ch  = 2 * s + (lane >> 4);
                uint32_t off = row * 128 + (((uint32_t)(ch ^ (row & 7))) << 4);
                ldsm4(bf[p], bB + off);
            }
#pragma unroll
            for (int mt = 0; mt < MT; mt++)
#pragma unroll
                for (int nt = 0; nt < 4; nt++) {
                    int p = nt >> 1, q = nt & 1;
                    mma16816(acc[mt][nt], af[mt], bf[p][q], bf[p][q + 2]);
                }
        }

        if (++st == NS) st = 0;
        if (++stn == NS) stn = 0;
    }

    __syncthreads();

    // --- epilogue ---
#pragma unroll
    for (int mt = 0; mt < MT; mt++) {
#pragma unroll
        for (int nt = 0; nt < 4; nt++) {
            int row = bm + wm * (BM/2) + mt * 16 + (lane >> 2);
            int col = bn + wn * 32 + nt * 8 + (lane & 3) * 2;
            size_t i0 = (size_t)row * N + col;
            size_t i1 = i0 + (size_t)8 * N;
            float* c = acc[mt][nt];
            if (EPI == EPI_STORE) {
                *(float2*)(C + i0) = make_float2(c[0], c[1]);
                *(float2*)(C + i1) = make_float2(c[2], c[3]);
            } else if (EPI == EPI_ADD) {
                float2 o0 = *(const float2*)(C + i0);
                float2 o1 = *(const float2*)(C + i1);
                o0.x += c[0]; o0.y += c[1];
                o1.x += c[2]; o1.y += c[3];
                *(float2*)(C + i0) = o0;
                *(float2*)(C + i1) = o1;
            } else if (EPI == EPI_GELU) {
#pragma unroll
                for (int e = 0; e < 4; e += 2) {
                    size_t ii = (e == 0) ? i0 : i1;
                    float v0 = c[e], v1 = c[e+1];
                    float q0 = 0.5f * v0 * (1.f + erff(v0 * 0.70710678118654752f));
                    float q1 = 0.5f * v1 * (1.f + erff(v1 * 0.70710678118654752f));
                    *(uint32_t*)(Ch + ii) = packh(__float2half(q0), __float2half(q1));
                }
            } else {  // EPI_STOREH
                *(uint32_t*)(Ch + i0) = packh(__float2half(c[0]), __float2half(c[1]));
                *(uint32_t*)(Ch + i1) = packh(__float2half(c[2]), __float2half(c[3]));
            }
        }
    }
}

// ---------------- flash attention (single fp16, mma.sync, 3-stage KV) ----------------
// q-tile 128 (8 warps x 16 rows), key blocks of 64, online softmax.
__global__ __launch_bounds__(256) void flash_kernel(
    const half* __restrict__ qkv, half* __restrict__ o)
{
    extern __shared__ uint8_t fsm[];
    const uint32_t sb  = (uint32_t)__cvta_generic_to_shared(fsm);
    const uint32_t sQ  = sb;                  // 128 x 64 halves = 16KB
    const uint32_t sKV = sb + 16384;          // + stage*16384 : [K 8KB | V 8KB], 3 stages

    const int tid = threadIdx.x, lane = tid & 31, w = tid >> 5;
    const int qi = (int)gridDim.x - 1 - (int)blockIdx.x;   // big tiles first
    const int bh = blockIdx.y;
    const int b = bh >> 4, h = bh & 15;
    const int qbase = qi * 128;
    const int nkb = (qbase + 128) >> 6;       // always >= 2

    const size_t tb = (size_t)b * TSEQ;
    const half* Q_ = qkv + tb * 3 * DMODEL + h * HDIM;
    const half* K_ = Q_ + DMODEL;
    const half* V_ = Q_ + 2 * DMODEL;

    auto load_kv = [&](int buf, int kb) {
        uint32_t base = sKV + (uint32_t)buf * 16384;
#pragma unroll
        for (int i = 0; i < 2; i++) {
            int idx = tid * 2 + i;          // 0..511
            int r = idx >> 3, c = idx & 7;
            size_t go = (size_t)(kb * 64 + r) * 3 * DMODEL + c * 8;
            uint32_t so = r * 128 + (((uint32_t)(c ^ (r & 7))) << 4);
            cp_async16(base + so,        K_ + go);
            cp_async16(base + 8192 + so, V_ + go);
        }
    };

    // prologue: Q + KV0 in group 0, KV1 in group 1
#pragma unroll
    for (int i = 0; i < 4; i++) {
        int idx = tid * 4 + i;              // 0..1023
        int r = idx >> 3, c = idx & 7;
        size_t go = (size_t)(qbase + r) * 3 * DMODEL + c * 8;
        uint32_t so = r * 128 + (((uint32_t)(c ^ (r & 7))) << 4);
        cp_async16(sQ + so, Q_ + go);
    }
    load_kv(0, 0);
    cp_commit();                 // group 0
    load_kv(1, 1);
    cp_commit();                 // group 1

    cp_wait<1>();                // group 0 (Q + KV0) complete
    __syncthreads();

    uint32_t qf[4][4];
#pragma unroll
    for (int s = 0; s < 4; s++) {
        int r = 16 * w + (lane & 15);
        int c = 2 * s + (lane >> 4);
        uint32_t so = r * 128 + (((uint32_t)(c ^ (r & 7))) << 4);
        ldsm4(qf[s], sQ + so);
    }

    float oacc[8][4];
#pragma unroll
    for (int j = 0; j < 8; j++)
#pragma unroll
        for (int c = 0; c < 4; c++) oacc[j][c] = 0.f;
    float mrow0 = -1e30f, mrow1 = -1e30f, lrow0 = 0.f, lrow1 = 0.f;
    const int r0 = qbase + 16 * w + (lane >> 2);

    int st = 0, stn = 2;
    for (int kb = 0; kb < nkb; kb++) {
        cp_wait<1>();                       // group kb complete
        __syncthreads();                    // all warps done reading stage (kb-1)%3

        int tn = kb + 2;
        if (tn < nkb) load_kv(stn, tn);
        cp_commit();                        // always commit (empty in tail)

        if (kb * 64 <= qbase + 16 * w + 15) {
            uint32_t base = sKV + (uint32_t)st * 16384;
            float sacc[8][4];
#pragma unroll
            for (int j = 0; j < 8; j++)
#pragma unroll
                for (int c = 0; c < 4; c++) sacc[j][c] = 0.f;

#pragma unroll
            for (int p = 0; p < 4; p++) {
                int rr = 16 * p + (lane & 15);
#pragma unroll
                for (int s = 0; s < 4; s++) {
                    int cc = 2 * s + (lane >> 4);
                    uint32_t so = rr * 128 + (((uint32_t)(cc ^ (rr & 7))) << 4);
                    uint32_t k4[4];
                    ldsm4(k4, base + so);
                    mma16816(sacc[2*p],   qf[s], k4[0], k4[2]);
                    mma16816(sacc[2*p+1], qf[s], k4[1], k4[3]);
                }
            }
            int cbase = kb * 64 + 2 * (lane & 3);
#pragma unroll
            for (int j = 0; j < 8; j++) {
                int c0 = cbase + 8 * j;
                sacc[j][0] = (c0     <= r0    ) ? sacc[j][0] * 0.125f : -1e30f;
                sacc[j][1] = (c0 + 1 <= r0    ) ? sacc[j][1] * 0.125f : -1e30f;
                sacc[j][2] = (c0     <= r0 + 8) ? sacc[j][2] * 0.125f : -1e30f;
                sacc[j][3] = (c0 + 1 <= r0 + 8) ? sacc[j][3] * 0.125f : -1e30f;
            }
            float mx0 = -1e30f, mx1 = -1e30f;
#pragma unroll
            for (int j = 0; j < 8; j++) {
                mx0 = fmaxf(mx0, fmaxf(sacc[j][0], sacc[j][1]));
                mx1 = fmaxf(mx1, fmaxf(sacc[j][2], sacc[j][3]));
            }
            mx0 = fmaxf(mx0, __shfl_xor_sync(0xffffffffu, mx0, 1));
            mx0 = fmaxf(mx0, __shfl_xor_sync(0xffffffffu, mx0, 2));
            mx1 = fmaxf(mx1, __shfl_xor_sync(0xffffffffu, mx1, 1));
            mx1 = fmaxf(mx1, __shfl_xor_sync(0xffffffffu, mx1, 2));
            float mn0 = fmaxf(mrow0, mx0), mn1 = fmaxf(mrow1, mx1);
            float al0 = __expf(mrow0 - mn0), al1 = __expf(mrow1 - mn1);
            mrow0 = mn0; mrow1 = mn1;

            uint32_t ph[8][2];
            float ls0 = 0.f, ls1 = 0.f;
#pragma unroll
            for (int j = 0; j < 8; j++) {
                float p0 = __expf(sacc[j][0] - mn0);
                float p1 = __expf(sacc[j][1] - mn0);
                float p2 = __expf(sacc[j][2] - mn1);
                float p3 = __expf(sacc[j][3] - mn1);
                ls0 += p0 + p1; ls1 += p2 + p3;
                ph[j][0] = packh(__float2half(p0), __float2half(p1));
                ph[j][1] = packh(__float2half(p2), __float2half(p3));
            }
            ls0 += __shfl_xor_sync(0xffffffffu, ls0, 1);
            ls0 += __shfl_xor_sync(0xffffffffu, ls0, 2);
            ls1 += __shfl_xor_sync(0xffffffffu, ls1, 1);
            ls1 += __shfl_xor_sync(0xffffffffu, ls1, 2);
            lrow0 = lrow0 * al0 + ls0;
            lrow1 = lrow1 * al1 + ls1;
#pragma unroll
            for (int j = 0; j < 8; j++) {
                oacc[j][0] *= al0; oacc[j][1] *= al0;
                oacc[j][2] *= al1; oacc[j][3] *= al1;
            }
            // P @ V
#pragma unroll
            for (int pv = 0; pv < 4; pv++) {
#pragma unroll
                for (int s = 0; s < 4; s++) {
                    int tok = 16 * s + ((lane >> 3) & 1) * 8 + (lane & 7);
                    int dc  = 16 * pv + (lane >> 4) * 8;
                    uint32_t so = tok * 128 + ((((uint32_t)(dc >> 3)) ^ (uint32_t)(tok & 7)) << 4);
                    uint32_t v4[4];
                    ldsm4t(v4, base + 8192 + so);
                    uint32_t pa[4] = {ph[2*s][0], ph[2*s][1], ph[2*s+1][0], ph[2*s+1][1]};
                    mma16816(oacc[2*pv],   pa, v4[0], v4[1]);
                    mma16816(oacc[2*pv+1], pa, v4[2], v4[3]);
                }
            }
        }

        if (++st == 3) st = 0;
        if (++stn == 3) stn = 0;
    }

    float rl0 = 1.f / lrow0, rl1 = 1.f / lrow1;
    size_t ob0 = (tb + r0) * (size_t)DMODEL + h * HDIM + 2 * (lane & 3);
    size_t ob1 = ob0 + 8 * (size_t)DMODEL;
#pragma unroll
    for (int j = 0; j < 8; j++) {
        *(uint32_t*)(o + ob0 + 8 * j) =
            packh(__float2half(oacc[j][0] * rl0), __float2half(oacc[j][1] * rl0));
        *(uint32_t*)(o + ob1 + 8 * j) =
            packh(__float2half(oacc[j][2] * rl1), __float2half(oacc[j][3] * rl1));
    }
}

// ---------------- embedding ----------------
__global__ void embed_kernel(const int* __restrict__ idx,
                             const float* __restrict__ tok,
                             const float* __restrict__ pos,
                             float* __restrict__ x)
{
    int t = blockIdx.x;
    int token = idx[t];
    const float* tr = tok + (size_t)token * DMODEL;
    const float* pr = pos + (size_t)(t & (TSEQ - 1)) * DMODEL;
    float* xr = x + (size_t)t * DMODEL;
    for (int d = threadIdx.x; d < DMODEL; d += blockDim.x)
        xr[d] = tr[d] + pr[d];
}

// ---------------- layernorm: warp per row, 8 rows/CTA ----------------
__global__ __launch_bounds__(256) void layernorm_kernel(
    const float* __restrict__ x, half* __restrict__ y,
    const float* __restrict__ w, const float* __restrict__ bvec)
{
    int lane = threadIdx.x & 31, wid = threadIdx.x >> 5;
    int row = blockIdx.x * 8 + wid;
    const float4* px = (const float4*)(x + (size_t)row * DMODEL);

    float4 v[8];
    float s = 0.f, ss = 0.f;
#pragma unroll
    for (int c = 0; c < 8; c++) {
        v[c] = px[lane + c * 32];
        s  += v[c].x + v[c].y + v[c].z + v[c].w;
        ss += v[c].x*v[c].x + v[c].y*v[c].y + v[c].z*v[c].z + v[c].w*v[c].w;
    }
#pragma unroll
    for (int o = 16; o; o >>= 1) {
        s  += __shfl_xor_sync(0xffffffffu, s,  o);
        ss += __shfl_xor_sync(0xffffffffu, ss, o);
    }
    float mean = s * (1.f / DMODEL);
    float var  = ss * (1.f / DMODEL) - mean * mean;
    float inv  = rsqrtf(var + 1e-5f);

    half* py = y + (size_t)row * DMODEL;
#pragma unroll
    for (int c = 0; c < 8; c++) {
        int j = (lane + c * 32) * 4;
        float4 wv = *(const float4*)(w + j);
        float4 bv = *(const float4*)(bvec + j);
        float y0 = (v[c].x - mean) * inv * wv.x + bv.x;
        float y1 = (v[c].y - mean) * inv * wv.y + bv.y;
        float y2 = (v[c].z - mean) * inv * wv.z + bv.z;
        float y3 = (v[c].w - mean) * inv * wv.w + bv.w;
        uint2 pk;
        pk.x = packh(__float2half(y0), __float2half(y1));
        pk.y = packh(__float2half(y2), __float2half(y3));
        *(uint2*)(py + j) = pk;
    }
}

// ---------------- launch ----------------
extern "C" void kernel_launch(void* const* d_in, const int* in_sizes, int n_in,
                              void* d_out, int out_size)
{
    (void)in_sizes; (void)n_in; (void)out_size;
    const int*   idx     = (const int*)  d_in[0];
    const float* tok_emb = (const float*)d_in[1];
    const float* pos_emb = (const float*)d_in[2];
    const float* ln1_w   = (const float*)d_in[3];
    const float* ln1_b   = (const float*)d_in[4];
    const float* qkv_w   = (const float*)d_in[5];
    const float* out_w   = (const float*)d_in[6];
    const float* ln2_w   = (const float*)d_in[7];
    const float* ln2_b   = (const float*)d_in[8];
    const float* ffn1_w  = (const float*)d_in[9];
    const float* ffn2_w  = (const float*)d_in[10];
    const float* lnf_w   = (const float*)d_in[11];
    const float* lnf_b   = (const float*)d_in[12];
    float* out = (float*)d_out;

    float *x;
    half *h, *qv, *o, *f, *wq, *wo, *w1, *w2, *eh;
    cudaGetSymbolAddress((void**)&x,   g_x);
    cudaGetSymbolAddress((void**)&h,   g_h);
    cudaGetSymbolAddress((void**)&qv,  g_qkv);
    cudaGetSymbolAddress((void**)&o,   g_o);
    cudaGetSymbolAddress((void**)&f,   g_f);
    cudaGetSymbolAddress((void**)&wq,  g_wq);
    cudaGetSymbolAddress((void**)&wo,  g_wo);
    cudaGetSymbolAddress((void**)&w1,  g_w1);
    cudaGetSymbolAddress((void**)&w2,  g_w2);
    cudaGetSymbolAddress((void**)&eh,  g_eh);

    cudaFuncSetAttribute(gemm_f16<64, EPI_STOREH>, cudaFuncAttributeMaxDynamicSharedMemorySize, 73728);
    cudaFuncSetAttribute(gemm_f16<64, EPI_ADD>,    cudaFuncAttributeMaxDynamicSharedMemorySize, 73728);
    cudaFuncSetAttribute(gemm_f16<128,EPI_GELU>,   cudaFuncAttributeMaxDynamicSharedMemorySize, 98304);
    cudaFuncSetAttribute(gemm_f16<128,EPI_STORE>,  cudaFuncAttributeMaxDynamicSharedMemorySize, 98304);
    cudaFuncSetAttribute(flash_kernel,             cudaFuncAttributeMaxDynamicSharedMemorySize, 65536);

    // fused weight conversion (single fp16) — one kernel, 8 elems/thread
    {
        const size_t n0 = (size_t)NL*3*DMODEL*DMODEL;  // 18,874,368
        const size_t n1 = (size_t)NL*DMODEL*DMODEL;    //  6,291,456
        const size_t n2 = (size_t)NL*DFF*DMODEL;       // 25,165,824
        const size_t n3 = (size_t)NL*DMODEL*DFF;       // 25,165,824
        const size_t n4 = (size_t)VOC*DMODEL;          // 32,768,000
        const size_t total = n0 + n1 + n2 + n3 + n4;   // 108,265,472
        int blocks = (int)(total / 8 / 256);           // exact: 52,864
        cvt_all<<<blocks, 256>>>(qkv_w, wq, n0, out_w, wo, n1,
                                 ffn1_w, w1, n2, ffn2_w, w2, n3,
                                 tok_emb, eh, n4);
    }

    embed_kernel<<<MTOK, 256>>>(idx, tok_emb, pos_emb, x);

    for (int l = 0; l < NL; l++) {
        // --- attention block ---
        layernorm_kernel<<<MTOK/8, 256>>>(x, h, ln1_w + l * DMODEL, ln1_b + l * DMODEL);
        gemm_f16<64,EPI_STOREH><<<dim3(3*DMODEL/128, MTOK/64), 256, 73728>>>(
            h, wq + (size_t)l*3*DMODEL*DMODEL, nullptr, qv, MTOK, 3*DMODEL, DMODEL);
        flash_kernel<<<dim3(TSEQ/128, BATCH*NH), 256, 65536>>>(qv, o);
        gemm_f16<64,EPI_ADD><<<dim3(DMODEL/128, MTOK/64), 256, 73728>>>(
            o, wo + (size_t)l*DMODEL*DMODEL, x, nullptr, MTOK, DMODEL, DMODEL);
        // --- FFN block ---
        layernorm_kernel<<<MTOK/8, 256>>>(x, h, ln2_w + l * DMODEL, ln2_b + l * DMODEL);
        gemm_f16<128,EPI_GELU><<<dim3(DFF/128, MTOK/128), 256, 98304>>>(
            h, w1 + (size_t)l*DFF*DMODEL, nullptr, f, MTOK, DFF, DMODEL);
        gemm_f16<64,EPI_ADD><<<dim3(DMODEL/128, MTOK/64), 256, 73728>>>(
            f, w2 + (size_t)l*DMODEL*DFF, x, nullptr, MTOK, DMODEL, DFF);
    }

    layernorm_kernel<<<MTOK/8, 256>>>(x, h, lnf_w, lnf_b);
    gemm_f16<128,EPI_STORE><<<dim3(VOC/128, MTOK/128), 256, 98304>>>(
        h, eh, out, nullptr, MTOK, VOC, DMODEL);
}